// round 1
// baseline (speedup 1.0000x reference)
#include <cuda_runtime.h>
#include <math.h>

// Problem constants
constexpr int BB = 4;
constexpr int SS = 2048;
constexpr int DD = 1024;
constexpr int HH = 16;
constexpr int HD = 64;
constexpr int FF = 4096;
constexpr int MM = BB * SS;  // 8192 tokens

// Scratch (device globals; no allocation allowed)
__device__ float g_q[(size_t)MM * DD];     // q [B,H,S,hd] -> later o-proj out [M,D]
__device__ float g_k[(size_t)MM * DD];     // k [B,H,S,hd] -> later h (post-LN1)
__device__ float g_v[(size_t)MM * DD];     // v [B,H,S,hd] -> later ffn2 out
__device__ float g_attn[(size_t)MM * DD];  // attention out, token layout [M,D]
__device__ float g_ff[(size_t)MM * FF];    // ffn hidden [M,F]

// ---------------------------------------------------------------------------
// Generic SGEMM: C = A[M,K] @ W[K,N] + bias, 128x128x16 tiles, 256 threads,
// 8x8 per-thread microtile. EPI: 0 = plain, 1 = ReLU, 2 = scatter to [B,H,S,hd].
// All dims divisible by tiles for this problem (no bounds checks).
// ---------------------------------------------------------------------------
template <int EPI>
__global__ __launch_bounds__(256) void sgemm_kernel(
    const float* __restrict__ A, const float* __restrict__ W,
    const float* __restrict__ bias, float* __restrict__ C,
    int M, int N, int K)
{
    __shared__ float As[16][128];  // transposed A tile: As[k][m]
    __shared__ float Bs[16][128];  // Bs[k][n]

    const int tid = threadIdx.x;
    const int tx = tid & 15;
    const int ty = tid >> 4;
    const int m0 = blockIdx.y << 7;
    const int n0 = blockIdx.x << 7;

    float acc[8][8];
#pragma unroll
    for (int i = 0; i < 8; i++)
#pragma unroll
        for (int j = 0; j < 8; j++) acc[i][j] = 0.0f;

    // bias fragment (constant across rows)
    float bfr[8];
#pragma unroll
    for (int j = 0; j < 8; j++) bfr[j] = bias[n0 + tx * 8 + j];

    const int aRow = tid >> 2;  // 0..63
    const int aC4  = tid & 3;   // 0..3
    const int bRow = tid >> 5;  // 0..7
    const int bC4  = tid & 31;  // 0..31

    for (int k0 = 0; k0 < K; k0 += 16) {
        // A tile: 128 rows x 16 cols, store transposed
#pragma unroll
        for (int i = 0; i < 2; i++) {
            int r = aRow + i * 64;
            float4 v = *(const float4*)(A + (size_t)(m0 + r) * K + k0 + aC4 * 4);
            As[aC4 * 4 + 0][r] = v.x;
            As[aC4 * 4 + 1][r] = v.y;
            As[aC4 * 4 + 2][r] = v.z;
            As[aC4 * 4 + 3][r] = v.w;
        }
        // B tile: 16 rows x 128 cols
#pragma unroll
        for (int i = 0; i < 2; i++) {
            int r = bRow + i * 8;
            *(float4*)(&Bs[r][bC4 * 4]) =
                *(const float4*)(W + (size_t)(k0 + r) * N + n0 + bC4 * 4);
        }
        __syncthreads();

#pragma unroll
        for (int k = 0; k < 16; k++) {
            float a[8], b[8];
            *(float4*)(a)     = *(const float4*)(&As[k][ty * 8]);
            *(float4*)(a + 4) = *(const float4*)(&As[k][ty * 8 + 4]);
            *(float4*)(b)     = *(const float4*)(&Bs[k][tx * 8]);
            *(float4*)(b + 4) = *(const float4*)(&Bs[k][tx * 8 + 4]);
#pragma unroll
            for (int i = 0; i < 8; i++)
#pragma unroll
                for (int j = 0; j < 8; j++)
                    acc[i][j] = fmaf(a[i], b[j], acc[i][j]);
        }
        __syncthreads();
    }

    // Epilogue
#pragma unroll
    for (int i = 0; i < 8; i++) {
        int row = m0 + ty * 8 + i;
#pragma unroll
        for (int jj = 0; jj < 8; jj += 4) {
            float4 r4;
            r4.x = acc[i][jj + 0] + bfr[jj + 0];
            r4.y = acc[i][jj + 1] + bfr[jj + 1];
            r4.z = acc[i][jj + 2] + bfr[jj + 2];
            r4.w = acc[i][jj + 3] + bfr[jj + 3];
            if (EPI == 1) {
                r4.x = fmaxf(r4.x, 0.0f);
                r4.y = fmaxf(r4.y, 0.0f);
                r4.z = fmaxf(r4.z, 0.0f);
                r4.w = fmaxf(r4.w, 0.0f);
            }
            int col = n0 + tx * 8 + jj;
            if (EPI == 2) {
                // token row -> (b, s); col -> (h, dh). 8-col group never crosses a head.
                int b_ = row >> 11;        // / SS
                int s_ = row & (SS - 1);
                int h_ = col >> 6;         // / HD
                int dh = col & (HD - 1);
                size_t dst = (((size_t)b_ * HH + h_) * SS + s_) * HD + dh;
                *(float4*)(C + dst) = r4;
            } else {
                *(float4*)(C + (size_t)row * N + col) = r4;
            }
        }
    }
}

// ---------------------------------------------------------------------------
// Flash attention: one block per (b, h, q-tile of 64 rows). BC = 32 k-cols per
// inner tile, hd = 64. 256 threads: thread (tx,ty) owns q-rows ty*4..+3.
// Scores: cols {tx, tx+16}. Output: dims tx*4..+3 (float4).
// ---------------------------------------------------------------------------
__global__ __launch_bounds__(256) void flash_kernel(
    const float* __restrict__ q, const float* __restrict__ k,
    const float* __restrict__ v, const int* __restrict__ mask,
    float* __restrict__ out)
{
    __shared__ float Qs[64][64];   // 16 KB
    __shared__ float Ks[32][68];   // padded: float4 reads, stride-16 cols -> ~2-way
    __shared__ float Vs[32][64];
    __shared__ float Ss[64][32];

    const int tid = threadIdx.x;
    const int tx = tid & 15;
    const int ty = tid >> 4;
    const int bh = blockIdx.y;      // b*H + h
    const int b_ = bh >> 4;         // / HH
    const int h_ = bh & (HH - 1);
    const int q0 = blockIdx.x * 64;

    // Load Q tile (64x64 floats = 1024 float4)
    const float* qb = q + ((size_t)bh * SS + q0) * HD;
#pragma unroll
    for (int i = 0; i < 4; i++) {
        int f = tid + i * 256;
        ((float4*)Qs)[f] = ((const float4*)qb)[f];
    }

    float m_i[4], l_i[4];
    float4 o_acc[4];
#pragma unroll
    for (int i = 0; i < 4; i++) {
        m_i[i] = -1e30f;
        l_i[i] = 0.0f;
        o_acc[i] = make_float4(0.f, 0.f, 0.f, 0.f);
    }

    for (int kc = 0; kc < SS / 32; kc++) {
        const float* kb = k + ((size_t)bh * SS + kc * 32) * HD;
        const float* vb = v + ((size_t)bh * SS + kc * 32) * HD;
#pragma unroll
        for (int i = 0; i < 2; i++) {
            int f = tid + i * 256;         // 512 float4 total
            int r = f >> 4, c4 = f & 15;
            *(float4*)(&Ks[r][c4 * 4]) = ((const float4*)kb)[f];
            ((float4*)Vs)[f] = ((const float4*)vb)[f];
        }
        __syncthreads();

        // S = Q K^T for this tile
        float sc0[4] = {0.f, 0.f, 0.f, 0.f};
        float sc1[4] = {0.f, 0.f, 0.f, 0.f};
#pragma unroll
        for (int d4 = 0; d4 < 16; d4++) {
            float4 ka = *(const float4*)(&Ks[tx][d4 * 4]);
            float4 kbv = *(const float4*)(&Ks[tx + 16][d4 * 4]);
#pragma unroll
            for (int i = 0; i < 4; i++) {
                float4 qv = *(const float4*)(&Qs[ty * 4 + i][d4 * 4]);
                sc0[i] = fmaf(qv.x, ka.x, sc0[i]);
                sc0[i] = fmaf(qv.y, ka.y, sc0[i]);
                sc0[i] = fmaf(qv.z, ka.z, sc0[i]);
                sc0[i] = fmaf(qv.w, ka.w, sc0[i]);
                sc1[i] = fmaf(qv.x, kbv.x, sc1[i]);
                sc1[i] = fmaf(qv.y, kbv.y, sc1[i]);
                sc1[i] = fmaf(qv.z, kbv.z, sc1[i]);
                sc1[i] = fmaf(qv.w, kbv.w, sc1[i]);
            }
        }

        const int mk0 = mask[b_ * SS + kc * 32 + tx];
        const int mk1 = mask[b_ * SS + kc * 32 + tx + 16];

        // Online softmax update per owned row
#pragma unroll
        for (int i = 0; i < 4; i++) {
            float s0 = sc0[i] * 0.125f;  // 1/sqrt(64)
            float s1 = sc1[i] * 0.125f;
            if (mk0 == 0) s0 = -1e9f;
            if (mk1 == 0) s1 = -1e9f;
            float mx = fmaxf(s0, s1);
#pragma unroll
            for (int off = 8; off >= 1; off >>= 1)
                mx = fmaxf(mx, __shfl_xor_sync(0xffffffffu, mx, off, 16));
            float mnew = fmaxf(m_i[i], mx);
            float corr = __expf(m_i[i] - mnew);
            float p0 = __expf(s0 - mnew);
            float p1 = __expf(s1 - mnew);
            Ss[ty * 4 + i][tx] = p0;
            Ss[ty * 4 + i][tx + 16] = p1;
            float ps = p0 + p1;
#pragma unroll
            for (int off = 8; off >= 1; off >>= 1)
                ps += __shfl_xor_sync(0xffffffffu, ps, off, 16);
            l_i[i] = l_i[i] * corr + ps;
            m_i[i] = mnew;
            o_acc[i].x *= corr;
            o_acc[i].y *= corr;
            o_acc[i].z *= corr;
            o_acc[i].w *= corr;
        }
        __syncthreads();

        // O += P @ V
#pragma unroll
        for (int c4 = 0; c4 < 8; c4++) {
            float4 v0 = *(const float4*)(&Vs[c4 * 4 + 0][tx * 4]);
            float4 v1 = *(const float4*)(&Vs[c4 * 4 + 1][tx * 4]);
            float4 v2 = *(const float4*)(&Vs[c4 * 4 + 2][tx * 4]);
            float4 v3 = *(const float4*)(&Vs[c4 * 4 + 3][tx * 4]);
#pragma unroll
            for (int i = 0; i < 4; i++) {
                float4 p = *(const float4*)(&Ss[ty * 4 + i][c4 * 4]);
                o_acc[i].x = fmaf(p.x, v0.x, o_acc[i].x);
                o_acc[i].y = fmaf(p.x, v0.y, o_acc[i].y);
                o_acc[i].z = fmaf(p.x, v0.z, o_acc[i].z);
                o_acc[i].w = fmaf(p.x, v0.w, o_acc[i].w);
                o_acc[i].x = fmaf(p.y, v1.x, o_acc[i].x);
                o_acc[i].y = fmaf(p.y, v1.y, o_acc[i].y);
                o_acc[i].z = fmaf(p.y, v1.z, o_acc[i].z);
                o_acc[i].w = fmaf(p.y, v1.w, o_acc[i].w);
                o_acc[i].x = fmaf(p.z, v2.x, o_acc[i].x);
                o_acc[i].y = fmaf(p.z, v2.y, o_acc[i].y);
                o_acc[i].z = fmaf(p.z, v2.z, o_acc[i].z);
                o_acc[i].w = fmaf(p.z, v2.w, o_acc[i].w);
                o_acc[i].x = fmaf(p.w, v3.x, o_acc[i].x);
                o_acc[i].y = fmaf(p.w, v3.y, o_acc[i].y);
                o_acc[i].z = fmaf(p.w, v3.z, o_acc[i].z);
                o_acc[i].w = fmaf(p.w, v3.w, o_acc[i].w);
            }
        }
        __syncthreads();
    }

    // Write normalized output to token layout [M, D]
#pragma unroll
    for (int i = 0; i < 4; i++) {
        float inv = 1.0f / l_i[i];
        int row = q0 + ty * 4 + i;
        float4 r4 = make_float4(o_acc[i].x * inv, o_acc[i].y * inv,
                                o_acc[i].z * inv, o_acc[i].w * inv);
        *(float4*)(out + ((size_t)(b_ * SS + row)) * DD + h_ * HD + tx * 4) = r4;
    }
}

// ---------------------------------------------------------------------------
// Fused residual-add + LayerNorm over D=1024. One block (256 thr) per row.
// ---------------------------------------------------------------------------
__global__ __launch_bounds__(256) void add_ln_kernel(
    const float* __restrict__ a, const float* __restrict__ b,
    const float* __restrict__ g, const float* __restrict__ be,
    float* __restrict__ out)
{
    __shared__ float sh[10];
    const int row = blockIdx.x;
    const int tid = threadIdx.x;
    const int wid = tid >> 5, lane = tid & 31;
    const size_t base = (size_t)row * DD + tid * 4;

    float4 av = *(const float4*)(a + base);
    float4 bv = *(const float4*)(b + base);
    float4 t = make_float4(av.x + bv.x, av.y + bv.y, av.z + bv.z, av.w + bv.w);

    float s = t.x + t.y + t.z + t.w;
#pragma unroll
    for (int off = 16; off >= 1; off >>= 1)
        s += __shfl_xor_sync(0xffffffffu, s, off);
    if (lane == 0) sh[wid] = s;
    __syncthreads();
    if (tid == 0) {
        float t2 = 0.f;
#pragma unroll
        for (int w = 0; w < 8; w++) t2 += sh[w];
        sh[8] = t2 * (1.0f / 1024.0f);
    }
    __syncthreads();
    float mu = sh[8];

    float dx = t.x - mu, dy = t.y - mu, dz = t.z - mu, dw = t.w - mu;
    float sq = dx * dx + dy * dy + dz * dz + dw * dw;
#pragma unroll
    for (int off = 16; off >= 1; off >>= 1)
        sq += __shfl_xor_sync(0xffffffffu, sq, off);
    if (lane == 0) sh[wid] = sq;
    __syncthreads();
    if (tid == 0) {
        float t2 = 0.f;
#pragma unroll
        for (int w = 0; w < 8; w++) t2 += sh[w];
        sh[9] = rsqrtf(t2 * (1.0f / 1024.0f) + 1e-5f);
    }
    __syncthreads();
    float inv = sh[9];

    float4 gv = *(const float4*)(g + tid * 4);
    float4 bev = *(const float4*)(be + tid * 4);
    float4 r = make_float4(dx * inv * gv.x + bev.x,
                           dy * inv * gv.y + bev.y,
                           dz * inv * gv.z + bev.z,
                           dw * inv * gv.w + bev.w);
    *(float4*)(out + base) = r;
}

// ---------------------------------------------------------------------------
extern "C" void kernel_launch(void* const* d_in, const int* in_sizes, int n_in,
                              void* d_out, int out_size)
{
    const float* x   = (const float*)d_in[0];
    const int*   msk = (const int*)d_in[1];
    const float* Wq  = (const float*)d_in[2];
    const float* bq  = (const float*)d_in[3];
    const float* Wk  = (const float*)d_in[4];
    const float* bk  = (const float*)d_in[5];
    const float* Wv  = (const float*)d_in[6];
    const float* bv  = (const float*)d_in[7];
    const float* Wo  = (const float*)d_in[8];
    const float* bo  = (const float*)d_in[9];
    const float* W1  = (const float*)d_in[10];
    const float* b1  = (const float*)d_in[11];
    const float* W2  = (const float*)d_in[12];
    const float* b2  = (const float*)d_in[13];
    const float* g1  = (const float*)d_in[14];
    const float* be1 = (const float*)d_in[15];
    const float* g2  = (const float*)d_in[16];
    const float* be2 = (const float*)d_in[17];
    float* out = (float*)d_out;

    float *q, *kb, *vb, *attn, *ff;
    cudaGetSymbolAddress((void**)&q,    g_q);
    cudaGetSymbolAddress((void**)&kb,   g_k);
    cudaGetSymbolAddress((void**)&vb,   g_v);
    cudaGetSymbolAddress((void**)&attn, g_attn);
    cudaGetSymbolAddress((void**)&ff,   g_ff);

    dim3 blk(256);
    dim3 gD(DD / 128, MM / 128);   // (8, 64)
    dim3 gF(FF / 128, MM / 128);   // (32, 64)

    // QKV projections, scattered to [B,H,S,hd]
    sgemm_kernel<2><<<gD, blk>>>(x, Wq, bq, q,  MM, DD, DD);
    sgemm_kernel<2><<<gD, blk>>>(x, Wk, bk, kb, MM, DD, DD);
    sgemm_kernel<2><<<gD, blk>>>(x, Wv, bv, vb, MM, DD, DD);

    // Flash attention -> token layout [M, D]
    flash_kernel<<<dim3(SS / 64, BB * HH), blk>>>(q, kb, vb, msk, attn);

    // Output projection (reuse g_q)
    sgemm_kernel<0><<<gD, blk>>>(attn, Wo, bo, q, MM, DD, DD);

    // Residual + LN1 -> h (reuse g_k)
    add_ln_kernel<<<MM, blk>>>(x, q, g1, be1, kb);

    // FFN
    sgemm_kernel<1><<<gF, blk>>>(kb, W1, b1, ff, MM, FF, DD);   // ReLU
    sgemm_kernel<0><<<gD, blk>>>(ff, W2, b2, vb, MM, DD, FF);

    // Residual + LN2 -> output
    add_ln_kernel<<<MM, blk>>>(kb, vb, g2, be2, out);
}

// round 3
// speedup vs baseline: 1.0239x; 1.0239x over previous
#include <cuda_runtime.h>
#include <mma.h>
#include <math.h>

using namespace nvcuda;

// Problem constants
constexpr int BB = 4;
constexpr int SS = 2048;
constexpr int DD = 1024;
constexpr int HH = 16;
constexpr int HD = 64;
constexpr int FF = 4096;
constexpr int MM = BB * SS;  // 8192 tokens

// Scratch (device globals; no allocation allowed)
__device__ float g_q[(size_t)MM * DD];     // q heads / later h (post-LN1)... see launch
__device__ float g_k[(size_t)MM * DD];
__device__ float g_v[(size_t)MM * DD];
__device__ float g_attn[(size_t)MM * DD];  // staging + attention out [M,D]
__device__ float g_ff[(size_t)MM * FF];    // ffn hidden / o-proj staging

// ---------------------------------------------------------------------------
// TF32 tensor-core GEMM: C = A[M,K] @ W[K,N].  128x128x16 tiles, 256 threads
// (8 warps, each 64x32), wmma m16n16k8 tf32, double-buffered smem.
// ---------------------------------------------------------------------------
constexpr int AS_LD = 24;    // 16 cols + pad (float4-aligned rows: 96B)
constexpr int BS_LD = 136;   // 128 cols + pad (544B rows, 16B-aligned)

__global__ __launch_bounds__(256) void gemm_tf32_kernel(
    const float* __restrict__ A, const float* __restrict__ W,
    float* __restrict__ C, int M, int N, int K)
{
    __shared__ float As[2][128 * AS_LD];
    __shared__ float Bs[2][16 * BS_LD];

    const int tid = threadIdx.x;
    const int wid = tid >> 5;
    const int m0 = blockIdx.y << 7;
    const int n0 = blockIdx.x << 7;
    const int warp_m = wid & 1;   // 0..1  -> 64-row slab
    const int warp_n = wid >> 1;  // 0..3  -> 32-col slab

    typedef wmma::fragment<wmma::matrix_a, 16, 16, 8, wmma::precision::tf32, wmma::row_major> FragA;
    typedef wmma::fragment<wmma::matrix_b, 16, 16, 8, wmma::precision::tf32, wmma::row_major> FragB;
    typedef wmma::fragment<wmma::accumulator, 16, 16, 8, float> FragC;

    FragC acc[4][2];
#pragma unroll
    for (int i = 0; i < 4; i++)
#pragma unroll
        for (int j = 0; j < 2; j++) wmma::fill_fragment(acc[i][j], 0.0f);

    // Global-load addressing (per thread: 2 float4 for A, 2 for B per k-tile)
    const int aRow0 = tid >> 2, aC4 = tid & 3;        // A: f=tid+i*256 -> row=f>>2
    const int bRow0 = tid >> 5, bC4 = tid & 31;       // B: row=f>>5

    float4 aReg[2], bReg[2];
    auto load_gmem = [&](int k0) {
#pragma unroll
        for (int i = 0; i < 2; i++) {
            int ar = aRow0 + i * 64;
            aReg[i] = *(const float4*)(A + (size_t)(m0 + ar) * K + k0 + aC4 * 4);
            int br = bRow0 + i * 8;
            bReg[i] = *(const float4*)(W + (size_t)(k0 + br) * N + n0 + bC4 * 4);
        }
    };
    auto store_smem = [&](int buf) {
#pragma unroll
        for (int i = 0; i < 2; i++) {
            int ar = aRow0 + i * 64;
            *(float4*)(&As[buf][ar * AS_LD + aC4 * 4]) = aReg[i];
            int br = bRow0 + i * 8;
            *(float4*)(&Bs[buf][br * BS_LD + bC4 * 4]) = bReg[i];
        }
    };

    const int KT = K >> 4;
    load_gmem(0);
    store_smem(0);
    __syncthreads();

    for (int kt = 0; kt < KT; kt++) {
        const int cur = kt & 1;
        if (kt + 1 < KT) load_gmem((kt + 1) << 4);

        const float* as = &As[cur][warp_m * 64 * AS_LD];
        const float* bs = &Bs[cur][warp_n * 32];
#pragma unroll
        for (int kk = 0; kk < 16; kk += 8) {
            FragA af[4];
            FragB bf[2];
#pragma unroll
            for (int i = 0; i < 4; i++) {
                wmma::load_matrix_sync(af[i], as + i * 16 * AS_LD + kk, AS_LD);
#pragma unroll
                for (int t = 0; t < af[i].num_elements; t++)
                    af[i].x[t] = wmma::__float_to_tf32(af[i].x[t]);
            }
#pragma unroll
            for (int j = 0; j < 2; j++) {
                wmma::load_matrix_sync(bf[j], bs + kk * BS_LD + j * 16, BS_LD);
#pragma unroll
                for (int t = 0; t < bf[j].num_elements; t++)
                    bf[j].x[t] = wmma::__float_to_tf32(bf[j].x[t]);
            }
#pragma unroll
            for (int i = 0; i < 4; i++)
#pragma unroll
                for (int j = 0; j < 2; j++)
                    wmma::mma_sync(acc[i][j], af[i], bf[j], acc[i][j]);
        }

        if (kt + 1 < KT) {
            __syncthreads();
            store_smem((kt + 1) & 1);
            __syncthreads();
        }
    }

    // Epilogue: direct store (pure GEMM; bias handled downstream)
#pragma unroll
    for (int i = 0; i < 4; i++)
#pragma unroll
        for (int j = 0; j < 2; j++) {
            float* cp = C + (size_t)(m0 + warp_m * 64 + i * 16) * N +
                        n0 + warp_n * 32 + j * 16;
            wmma::store_matrix_sync(cp, acc[i][j], N, wmma::mem_row_major);
        }
}

// ---------------------------------------------------------------------------
// QKV epilogue: add bias, scatter token layout [M,D] -> heads [B,H,S,hd]
// ---------------------------------------------------------------------------
__global__ __launch_bounds__(256) void scatter_bias_kernel(
    const float* __restrict__ in, const float* __restrict__ bias,
    float* __restrict__ out)
{
    const int row = blockIdx.x;
    const int col = threadIdx.x * 4;
    float4 v = *(const float4*)(in + (size_t)row * DD + col);
    float4 bv = *(const float4*)(bias + col);
    v.x += bv.x; v.y += bv.y; v.z += bv.z; v.w += bv.w;
    int b_ = row >> 11;
    int s_ = row & (SS - 1);
    int h_ = col >> 6;
    int dh = col & (HD - 1);
    *(float4*)(out + (((size_t)b_ * HH + h_) * SS + s_) * HD + dh) = v;
}

// FFN1 epilogue: in-place bias + ReLU over [M, FF]
__global__ __launch_bounds__(256) void bias_relu_kernel(
    float* __restrict__ io, const float* __restrict__ bias)
{
    size_t idx = ((size_t)blockIdx.x * 256 + threadIdx.x) * 4;
    int col = (int)(idx & (FF - 1));
    float4 v = *(const float4*)(io + idx);
    float4 bv = *(const float4*)(bias + col);
    v.x = fmaxf(v.x + bv.x, 0.0f);
    v.y = fmaxf(v.y + bv.y, 0.0f);
    v.z = fmaxf(v.z + bv.z, 0.0f);
    v.w = fmaxf(v.w + bv.w, 0.0f);
    *(float4*)(io + idx) = v;
}

// ---------------------------------------------------------------------------
// Flash attention (unchanged from round 1): block per (b,h,64 q-rows), BC=32.
// ---------------------------------------------------------------------------
__global__ __launch_bounds__(256) void flash_kernel(
    const float* __restrict__ q, const float* __restrict__ k,
    const float* __restrict__ v, const int* __restrict__ mask,
    float* __restrict__ out)
{
    __shared__ float Qs[64][64];
    __shared__ float Ks[32][68];
    __shared__ float Vs[32][64];
    __shared__ float Ss[64][32];

    const int tid = threadIdx.x;
    const int tx = tid & 15;
    const int ty = tid >> 4;
    const int bh = blockIdx.y;
    const int b_ = bh >> 4;
    const int h_ = bh & (HH - 1);
    const int q0 = blockIdx.x * 64;

    const float* qb = q + ((size_t)bh * SS + q0) * HD;
#pragma unroll
    for (int i = 0; i < 4; i++) {
        int f = tid + i * 256;
        ((float4*)Qs)[f] = ((const float4*)qb)[f];
    }

    float m_i[4], l_i[4];
    float4 o_acc[4];
#pragma unroll
    for (int i = 0; i < 4; i++) {
        m_i[i] = -1e30f;
        l_i[i] = 0.0f;
        o_acc[i] = make_float4(0.f, 0.f, 0.f, 0.f);
    }

    for (int kc = 0; kc < SS / 32; kc++) {
        const float* kb = k + ((size_t)bh * SS + kc * 32) * HD;
        const float* vb = v + ((size_t)bh * SS + kc * 32) * HD;
#pragma unroll
        for (int i = 0; i < 2; i++) {
            int f = tid + i * 256;
            int r = f >> 4, c4 = f & 15;
            *(float4*)(&Ks[r][c4 * 4]) = ((const float4*)kb)[f];
            ((float4*)Vs)[f] = ((const float4*)vb)[f];
        }
        __syncthreads();

        float sc0[4] = {0.f, 0.f, 0.f, 0.f};
        float sc1[4] = {0.f, 0.f, 0.f, 0.f};
#pragma unroll
        for (int d4 = 0; d4 < 16; d4++) {
            float4 ka = *(const float4*)(&Ks[tx][d4 * 4]);
            float4 kbv = *(const float4*)(&Ks[tx + 16][d4 * 4]);
#pragma unroll
            for (int i = 0; i < 4; i++) {
                float4 qv = *(const float4*)(&Qs[ty * 4 + i][d4 * 4]);
                sc0[i] = fmaf(qv.x, ka.x, sc0[i]);
                sc0[i] = fmaf(qv.y, ka.y, sc0[i]);
                sc0[i] = fmaf(qv.z, ka.z, sc0[i]);
                sc0[i] = fmaf(qv.w, ka.w, sc0[i]);
                sc1[i] = fmaf(qv.x, kbv.x, sc1[i]);
                sc1[i] = fmaf(qv.y, kbv.y, sc1[i]);
                sc1[i] = fmaf(qv.z, kbv.z, sc1[i]);
                sc1[i] = fmaf(qv.w, kbv.w, sc1[i]);
            }
        }

        const int mk0 = mask[b_ * SS + kc * 32 + tx];
        const int mk1 = mask[b_ * SS + kc * 32 + tx + 16];

#pragma unroll
        for (int i = 0; i < 4; i++) {
            float s0 = sc0[i] * 0.125f;
            float s1 = sc1[i] * 0.125f;
            if (mk0 == 0) s0 = -1e9f;
            if (mk1 == 0) s1 = -1e9f;
            float mx = fmaxf(s0, s1);
#pragma unroll
            for (int off = 8; off >= 1; off >>= 1)
                mx = fmaxf(mx, __shfl_xor_sync(0xffffffffu, mx, off, 16));
            float mnew = fmaxf(m_i[i], mx);
            float corr = __expf(m_i[i] - mnew);
            float p0 = __expf(s0 - mnew);
            float p1 = __expf(s1 - mnew);
            Ss[ty * 4 + i][tx] = p0;
            Ss[ty * 4 + i][tx + 16] = p1;
            float ps = p0 + p1;
#pragma unroll
            for (int off = 8; off >= 1; off >>= 1)
                ps += __shfl_xor_sync(0xffffffffu, ps, off, 16);
            l_i[i] = l_i[i] * corr + ps;
            m_i[i] = mnew;
            o_acc[i].x *= corr;
            o_acc[i].y *= corr;
            o_acc[i].z *= corr;
            o_acc[i].w *= corr;
        }
        __syncthreads();

#pragma unroll
        for (int c4 = 0; c4 < 8; c4++) {
            float4 v0 = *(const float4*)(&Vs[c4 * 4 + 0][tx * 4]);
            float4 v1 = *(const float4*)(&Vs[c4 * 4 + 1][tx * 4]);
            float4 v2 = *(const float4*)(&Vs[c4 * 4 + 2][tx * 4]);
            float4 v3 = *(const float4*)(&Vs[c4 * 4 + 3][tx * 4]);
#pragma unroll
            for (int i = 0; i < 4; i++) {
                float4 p = *(const float4*)(&Ss[ty * 4 + i][c4 * 4]);
                o_acc[i].x = fmaf(p.x, v0.x, o_acc[i].x);
                o_acc[i].y = fmaf(p.x, v0.y, o_acc[i].y);
                o_acc[i].z = fmaf(p.x, v0.z, o_acc[i].z);
                o_acc[i].w = fmaf(p.x, v0.w, o_acc[i].w);
                o_acc[i].x = fmaf(p.y, v1.x, o_acc[i].x);
                o_acc[i].y = fmaf(p.y, v1.y, o_acc[i].y);
                o_acc[i].z = fmaf(p.y, v1.z, o_acc[i].z);
                o_acc[i].w = fmaf(p.y, v1.w, o_acc[i].w);
                o_acc[i].x = fmaf(p.z, v2.x, o_acc[i].x);
                o_acc[i].y = fmaf(p.z, v2.y, o_acc[i].y);
                o_acc[i].z = fmaf(p.z, v2.z, o_acc[i].z);
                o_acc[i].w = fmaf(p.z, v2.w, o_acc[i].w);
                o_acc[i].x = fmaf(p.w, v3.x, o_acc[i].x);
                o_acc[i].y = fmaf(p.w, v3.y, o_acc[i].y);
                o_acc[i].z = fmaf(p.w, v3.z, o_acc[i].z);
                o_acc[i].w = fmaf(p.w, v3.w, o_acc[i].w);
            }
        }
        __syncthreads();
    }

#pragma unroll
    for (int i = 0; i < 4; i++) {
        float inv = 1.0f / l_i[i];
        int row = q0 + ty * 4 + i;
        float4 r4 = make_float4(o_acc[i].x * inv, o_acc[i].y * inv,
                                o_acc[i].z * inv, o_acc[i].w * inv);
        *(float4*)(out + ((size_t)(b_ * SS + row)) * DD + h_ * HD + tx * 4) = r4;
    }
}

// ---------------------------------------------------------------------------
// Fused residual + bias + LayerNorm: out = LN(a + b + bias) * g + be
// ---------------------------------------------------------------------------
__global__ __launch_bounds__(256) void add_ln_kernel(
    const float* __restrict__ a, const float* __restrict__ b,
    const float* __restrict__ bias,
    const float* __restrict__ g, const float* __restrict__ be,
    float* __restrict__ out)
{
    __shared__ float sh[10];
    const int row = blockIdx.x;
    const int tid = threadIdx.x;
    const int wid = tid >> 5, lane = tid & 31;
    const size_t base = (size_t)row * DD + tid * 4;

    float4 av = *(const float4*)(a + base);
    float4 bv = *(const float4*)(b + base);
    float4 cv = *(const float4*)(bias + tid * 4);
    float4 t = make_float4(av.x + bv.x + cv.x, av.y + bv.y + cv.y,
                           av.z + bv.z + cv.z, av.w + bv.w + cv.w);

    float s = t.x + t.y + t.z + t.w;
#pragma unroll
    for (int off = 16; off >= 1; off >>= 1)
        s += __shfl_xor_sync(0xffffffffu, s, off);
    if (lane == 0) sh[wid] = s;
    __syncthreads();
    if (tid == 0) {
        float t2 = 0.f;
#pragma unroll
        for (int w = 0; w < 8; w++) t2 += sh[w];
        sh[8] = t2 * (1.0f / 1024.0f);
    }
    __syncthreads();
    float mu = sh[8];

    float dx = t.x - mu, dy = t.y - mu, dz = t.z - mu, dw = t.w - mu;
    float sq = dx * dx + dy * dy + dz * dz + dw * dw;
#pragma unroll
    for (int off = 16; off >= 1; off >>= 1)
        sq += __shfl_xor_sync(0xffffffffu, sq, off);
    if (lane == 0) sh[wid] = sq;
    __syncthreads();
    if (tid == 0) {
        float t2 = 0.f;
#pragma unroll
        for (int w = 0; w < 8; w++) t2 += sh[w];
        sh[9] = rsqrtf(t2 * (1.0f / 1024.0f) + 1e-5f);
    }
    __syncthreads();
    float inv = sh[9];

    float4 gv = *(const float4*)(g + tid * 4);
    float4 bev = *(const float4*)(be + tid * 4);
    float4 r = make_float4(dx * inv * gv.x + bev.x,
                           dy * inv * gv.y + bev.y,
                           dz * inv * gv.z + bev.z,
                           dw * inv * gv.w + bev.w);
    *(float4*)(out + base) = r;
}

// ---------------------------------------------------------------------------
extern "C" void kernel_launch(void* const* d_in, const int* in_sizes, int n_in,
                              void* d_out, int out_size)
{
    const float* x   = (const float*)d_in[0];
    const int*   msk = (const int*)d_in[1];
    const float* Wq  = (const float*)d_in[2];
    const float* bq  = (const float*)d_in[3];
    const float* Wk  = (const float*)d_in[4];
    const float* bk  = (const float*)d_in[5];
    const float* Wv  = (const float*)d_in[6];
    const float* bv  = (const float*)d_in[7];
    const float* Wo  = (const float*)d_in[8];
    const float* bo  = (const float*)d_in[9];
    const float* W1  = (const float*)d_in[10];
    const float* b1  = (const float*)d_in[11];
    const float* W2  = (const float*)d_in[12];
    const float* b2  = (const float*)d_in[13];
    const float* g1  = (const float*)d_in[14];
    const float* be1 = (const float*)d_in[15];
    const float* g2  = (const float*)d_in[16];
    const float* be2 = (const float*)d_in[17];
    float* out = (float*)d_out;

    float *q, *kb, *vb, *attn, *ffh;
    cudaGetSymbolAddress((void**)&q,    g_q);
    cudaGetSymbolAddress((void**)&kb,   g_k);
    cudaGetSymbolAddress((void**)&vb,   g_v);
    cudaGetSymbolAddress((void**)&attn, g_attn);
    cudaGetSymbolAddress((void**)&ffh,  g_ff);

    dim3 blk(256);
    dim3 gD(DD / 128, MM / 128);   // (8, 64)
    dim3 gF(FF / 128, MM / 128);   // (32, 64)

    // QKV projections (tf32 tensor cores) -> stage -> scatter to head layout
    gemm_tf32_kernel<<<gD, blk>>>(x, Wq, attn, MM, DD, DD);
    scatter_bias_kernel<<<MM, blk>>>(attn, bq, q);
    gemm_tf32_kernel<<<gD, blk>>>(x, Wk, attn, MM, DD, DD);
    scatter_bias_kernel<<<MM, blk>>>(attn, bk, kb);
    gemm_tf32_kernel<<<gD, blk>>>(x, Wv, attn, MM, DD, DD);
    scatter_bias_kernel<<<MM, blk>>>(attn, bv, vb);

    // Flash attention -> token layout [M, D]
    flash_kernel<<<dim3(SS / 64, BB * HH), blk>>>(q, kb, vb, msk, attn);

    // Output projection; h = LN(x + o + bo) -> g_q
    gemm_tf32_kernel<<<gD, blk>>>(attn, Wo, ffh, MM, DD, DD);
    add_ln_kernel<<<MM, blk>>>(x, ffh, bo, g1, be1, q);

    // FFN
    gemm_tf32_kernel<<<gF, blk>>>(q, W1, ffh, MM, FF, DD);
    bias_relu_kernel<<<(size_t)MM * FF / 1024, blk>>>(ffh, b1);
    gemm_tf32_kernel<<<gD, blk>>>(ffh, W2, kb, MM, DD, FF);

    // out = LN(h + ffn + b2)
    add_ln_kernel<<<MM, blk>>>(q, kb, b2, g2, be2, out);
}

// round 5
// speedup vs baseline: 1.2540x; 1.2247x over previous
#include <cuda_runtime.h>
#include <cuda_bf16.h>
#include <math.h>
#include <stdint.h>

// Problem constants
constexpr int BB = 4;
constexpr int SS = 2048;
constexpr int DD = 1024;
constexpr int HH = 16;
constexpr int HD = 64;
constexpr int FF = 4096;
constexpr int MM = BB * SS;  // 8192 tokens

// tcgen05 available only in the arch-specific (sm_103a/sm_100a) device pass.
#if defined(__CUDA_ARCH_FEAT_SM103_ALL) || defined(__CUDA_ARCH_FEAT_SM100_ALL)
#define HAS_TCGEN05 1
#else
#define HAS_TCGEN05 0
#endif

// Scratch (device globals; no allocation allowed)
__device__ float g_q[(size_t)MM * DD];
__device__ float g_k[(size_t)MM * DD];
__device__ float g_v[(size_t)MM * DD];
__device__ float g_attn[(size_t)MM * DD];
__device__ float g_ff[(size_t)MM * FF];

// Weight scratch: transposed [N][K] bf16 hi/lo splits
constexpr size_t WQ_OFF = 0;
constexpr size_t WK_OFF = 1048576;
constexpr size_t WV_OFF = 2097152;
constexpr size_t WO_OFF = 3145728;
constexpr size_t W1_OFF = 4194304;
constexpr size_t W2_OFF = 8388608;
constexpr size_t WTOT   = 12582912;
__device__ __nv_bfloat16 g_wh[WTOT];
__device__ __nv_bfloat16 g_wl[WTOT];

// ---------------------------------------------------------------------------
// PTX helpers
// ---------------------------------------------------------------------------
__device__ __forceinline__ uint32_t smem_u32(const void* p) {
    uint32_t a;
    asm("{ .reg .u64 t; cvta.to.shared.u64 t, %1; cvt.u32.u64 %0, t; }"
        : "=r"(a) : "l"(p));
    return a;
}

#if HAS_TCGEN05
__device__ __forceinline__ uint32_t elect_one_pred() {
    uint32_t pred;
    asm volatile(
        "{\n\t.reg .pred p;\n\t"
        "elect.sync _|p, 0xFFFFFFFF;\n\t"
        "selp.b32 %0, 1, 0, p;\n\t}"
        : "=r"(pred));
    return pred;
}
#define TCGEN05_ALLOC(smem_addr, nCols) \
    asm volatile("tcgen05.alloc.cta_group::1.sync.aligned.shared::cta.b32 [%0], %1;" \
        :: "r"((uint32_t)(smem_addr)), "r"((uint32_t)(nCols)) : "memory")
#define TCGEN05_DEALLOC(tmem_addr, nCols) \
    asm volatile("tcgen05.dealloc.cta_group::1.sync.aligned.b32 %0, %1;" \
        :: "r"(tmem_addr), "r"((uint32_t)(nCols)))
#define TCGEN05_COMMIT(mbar) \
    asm volatile("tcgen05.commit.cta_group::1.mbarrier::arrive::one.shared::cluster.b64 [%0];" \
        :: "r"((uint32_t)(mbar)) : "memory")
#define TCGEN05_WAIT_LD()  asm volatile("tcgen05.wait::ld.sync.aligned;" ::: "memory")
#define TCGEN05_FENCE_BEFORE() asm volatile("tcgen05.fence::before_thread_sync;" ::: "memory")
#define TCGEN05_FENCE_AFTER()  asm volatile("tcgen05.fence::after_thread_sync;" ::: "memory")
#define FENCE_ASYNC_SHARED() asm volatile("fence.proxy.async.shared::cta;" ::: "memory")
#define MBARRIER_INIT(mbar, cnt) \
    asm volatile("mbarrier.init.shared.b64 [%0], %1;" \
        :: "r"((uint32_t)(mbar)), "r"((uint32_t)(cnt)) : "memory")
#define MBARRIER_INVAL(mbar) \
    asm volatile("mbarrier.inval.shared.b64 [%0];" :: "r"((uint32_t)(mbar)) : "memory")
#define MBARRIER_WAIT_PARITY(mbar, parity) do {                                    \
    uint32_t _mb = (uint32_t)(mbar);                                               \
    uint32_t _pa = (uint32_t)(parity);                                             \
    uint32_t _done;                                                                \
    asm volatile(                                                                  \
        "{\n\t.reg .pred p;\n\t"                                                   \
        "mbarrier.try_wait.parity.acquire.cta.shared::cta.b64 p, [%1], %2;\n\t"    \
        "selp.b32 %0, 1, 0, p;\n\t}"                                               \
        : "=r"(_done) : "r"(_mb), "r"(_pa) : "memory");                            \
    if (!_done) {                                                                  \
        asm volatile(                                                              \
            "{\n\t.reg .pred P1;\n\t"                                              \
            "WL_%=:\n\t"                                                           \
            "mbarrier.try_wait.parity.acquire.cta.shared::cta.b64 P1, [%0], %1, 0x989680;\n\t" \
            "@P1 bra.uni WD_%=;\n\t"                                               \
            "bra.uni WL_%=;\n\t"                                                   \
            "WD_%=:\n\t}"                                                          \
            :: "r"(_mb), "r"(_pa) : "memory");                                     \
    }                                                                              \
} while (0)
#define TCGEN05_LD_X32(r, addr) \
    asm volatile( \
        "tcgen05.ld.sync.aligned.32x32b.x32.b32 " \
        "{%0, %1, %2, %3, %4, %5, %6, %7, " \
        " %8, %9, %10, %11, %12, %13, %14, %15, " \
        " %16, %17, %18, %19, %20, %21, %22, %23, " \
        " %24, %25, %26, %27, %28, %29, %30, %31}, [%32];" \
        : "=r"((r)[0]),  "=r"((r)[1]),  "=r"((r)[2]),  "=r"((r)[3]), \
          "=r"((r)[4]),  "=r"((r)[5]),  "=r"((r)[6]),  "=r"((r)[7]), \
          "=r"((r)[8]),  "=r"((r)[9]),  "=r"((r)[10]), "=r"((r)[11]), \
          "=r"((r)[12]), "=r"((r)[13]), "=r"((r)[14]), "=r"((r)[15]), \
          "=r"((r)[16]), "=r"((r)[17]), "=r"((r)[18]), "=r"((r)[19]), \
          "=r"((r)[20]), "=r"((r)[21]), "=r"((r)[22]), "=r"((r)[23]), \
          "=r"((r)[24]), "=r"((r)[25]), "=r"((r)[26]), "=r"((r)[27]), \
          "=r"((r)[28]), "=r"((r)[29]), "=r"((r)[30]), "=r"((r)[31]) \
        : "r"(addr))

// SW128 smem descriptor: layout=SW128, version=1 (Blackwell), SBO=64, LBO=1
__device__ __forceinline__ uint64_t make_desc_sw128(uint32_t addr) {
    constexpr uint64_t BASE =
        (uint64_t(2) << 61) | (uint64_t(1) << 46) | (uint64_t(64) << 32) | (uint64_t(1) << 16);
    return BASE | ((uint64_t)(addr >> 4) & 0x3FFF);
}
// cg1 SS bf16 MMA
__device__ __forceinline__ void mma_bf16_ss(uint32_t d, uint64_t ad, uint64_t bd,
                                            uint32_t idesc, bool acc) {
    uint32_t en = acc ? 1u : 0u;
    asm volatile(
        "{\n\t.reg .pred p;\n\t"
        "setp.ne.u32 p, %5, 0;\n\t"
        "tcgen05.mma.cta_group::1.kind::f16 [%0], %1, %2, %3, {%4, %4, %4, %4}, p;\n\t}"
        :: "r"(d), "l"(ad), "l"(bd), "r"(idesc), "r"(0u), "r"(en) : "memory");
}
#endif  // HAS_TCGEN05

__device__ __forceinline__ uint32_t swz128(uint32_t off) {
    return off ^ ((off >> 3) & 0x70);
}

// idesc: dtype F32, atype/btype BF16, N=128, M=128
constexpr uint32_t GEMM_IDESC =
    (1u << 4) | (1u << 7) | (1u << 10) | ((128 / 8) << 17) | ((128 / 16) << 24);

// ---------------------------------------------------------------------------
// Weight prep: W[K][N] fp32 -> Bh/Bl [N][K] bf16 (hi/lo split), transposed.
// ---------------------------------------------------------------------------
__global__ void prep_w_kernel(const float* __restrict__ W,
                              __nv_bfloat16* __restrict__ Bh,
                              __nv_bfloat16* __restrict__ Bl, int K, int N)
{
    __shared__ float t[32][33];
    const int n0 = blockIdx.x * 32, k0 = blockIdx.y * 32;
#pragma unroll
    for (int i = 0; i < 4; i++)
        t[threadIdx.y + i * 8][threadIdx.x] =
            W[(size_t)(k0 + threadIdx.y + i * 8) * N + n0 + threadIdx.x];
    __syncthreads();
#pragma unroll
    for (int i = 0; i < 4; i++) {
        int n = threadIdx.y + i * 8;
        float v = t[threadIdx.x][n];
        __nv_bfloat16 h = __float2bfloat16(v);
        float lo = v - __bfloat162float(h);
        size_t idx = (size_t)(n0 + n) * K + k0 + threadIdx.x;
        Bh[idx] = h;
        Bl[idx] = __float2bfloat16(lo);
    }
}

// ---------------------------------------------------------------------------
// GEMM: C[M,N] = A[M,K](fp32) @ B^T, B = [N][K] bf16 hi/lo.
// sm_103a pass: tcgen05, 128x128 tile, TMEM accum, double-buffered smem.
// base pass (fallback): classic tiled FFMA SGEMM, correct but slower.
// ---------------------------------------------------------------------------
constexpr int GEMM_SMEM_BYTES = 131072 + 1024;

__global__ __launch_bounds__(256, 1) void gemm_tc_kernel(
    const float* __restrict__ A,
    const __nv_bfloat16* __restrict__ Bh, const __nv_bfloat16* __restrict__ Bl,
    float* __restrict__ C, int M, int N, int K)
{
    extern __shared__ char dsmem[];
    uintptr_t p = ((uintptr_t)dsmem + 1023) & ~(uintptr_t)1023;
    char* buf = (char*)p;

    const int tid = threadIdx.x;
    const int wid = tid >> 5;
    const int lane = tid & 31;
    const int m0 = blockIdx.y << 7;
    const int n0 = blockIdx.x << 7;

#if HAS_TCGEN05
    __shared__ alignas(16) unsigned long long ctrlq[4];
    const uint32_t sbuf = smem_u32(buf);
    const uint32_t ctrl = smem_u32(ctrlq);

    if (wid == 0) TCGEN05_ALLOC(ctrl, 128);
    if (tid == 0) {
        MBARRIER_INIT(ctrl + 8, 1);
        MBARRIER_INIT(ctrl + 16, 1);
        MBARRIER_INIT(ctrl + 24, 1);
    }
    __syncthreads();
    uint32_t tmem;
    asm volatile("ld.shared.b32 %0, [%1];" : "=r"(tmem) : "r"(ctrl));

    const int NC = K >> 6;
    int ph0 = 0, ph1 = 0;

    const float* Ab = A + (size_t)m0 * K;
    const __nv_bfloat16* Bhb = Bh + (size_t)n0 * K;
    const __nv_bfloat16* Blb = Bl + (size_t)n0 * K;

    for (int i = 0; i < NC; i++) {
        const int b = i & 1;
        const uint32_t boff = (uint32_t)b << 16;  // 65536
        const int k0 = i << 6;

        if (i >= 2) {
            if (b == 0) { MBARRIER_WAIT_PARITY(ctrl + 8, ph0); ph0 ^= 1; }
            else        { MBARRIER_WAIT_PARITY(ctrl + 16, ph1); ph1 ^= 1; }
        }

        // A tile: fp32 -> bf16 hi/lo, swizzled SW128 rows of 128B
        float4 af[8];
#pragma unroll
        for (int j = 0; j < 2; j++) {
            int u = tid + j * 256;
            int r = u >> 2;
            int kq = (u & 3) * 16;
            const float* ap = Ab + (size_t)r * K + k0 + kq;
#pragma unroll
            for (int t = 0; t < 4; t++) af[j * 4 + t] = *(const float4*)(ap + t * 4);
        }
        uint4 bhr[4], blr[4];
#pragma unroll
        for (int j = 0; j < 4; j++) {
            int u = tid + j * 256;
            int r = u >> 3;
            int kk = (u & 7) * 8;
            bhr[j] = *(const uint4*)(Bhb + (size_t)r * K + k0 + kk);
            blr[j] = *(const uint4*)(Blb + (size_t)r * K + k0 + kk);
        }
#pragma unroll
        for (int j = 0; j < 2; j++) {
            int u = tid + j * 256;
            int r = u >> 2;
            int kq = (u & 3) * 16;
            uint32_t hi[8], lo[8];
            const float* fv = (const float*)&af[j * 4];
#pragma unroll
            for (int e = 0; e < 8; e++) {
                float x = fv[2 * e], y = fv[2 * e + 1];
                __nv_bfloat16 hx = __float2bfloat16(x), hy = __float2bfloat16(y);
                float lx = x - __bfloat162float(hx);
                float ly = y - __bfloat162float(hy);
                __nv_bfloat162 hp; hp.x = hx; hp.y = hy;
                __nv_bfloat162 lp; lp.x = __float2bfloat16(lx); lp.y = __float2bfloat16(ly);
                hi[e] = *(uint32_t*)&hp;
                lo[e] = *(uint32_t*)&lp;
            }
            uint32_t o0 = (uint32_t)(r * 128 + kq * 2);
            *(uint4*)(buf + boff + swz128(o0))              = make_uint4(hi[0], hi[1], hi[2], hi[3]);
            *(uint4*)(buf + boff + swz128(o0 + 16))         = make_uint4(hi[4], hi[5], hi[6], hi[7]);
            *(uint4*)(buf + boff + 16384 + swz128(o0))      = make_uint4(lo[0], lo[1], lo[2], lo[3]);
            *(uint4*)(buf + boff + 16384 + swz128(o0 + 16)) = make_uint4(lo[4], lo[5], lo[6], lo[7]);
        }
#pragma unroll
        for (int j = 0; j < 4; j++) {
            int u = tid + j * 256;
            int r = u >> 3;
            int kk = (u & 7) * 8;
            uint32_t o = swz128((uint32_t)(r * 128 + kk * 2));
            *(uint4*)(buf + boff + 32768 + o) = bhr[j];
            *(uint4*)(buf + boff + 49152 + o) = blr[j];
        }

        FENCE_ASYNC_SHARED();
        __syncthreads();

        if (wid == 0 && elect_one_pred()) {
            uint64_t dAh = make_desc_sw128(sbuf + boff);
            uint64_t dAl = make_desc_sw128(sbuf + boff + 16384);
            uint64_t dBh = make_desc_sw128(sbuf + boff + 32768);
            uint64_t dBl = make_desc_sw128(sbuf + boff + 49152);
#pragma unroll
            for (int ks = 0; ks < 4; ks++)
                mma_bf16_ss(tmem, dAh + ks * 2, dBh + ks * 2, GEMM_IDESC, !(i == 0 && ks == 0));
#pragma unroll
            for (int ks = 0; ks < 4; ks++)
                mma_bf16_ss(tmem, dAl + ks * 2, dBh + ks * 2, GEMM_IDESC, true);
#pragma unroll
            for (int ks = 0; ks < 4; ks++)
                mma_bf16_ss(tmem, dAh + ks * 2, dBl + ks * 2, GEMM_IDESC, true);
            TCGEN05_COMMIT(ctrl + 8 + (b << 3));
        }
    }

    if (wid == 0 && elect_one_pred()) TCGEN05_COMMIT(ctrl + 24);
    MBARRIER_WAIT_PARITY(ctrl + 24, 0);
    TCGEN05_FENCE_AFTER();

    // epilogue: 8 warps read TMEM (warp%4 = subpartition, warp/4 = col half)
    {
        const int sp = wid & 3;
        const int ch = wid >> 2;
        uint32_t r[64];
        TCGEN05_LD_X32(r, tmem + ch * 64);
        TCGEN05_LD_X32(r + 32, tmem + ch * 64 + 32);
        TCGEN05_WAIT_LD();
        TCGEN05_FENCE_BEFORE();

        const int row = m0 + sp * 32 + lane;
        float* cp = C + (size_t)row * N + n0 + ch * 64;
#pragma unroll
        for (int c = 0; c < 16; c++) {
            float4 v;
            v.x = __uint_as_float(r[4 * c + 0]);
            v.y = __uint_as_float(r[4 * c + 1]);
            v.z = __uint_as_float(r[4 * c + 2]);
            v.w = __uint_as_float(r[4 * c + 3]);
            *(float4*)(cp + 4 * c) = v;
        }
    }

    __syncthreads();
    if (tid == 0) {
        MBARRIER_INVAL(ctrl + 8);
        MBARRIER_INVAL(ctrl + 16);
        MBARRIER_INVAL(ctrl + 24);
    }
    __syncthreads();
    if (wid == 0) TCGEN05_DEALLOC(tmem, 128);

#else  // ---------------- FFMA fallback (base-arch pass) ----------------
    // As[16][132] transposed A tile, Bs[16][132] B tile (k-major), FFMA 8x8.
    float* As = (float*)buf;               // 16*132 floats
    float* Bs = As + 16 * 132;
    const int tx = tid & 15;
    const int ty = tid >> 4;

    float acc[8][8];
#pragma unroll
    for (int i = 0; i < 8; i++)
#pragma unroll
        for (int j = 0; j < 8; j++) acc[i][j] = 0.0f;

    for (int k0 = 0; k0 < K; k0 += 16) {
        {
            int r = tid >> 2, q = (tid & 3) * 4;
#pragma unroll
            for (int i = 0; i < 2; i++) {
                int rr = r + i * 64;
                float4 v = *(const float4*)(A + (size_t)(m0 + rr) * K + k0 + q);
                As[(q + 0) * 132 + rr] = v.x;
                As[(q + 1) * 132 + rr] = v.y;
                As[(q + 2) * 132 + rr] = v.z;
                As[(q + 3) * 132 + rr] = v.w;
            }
            int n = tid >> 1, half = (tid & 1) * 8;
            const __nv_bfloat16* bhp = Bh + (size_t)(n0 + n) * K + k0 + half;
            const __nv_bfloat16* blp = Bl + (size_t)(n0 + n) * K + k0 + half;
#pragma unroll
            for (int e = 0; e < 8; e++)
                Bs[(half + e) * 132 + n] =
                    __bfloat162float(bhp[e]) + __bfloat162float(blp[e]);
        }
        __syncthreads();
#pragma unroll
        for (int k = 0; k < 16; k++) {
            float a[8], bvv[8];
#pragma unroll
            for (int i = 0; i < 8; i++) a[i] = As[k * 132 + ty * 8 + i];
#pragma unroll
            for (int j = 0; j < 8; j++) bvv[j] = Bs[k * 132 + tx * 8 + j];
#pragma unroll
            for (int i = 0; i < 8; i++)
#pragma unroll
                for (int j = 0; j < 8; j++)
                    acc[i][j] = fmaf(a[i], bvv[j], acc[i][j]);
        }
        __syncthreads();
    }
#pragma unroll
    for (int i = 0; i < 8; i++) {
        int row = m0 + ty * 8 + i;
#pragma unroll
        for (int jj = 0; jj < 8; jj += 4) {
            float4 r4 = make_float4(acc[i][jj], acc[i][jj + 1], acc[i][jj + 2], acc[i][jj + 3]);
            *(float4*)(C + (size_t)row * N + n0 + tx * 8 + jj) = r4;
        }
    }
#endif
}

// ---------------------------------------------------------------------------
// QKV epilogue: add bias, scatter token layout [M,D] -> heads [B,H,S,hd]
// ---------------------------------------------------------------------------
__global__ __launch_bounds__(256) void scatter_bias_kernel(
    const float* __restrict__ in, const float* __restrict__ bias,
    float* __restrict__ out)
{
    const int row = blockIdx.x;
    const int col = threadIdx.x * 4;
    float4 v = *(const float4*)(in + (size_t)row * DD + col);
    float4 bv = *(const float4*)(bias + col);
    v.x += bv.x; v.y += bv.y; v.z += bv.z; v.w += bv.w;
    int b_ = row >> 11;
    int s_ = row & (SS - 1);
    int h_ = col >> 6;
    int dh = col & (HD - 1);
    *(float4*)(out + (((size_t)b_ * HH + h_) * SS + s_) * HD + dh) = v;
}

// FFN1 epilogue: in-place bias + ReLU over [M, FF]
__global__ __launch_bounds__(256) void bias_relu_kernel(
    float* __restrict__ io, const float* __restrict__ bias)
{
    size_t idx = ((size_t)blockIdx.x * 256 + threadIdx.x) * 4;
    int col = (int)(idx & (FF - 1));
    float4 v = *(const float4*)(io + idx);
    float4 bv = *(const float4*)(bias + col);
    v.x = fmaxf(v.x + bv.x, 0.0f);
    v.y = fmaxf(v.y + bv.y, 0.0f);
    v.z = fmaxf(v.z + bv.z, 0.0f);
    v.w = fmaxf(v.w + bv.w, 0.0f);
    *(float4*)(io + idx) = v;
}

// ---------------------------------------------------------------------------
// Flash attention (fp32, unchanged — verified in rounds 1-2)
// ---------------------------------------------------------------------------
__global__ __launch_bounds__(256) void flash_kernel(
    const float* __restrict__ q, const float* __restrict__ k,
    const float* __restrict__ v, const int* __restrict__ mask,
    float* __restrict__ out)
{
    __shared__ float Qs[64][64];
    __shared__ float Ks[32][68];
    __shared__ float Vs[32][64];
    __shared__ float Ssm[64][32];

    const int tid = threadIdx.x;
    const int tx = tid & 15;
    const int ty = tid >> 4;
    const int bh = blockIdx.y;
    const int b_ = bh >> 4;
    const int h_ = bh & (HH - 1);
    const int q0 = blockIdx.x * 64;

    const float* qb = q + ((size_t)bh * SS + q0) * HD;
#pragma unroll
    for (int i = 0; i < 4; i++) {
        int f = tid + i * 256;
        ((float4*)Qs)[f] = ((const float4*)qb)[f];
    }

    float m_i[4], l_i[4];
    float4 o_acc[4];
#pragma unroll
    for (int i = 0; i < 4; i++) {
        m_i[i] = -1e30f;
        l_i[i] = 0.0f;
        o_acc[i] = make_float4(0.f, 0.f, 0.f, 0.f);
    }

    for (int kc = 0; kc < SS / 32; kc++) {
        const float* kb = k + ((size_t)bh * SS + kc * 32) * HD;
        const float* vb = v + ((size_t)bh * SS + kc * 32) * HD;
#pragma unroll
        for (int i = 0; i < 2; i++) {
            int f = tid + i * 256;
            int r = f >> 4, c4 = f & 15;
            *(float4*)(&Ks[r][c4 * 4]) = ((const float4*)kb)[f];
            ((float4*)Vs)[f] = ((const float4*)vb)[f];
        }
        __syncthreads();

        float sc0[4] = {0.f, 0.f, 0.f, 0.f};
        float sc1[4] = {0.f, 0.f, 0.f, 0.f};
#pragma unroll
        for (int d4 = 0; d4 < 16; d4++) {
            float4 ka = *(const float4*)(&Ks[tx][d4 * 4]);
            float4 kbv = *(const float4*)(&Ks[tx + 16][d4 * 4]);
#pragma unroll
            for (int i = 0; i < 4; i++) {
                float4 qv = *(const float4*)(&Qs[ty * 4 + i][d4 * 4]);
                sc0[i] = fmaf(qv.x, ka.x, sc0[i]);
                sc0[i] = fmaf(qv.y, ka.y, sc0[i]);
                sc0[i] = fmaf(qv.z, ka.z, sc0[i]);
                sc0[i] = fmaf(qv.w, ka.w, sc0[i]);
                sc1[i] = fmaf(qv.x, kbv.x, sc1[i]);
                sc1[i] = fmaf(qv.y, kbv.y, sc1[i]);
                sc1[i] = fmaf(qv.z, kbv.z, sc1[i]);
                sc1[i] = fmaf(qv.w, kbv.w, sc1[i]);
            }
        }

        const int mk0 = mask[b_ * SS + kc * 32 + tx];
        const int mk1 = mask[b_ * SS + kc * 32 + tx + 16];

#pragma unroll
        for (int i = 0; i < 4; i++) {
            float s0 = sc0[i] * 0.125f;
            float s1 = sc1[i] * 0.125f;
            if (mk0 == 0) s0 = -1e9f;
            if (mk1 == 0) s1 = -1e9f;
            float mx = fmaxf(s0, s1);
#pragma unroll
            for (int off = 8; off >= 1; off >>= 1)
                mx = fmaxf(mx, __shfl_xor_sync(0xffffffffu, mx, off, 16));
            float mnew = fmaxf(m_i[i], mx);
            float corr = __expf(m_i[i] - mnew);
            float p0 = __expf(s0 - mnew);
            float p1 = __expf(s1 - mnew);
            Ssm[ty * 4 + i][tx] = p0;
            Ssm[ty * 4 + i][tx + 16] = p1;
            float ps = p0 + p1;
#pragma unroll
            for (int off = 8; off >= 1; off >>= 1)
                ps += __shfl_xor_sync(0xffffffffu, ps, off, 16);
            l_i[i] = l_i[i] * corr + ps;
            m_i[i] = mnew;
            o_acc[i].x *= corr;
            o_acc[i].y *= corr;
            o_acc[i].z *= corr;
            o_acc[i].w *= corr;
        }
        __syncthreads();

#pragma unroll
        for (int c4 = 0; c4 < 8; c4++) {
            float4 v0 = *(const float4*)(&Vs[c4 * 4 + 0][tx * 4]);
            float4 v1 = *(const float4*)(&Vs[c4 * 4 + 1][tx * 4]);
            float4 v2 = *(const float4*)(&Vs[c4 * 4 + 2][tx * 4]);
            float4 v3 = *(const float4*)(&Vs[c4 * 4 + 3][tx * 4]);
#pragma unroll
            for (int i = 0; i < 4; i++) {
                float4 pp = *(const float4*)(&Ssm[ty * 4 + i][c4 * 4]);
                o_acc[i].x = fmaf(pp.x, v0.x, o_acc[i].x);
                o_acc[i].y = fmaf(pp.x, v0.y, o_acc[i].y);
                o_acc[i].z = fmaf(pp.x, v0.z, o_acc[i].z);
                o_acc[i].w = fmaf(pp.x, v0.w, o_acc[i].w);
                o_acc[i].x = fmaf(pp.y, v1.x, o_acc[i].x);
                o_acc[i].y = fmaf(pp.y, v1.y, o_acc[i].y);
                o_acc[i].z = fmaf(pp.y, v1.z, o_acc[i].z);
                o_acc[i].w = fmaf(pp.y, v1.w, o_acc[i].w);
                o_acc[i].x = fmaf(pp.z, v2.x, o_acc[i].x);
                o_acc[i].y = fmaf(pp.z, v2.y, o_acc[i].y);
                o_acc[i].z = fmaf(pp.z, v2.z, o_acc[i].z);
                o_acc[i].w = fmaf(pp.z, v2.w, o_acc[i].w);
                o_acc[i].x = fmaf(pp.w, v3.x, o_acc[i].x);
                o_acc[i].y = fmaf(pp.w, v3.y, o_acc[i].y);
                o_acc[i].z = fmaf(pp.w, v3.z, o_acc[i].z);
                o_acc[i].w = fmaf(pp.w, v3.w, o_acc[i].w);
            }
        }
        __syncthreads();
    }

#pragma unroll
    for (int i = 0; i < 4; i++) {
        float inv = 1.0f / l_i[i];
        int row = q0 + ty * 4 + i;
        float4 r4 = make_float4(o_acc[i].x * inv, o_acc[i].y * inv,
                                o_acc[i].z * inv, o_acc[i].w * inv);
        *(float4*)(out + ((size_t)(b_ * SS + row)) * DD + h_ * HD + tx * 4) = r4;
    }
}

// ---------------------------------------------------------------------------
// Fused residual + bias + LayerNorm: out = LN(a + b + bias) * g + be
// ---------------------------------------------------------------------------
__global__ __launch_bounds__(256) void add_ln_kernel(
    const float* __restrict__ a, const float* __restrict__ b,
    const float* __restrict__ bias,
    const float* __restrict__ g, const float* __restrict__ be,
    float* __restrict__ out)
{
    __shared__ float sh[10];
    const int row = blockIdx.x;
    const int tid = threadIdx.x;
    const int wid = tid >> 5, lane = tid & 31;
    const size_t base = (size_t)row * DD + tid * 4;

    float4 av = *(const float4*)(a + base);
    float4 bv = *(const float4*)(b + base);
    float4 cv = *(const float4*)(bias + tid * 4);
    float4 t = make_float4(av.x + bv.x + cv.x, av.y + bv.y + cv.y,
                           av.z + bv.z + cv.z, av.w + bv.w + cv.w);

    float s = t.x + t.y + t.z + t.w;
#pragma unroll
    for (int off = 16; off >= 1; off >>= 1)
        s += __shfl_xor_sync(0xffffffffu, s, off);
    if (lane == 0) sh[wid] = s;
    __syncthreads();
    if (tid == 0) {
        float t2 = 0.f;
#pragma unroll
        for (int w = 0; w < 8; w++) t2 += sh[w];
        sh[8] = t2 * (1.0f / 1024.0f);
    }
    __syncthreads();
    float mu = sh[8];

    float dx = t.x - mu, dy = t.y - mu, dz = t.z - mu, dw = t.w - mu;
    float sq = dx * dx + dy * dy + dz * dz + dw * dw;
#pragma unroll
    for (int off = 16; off >= 1; off >>= 1)
        sq += __shfl_xor_sync(0xffffffffu, sq, off);
    if (lane == 0) sh[wid] = sq;
    __syncthreads();
    if (tid == 0) {
        float t2 = 0.f;
#pragma unroll
        for (int w = 0; w < 8; w++) t2 += sh[w];
        sh[9] = rsqrtf(t2 * (1.0f / 1024.0f) + 1e-5f);
    }
    __syncthreads();
    float inv = sh[9];

    float4 gv = *(const float4*)(g + tid * 4);
    float4 bev = *(const float4*)(be + tid * 4);
    float4 r = make_float4(dx * inv * gv.x + bev.x,
                           dy * inv * gv.y + bev.y,
                           dz * inv * gv.z + bev.z,
                           dw * inv * gv.w + bev.w);
    *(float4*)(out + base) = r;
}

// ---------------------------------------------------------------------------
extern "C" void kernel_launch(void* const* d_in, const int* in_sizes, int n_in,
                              void* d_out, int out_size)
{
    const float* x   = (const float*)d_in[0];
    const int*   msk = (const int*)d_in[1];
    const float* Wq  = (const float*)d_in[2];
    const float* bq  = (const float*)d_in[3];
    const float* Wk  = (const float*)d_in[4];
    const float* bk  = (const float*)d_in[5];
    const float* Wv  = (const float*)d_in[6];
    const float* bv  = (const float*)d_in[7];
    const float* Wo  = (const float*)d_in[8];
    const float* bo  = (const float*)d_in[9];
    const float* W1  = (const float*)d_in[10];
    const float* b1  = (const float*)d_in[11];
    const float* W2  = (const float*)d_in[12];
    const float* b2  = (const float*)d_in[13];
    const float* g1  = (const float*)d_in[14];
    const float* be1 = (const float*)d_in[15];
    const float* g2  = (const float*)d_in[16];
    const float* be2 = (const float*)d_in[17];
    float* out = (float*)d_out;

    float *q, *kb, *vb, *attn, *ffh;
    __nv_bfloat16 *wh, *wl;
    cudaGetSymbolAddress((void**)&q,    g_q);
    cudaGetSymbolAddress((void**)&kb,   g_k);
    cudaGetSymbolAddress((void**)&vb,   g_v);
    cudaGetSymbolAddress((void**)&attn, g_attn);
    cudaGetSymbolAddress((void**)&ffh,  g_ff);
    cudaGetSymbolAddress((void**)&wh,   g_wh);
    cudaGetSymbolAddress((void**)&wl,   g_wl);

    cudaFuncSetAttribute(gemm_tc_kernel,
                         cudaFuncAttributeMaxDynamicSharedMemorySize, GEMM_SMEM_BYTES);

    dim3 blk(256);
    dim3 pw(32, 8);

    // Weight prep: transpose + bf16 hi/lo split
    prep_w_kernel<<<dim3(DD / 32, DD / 32), pw>>>(Wq, wh + WQ_OFF, wl + WQ_OFF, DD, DD);
    prep_w_kernel<<<dim3(DD / 32, DD / 32), pw>>>(Wk, wh + WK_OFF, wl + WK_OFF, DD, DD);
    prep_w_kernel<<<dim3(DD / 32, DD / 32), pw>>>(Wv, wh + WV_OFF, wl + WV_OFF, DD, DD);
    prep_w_kernel<<<dim3(DD / 32, DD / 32), pw>>>(Wo, wh + WO_OFF, wl + WO_OFF, DD, DD);
    prep_w_kernel<<<dim3(FF / 32, DD / 32), pw>>>(W1, wh + W1_OFF, wl + W1_OFF, DD, FF);
    prep_w_kernel<<<dim3(DD / 32, FF / 32), pw>>>(W2, wh + W2_OFF, wl + W2_OFF, FF, DD);

    dim3 gD(DD / 128, MM / 128);   // (8, 64)
    dim3 gF(FF / 128, MM / 128);   // (32, 64)

    // QKV projections -> stage -> scatter to head layout
    gemm_tc_kernel<<<gD, blk, GEMM_SMEM_BYTES>>>(x, wh + WQ_OFF, wl + WQ_OFF, attn, MM, DD, DD);
    scatter_bias_kernel<<<MM, blk>>>(attn, bq, q);
    gemm_tc_kernel<<<gD, blk, GEMM_SMEM_BYTES>>>(x, wh + WK_OFF, wl + WK_OFF, attn, MM, DD, DD);
    scatter_bias_kernel<<<MM, blk>>>(attn, bk, kb);
    gemm_tc_kernel<<<gD, blk, GEMM_SMEM_BYTES>>>(x, wh + WV_OFF, wl + WV_OFF, attn, MM, DD, DD);
    scatter_bias_kernel<<<MM, blk>>>(attn, bv, vb);

    // Flash attention -> token layout [M, D]
    flash_kernel<<<dim3(SS / 64, BB * HH), blk>>>(q, kb, vb, msk, attn);

    // Output projection; h = LN(x + o + bo) -> g_q
    gemm_tc_kernel<<<gD, blk, GEMM_SMEM_BYTES>>>(attn, wh + WO_OFF, wl + WO_OFF, ffh, MM, DD, DD);
    add_ln_kernel<<<MM, blk>>>(x, ffh, bo, g1, be1, q);

    // FFN
    gemm_tc_kernel<<<gF, blk, GEMM_SMEM_BYTES>>>(q, wh + W1_OFF, wl + W1_OFF, ffh, MM, FF, DD);
    bias_relu_kernel<<<(size_t)MM * FF / 1024, blk>>>(ffh, b1);
    gemm_tc_kernel<<<gD, blk, GEMM_SMEM_BYTES>>>(ffh, wh + W2_OFF, wl + W2_OFF, kb, MM, DD, FF);

    // out = LN(h + ffn + b2)
    add_ln_kernel<<<MM, blk>>>(q, kb, b2, g2, be2, out);
}

// round 6
// speedup vs baseline: 1.9564x; 1.5601x over previous
#include <cuda_runtime.h>
#include <cuda_bf16.h>
#include <math.h>
#include <stdint.h>

// Problem constants
constexpr int BB = 4;
constexpr int SS = 2048;
constexpr int DD = 1024;
constexpr int HH = 16;
constexpr int HD = 64;
constexpr int FF = 4096;
constexpr int MM = BB * SS;  // 8192 tokens

// tcgen05 available only in the arch-specific (sm_103a/sm_100a) device pass.
#if defined(__CUDA_ARCH_FEAT_SM103_ALL) || defined(__CUDA_ARCH_FEAT_SM100_ALL)
#define HAS_TCGEN05 1
#else
#define HAS_TCGEN05 0
#endif

// Scratch (device globals; no allocation allowed)
__device__ float g_q[(size_t)MM * DD];
__device__ float g_k[(size_t)MM * DD];
__device__ float g_v[(size_t)MM * DD];
__device__ float g_attn[(size_t)MM * DD];
__device__ float g_ff[(size_t)MM * FF];

// Weight scratch: transposed [N][K] bf16 hi/lo splits
constexpr size_t WQ_OFF = 0;
constexpr size_t WK_OFF = 1048576;
constexpr size_t WV_OFF = 2097152;
constexpr size_t WO_OFF = 3145728;
constexpr size_t W1_OFF = 4194304;
constexpr size_t W2_OFF = 8388608;
constexpr size_t WTOT   = 12582912;
__device__ __nv_bfloat16 g_wh[WTOT];
__device__ __nv_bfloat16 g_wl[WTOT];

// ---------------------------------------------------------------------------
// PTX helpers
// ---------------------------------------------------------------------------
__device__ __forceinline__ uint32_t smem_u32(const void* p) {
    uint32_t a;
    asm("{ .reg .u64 t; cvta.to.shared.u64 t, %1; cvt.u32.u64 %0, t; }"
        : "=r"(a) : "l"(p));
    return a;
}

#if HAS_TCGEN05
__device__ __forceinline__ uint32_t elect_one_pred() {
    uint32_t pred;
    asm volatile(
        "{\n\t.reg .pred p;\n\t"
        "elect.sync _|p, 0xFFFFFFFF;\n\t"
        "selp.b32 %0, 1, 0, p;\n\t}"
        : "=r"(pred));
    return pred;
}
#define TCGEN05_ALLOC(smem_addr, nCols) \
    asm volatile("tcgen05.alloc.cta_group::1.sync.aligned.shared::cta.b32 [%0], %1;" \
        :: "r"((uint32_t)(smem_addr)), "r"((uint32_t)(nCols)) : "memory")
#define TCGEN05_DEALLOC(tmem_addr, nCols) \
    asm volatile("tcgen05.dealloc.cta_group::1.sync.aligned.b32 %0, %1;" \
        :: "r"(tmem_addr), "r"((uint32_t)(nCols)))
#define TCGEN05_COMMIT(mbar) \
    asm volatile("tcgen05.commit.cta_group::1.mbarrier::arrive::one.shared::cluster.b64 [%0];" \
        :: "r"((uint32_t)(mbar)) : "memory")
#define TCGEN05_WAIT_LD()  asm volatile("tcgen05.wait::ld.sync.aligned;" ::: "memory")
#define TCGEN05_FENCE_BEFORE() asm volatile("tcgen05.fence::before_thread_sync;" ::: "memory")
#define TCGEN05_FENCE_AFTER()  asm volatile("tcgen05.fence::after_thread_sync;" ::: "memory")
#define FENCE_ASYNC_SHARED() asm volatile("fence.proxy.async.shared::cta;" ::: "memory")
#define MBARRIER_INIT(mbar, cnt) \
    asm volatile("mbarrier.init.shared.b64 [%0], %1;" \
        :: "r"((uint32_t)(mbar)), "r"((uint32_t)(cnt)) : "memory")
#define MBARRIER_INVAL(mbar) \
    asm volatile("mbarrier.inval.shared.b64 [%0];" :: "r"((uint32_t)(mbar)) : "memory")
#define MBARRIER_WAIT_PARITY(mbar, parity) do {                                    \
    uint32_t _mb = (uint32_t)(mbar);                                               \
    uint32_t _pa = (uint32_t)(parity);                                             \
    uint32_t _done;                                                                \
    asm volatile(                                                                  \
        "{\n\t.reg .pred p;\n\t"                                                   \
        "mbarrier.try_wait.parity.acquire.cta.shared::cta.b64 p, [%1], %2;\n\t"    \
        "selp.b32 %0, 1, 0, p;\n\t}"                                               \
        : "=r"(_done) : "r"(_mb), "r"(_pa) : "memory");                            \
    if (!_done) {                                                                  \
        asm volatile(                                                              \
            "{\n\t.reg .pred P1;\n\t"                                              \
            "WL_%=:\n\t"                                                           \
            "mbarrier.try_wait.parity.acquire.cta.shared::cta.b64 P1, [%0], %1, 0x989680;\n\t" \
            "@P1 bra.uni WD_%=;\n\t"                                               \
            "bra.uni WL_%=;\n\t"                                                   \
            "WD_%=:\n\t}"                                                          \
            :: "r"(_mb), "r"(_pa) : "memory");                                     \
    }                                                                              \
} while (0)
#define TCGEN05_LD_X32(r, addr) \
    asm volatile( \
        "tcgen05.ld.sync.aligned.32x32b.x32.b32 " \
        "{%0, %1, %2, %3, %4, %5, %6, %7, " \
        " %8, %9, %10, %11, %12, %13, %14, %15, " \
        " %16, %17, %18, %19, %20, %21, %22, %23, " \
        " %24, %25, %26, %27, %28, %29, %30, %31}, [%32];" \
        : "=r"((r)[0]),  "=r"((r)[1]),  "=r"((r)[2]),  "=r"((r)[3]), \
          "=r"((r)[4]),  "=r"((r)[5]),  "=r"((r)[6]),  "=r"((r)[7]), \
          "=r"((r)[8]),  "=r"((r)[9]),  "=r"((r)[10]), "=r"((r)[11]), \
          "=r"((r)[12]), "=r"((r)[13]), "=r"((r)[14]), "=r"((r)[15]), \
          "=r"((r)[16]), "=r"((r)[17]), "=r"((r)[18]), "=r"((r)[19]), \
          "=r"((r)[20]), "=r"((r)[21]), "=r"((r)[22]), "=r"((r)[23]), \
          "=r"((r)[24]), "=r"((r)[25]), "=r"((r)[26]), "=r"((r)[27]), \
          "=r"((r)[28]), "=r"((r)[29]), "=r"((r)[30]), "=r"((r)[31]) \
        : "r"(addr))

// SW128 smem descriptor: layout=SW128, version=1 (Blackwell), SBO=64, LBO=1
__device__ __forceinline__ uint64_t make_desc_sw128(uint32_t addr) {
    constexpr uint64_t BASE =
        (uint64_t(2) << 61) | (uint64_t(1) << 46) | (uint64_t(64) << 32) | (uint64_t(1) << 16);
    return BASE | ((uint64_t)(addr >> 4) & 0x3FFF);
}
// cg1 SS bf16 MMA
__device__ __forceinline__ void mma_bf16_ss(uint32_t d, uint64_t ad, uint64_t bd,
                                            uint32_t idesc, bool acc) {
    uint32_t en = acc ? 1u : 0u;
    asm volatile(
        "{\n\t.reg .pred p;\n\t"
        "setp.ne.u32 p, %5, 0;\n\t"
        "tcgen05.mma.cta_group::1.kind::f16 [%0], %1, %2, %3, {%4, %4, %4, %4}, p;\n\t}"
        :: "r"(d), "l"(ad), "l"(bd), "r"(idesc), "r"(0u), "r"(en) : "memory");
}
#endif  // HAS_TCGEN05

__device__ __forceinline__ uint32_t swz128(uint32_t off) {
    return off ^ ((off >> 3) & 0x70);
}

// idesc: dtype F32, atype/btype BF16, N=128, M=128
constexpr uint32_t GEMM_IDESC =
    (1u << 4) | (1u << 7) | (1u << 10) | ((128 / 8) << 17) | ((128 / 16) << 24);

// ---------------------------------------------------------------------------
// Weight prep: W[K][N] fp32 -> Bh/Bl [N][K] bf16 (hi/lo split), transposed.
// ---------------------------------------------------------------------------
__global__ void prep_w_kernel(const float* __restrict__ W,
                              __nv_bfloat16* __restrict__ Bh,
                              __nv_bfloat16* __restrict__ Bl, int K, int N)
{
    __shared__ float t[32][33];
    const int n0 = blockIdx.x * 32, k0 = blockIdx.y * 32;
#pragma unroll
    for (int i = 0; i < 4; i++)
        t[threadIdx.y + i * 8][threadIdx.x] =
            W[(size_t)(k0 + threadIdx.y + i * 8) * N + n0 + threadIdx.x];
    __syncthreads();
#pragma unroll
    for (int i = 0; i < 4; i++) {
        int n = threadIdx.y + i * 8;
        float v = t[threadIdx.x][n];
        __nv_bfloat16 h = __float2bfloat16(v);
        float lo = v - __bfloat162float(h);
        size_t idx = (size_t)(n0 + n) * K + k0 + threadIdx.x;
        Bh[idx] = h;
        Bl[idx] = __float2bfloat16(lo);
    }
}

// ---------------------------------------------------------------------------
// GEMM: C[M,N] = A[M,K](fp32) @ B^T, B = [N][K] bf16 hi/lo.
// sm_103a pass: tcgen05, 128x128 tile, TMEM accum, double-buffered smem.
// base pass (fallback): classic tiled FFMA SGEMM, correct but slower.
// ---------------------------------------------------------------------------
constexpr int GEMM_SMEM_BYTES = 131072 + 1024;

__global__ __launch_bounds__(256, 1) void gemm_tc_kernel(
    const float* __restrict__ A,
    const __nv_bfloat16* __restrict__ Bh, const __nv_bfloat16* __restrict__ Bl,
    float* __restrict__ C, int M, int N, int K)
{
    extern __shared__ char dsmem[];
    uintptr_t p = ((uintptr_t)dsmem + 1023) & ~(uintptr_t)1023;
    char* buf = (char*)p;

    const int tid = threadIdx.x;
    const int wid = tid >> 5;
    const int lane = tid & 31;
    const int m0 = blockIdx.y << 7;
    const int n0 = blockIdx.x << 7;

#if HAS_TCGEN05
    __shared__ alignas(16) unsigned long long ctrlq[4];
    const uint32_t sbuf = smem_u32(buf);
    const uint32_t ctrl = smem_u32(ctrlq);

    if (wid == 0) TCGEN05_ALLOC(ctrl, 128);
    if (tid == 0) {
        MBARRIER_INIT(ctrl + 8, 1);
        MBARRIER_INIT(ctrl + 16, 1);
        MBARRIER_INIT(ctrl + 24, 1);
    }
    __syncthreads();
    uint32_t tmem;
    asm volatile("ld.shared.b32 %0, [%1];" : "=r"(tmem) : "r"(ctrl));

    const int NC = K >> 6;
    int ph0 = 0, ph1 = 0;

    const float* Ab = A + (size_t)m0 * K;
    const __nv_bfloat16* Bhb = Bh + (size_t)n0 * K;
    const __nv_bfloat16* Blb = Bl + (size_t)n0 * K;

    for (int i = 0; i < NC; i++) {
        const int b = i & 1;
        const uint32_t boff = (uint32_t)b << 16;  // 65536
        const int k0 = i << 6;

        if (i >= 2) {
            if (b == 0) { MBARRIER_WAIT_PARITY(ctrl + 8, ph0); ph0 ^= 1; }
            else        { MBARRIER_WAIT_PARITY(ctrl + 16, ph1); ph1 ^= 1; }
        }

        // A tile: fp32 -> bf16 hi/lo, swizzled SW128 rows of 128B
        float4 af[8];
#pragma unroll
        for (int j = 0; j < 2; j++) {
            int u = tid + j * 256;
            int r = u >> 2;
            int kq = (u & 3) * 16;
            const float* ap = Ab + (size_t)r * K + k0 + kq;
#pragma unroll
            for (int t = 0; t < 4; t++) af[j * 4 + t] = *(const float4*)(ap + t * 4);
        }
        uint4 bhr[4], blr[4];
#pragma unroll
        for (int j = 0; j < 4; j++) {
            int u = tid + j * 256;
            int r = u >> 3;
            int kk = (u & 7) * 8;
            bhr[j] = *(const uint4*)(Bhb + (size_t)r * K + k0 + kk);
            blr[j] = *(const uint4*)(Blb + (size_t)r * K + k0 + kk);
        }
#pragma unroll
        for (int j = 0; j < 2; j++) {
            int u = tid + j * 256;
            int r = u >> 2;
            int kq = (u & 3) * 16;
            uint32_t hi[8], lo[8];
            const float* fv = (const float*)&af[j * 4];
#pragma unroll
            for (int e = 0; e < 8; e++) {
                float x = fv[2 * e], y = fv[2 * e + 1];
                __nv_bfloat16 hx = __float2bfloat16(x), hy = __float2bfloat16(y);
                float lx = x - __bfloat162float(hx);
                float ly = y - __bfloat162float(hy);
                __nv_bfloat162 hp; hp.x = hx; hp.y = hy;
                __nv_bfloat162 lp; lp.x = __float2bfloat16(lx); lp.y = __float2bfloat16(ly);
                hi[e] = *(uint32_t*)&hp;
                lo[e] = *(uint32_t*)&lp;
            }
            uint32_t o0 = (uint32_t)(r * 128 + kq * 2);
            *(uint4*)(buf + boff + swz128(o0))              = make_uint4(hi[0], hi[1], hi[2], hi[3]);
            *(uint4*)(buf + boff + swz128(o0 + 16))         = make_uint4(hi[4], hi[5], hi[6], hi[7]);
            *(uint4*)(buf + boff + 16384 + swz128(o0))      = make_uint4(lo[0], lo[1], lo[2], lo[3]);
            *(uint4*)(buf + boff + 16384 + swz128(o0 + 16)) = make_uint4(lo[4], lo[5], lo[6], lo[7]);
        }
#pragma unroll
        for (int j = 0; j < 4; j++) {
            int u = tid + j * 256;
            int r = u >> 3;
            int kk = (u & 7) * 8;
            uint32_t o = swz128((uint32_t)(r * 128 + kk * 2));
            *(uint4*)(buf + boff + 32768 + o) = bhr[j];
            *(uint4*)(buf + boff + 49152 + o) = blr[j];
        }

        FENCE_ASYNC_SHARED();
        __syncthreads();

        if (wid == 0 && elect_one_pred()) {
            uint64_t dAh = make_desc_sw128(sbuf + boff);
            uint64_t dAl = make_desc_sw128(sbuf + boff + 16384);
            uint64_t dBh = make_desc_sw128(sbuf + boff + 32768);
            uint64_t dBl = make_desc_sw128(sbuf + boff + 49152);
#pragma unroll
            for (int ks = 0; ks < 4; ks++)
                mma_bf16_ss(tmem, dAh + ks * 2, dBh + ks * 2, GEMM_IDESC, !(i == 0 && ks == 0));
#pragma unroll
            for (int ks = 0; ks < 4; ks++)
                mma_bf16_ss(tmem, dAl + ks * 2, dBh + ks * 2, GEMM_IDESC, true);
#pragma unroll
            for (int ks = 0; ks < 4; ks++)
                mma_bf16_ss(tmem, dAh + ks * 2, dBl + ks * 2, GEMM_IDESC, true);
            TCGEN05_COMMIT(ctrl + 8 + (b << 3));
        }
    }

    if (wid == 0 && elect_one_pred()) TCGEN05_COMMIT(ctrl + 24);
    MBARRIER_WAIT_PARITY(ctrl + 24, 0);
    TCGEN05_FENCE_AFTER();

    // epilogue: 8 warps read TMEM (warp%4 = subpartition, warp/4 = col half)
    {
        const int sp = wid & 3;
        const int ch = wid >> 2;
        uint32_t r[64];
        TCGEN05_LD_X32(r, tmem + ch * 64);
        TCGEN05_LD_X32(r + 32, tmem + ch * 64 + 32);
        TCGEN05_WAIT_LD();
        TCGEN05_FENCE_BEFORE();

        const int row = m0 + sp * 32 + lane;
        float* cp = C + (size_t)row * N + n0 + ch * 64;
#pragma unroll
        for (int c = 0; c < 16; c++) {
            float4 v;
            v.x = __uint_as_float(r[4 * c + 0]);
            v.y = __uint_as_float(r[4 * c + 1]);
            v.z = __uint_as_float(r[4 * c + 2]);
            v.w = __uint_as_float(r[4 * c + 3]);
            *(float4*)(cp + 4 * c) = v;
        }
    }

    __syncthreads();
    if (tid == 0) {
        MBARRIER_INVAL(ctrl + 8);
        MBARRIER_INVAL(ctrl + 16);
        MBARRIER_INVAL(ctrl + 24);
    }
    __syncthreads();
    if (wid == 0) TCGEN05_DEALLOC(tmem, 128);

#else  // ---------------- FFMA fallback (base-arch pass) ----------------
    // As[16][132] transposed A tile, Bs[16][132] B tile (k-major), FFMA 8x8.
    float* As = (float*)buf;               // 16*132 floats
    float* Bs = As + 16 * 132;
    const int tx = tid & 15;
    const int ty = tid >> 4;

    float acc[8][8];
#pragma unroll
    for (int i = 0; i < 8; i++)
#pragma unroll
        for (int j = 0; j < 8; j++) acc[i][j] = 0.0f;

    for (int k0 = 0; k0 < K; k0 += 16) {
        {
            int r = tid >> 2, q = (tid & 3) * 4;
#pragma unroll
            for (int i = 0; i < 2; i++) {
                int rr = r + i * 64;
                float4 v = *(const float4*)(A + (size_t)(m0 + rr) * K + k0 + q);
                As[(q + 0) * 132 + rr] = v.x;
                As[(q + 1) * 132 + rr] = v.y;
                As[(q + 2) * 132 + rr] = v.z;
                As[(q + 3) * 132 + rr] = v.w;
            }
            int n = tid >> 1, half = (tid & 1) * 8;
            const __nv_bfloat16* bhp = Bh + (size_t)(n0 + n) * K + k0 + half;
            const __nv_bfloat16* blp = Bl + (size_t)(n0 + n) * K + k0 + half;
#pragma unroll
            for (int e = 0; e < 8; e++)
                Bs[(half + e) * 132 + n] =
                    __bfloat162float(bhp[e]) + __bfloat162float(blp[e]);
        }
        __syncthreads();
#pragma unroll
        for (int k = 0; k < 16; k++) {
            float a[8], bvv[8];
#pragma unroll
            for (int i = 0; i < 8; i++) a[i] = As[k * 132 + ty * 8 + i];
#pragma unroll
            for (int j = 0; j < 8; j++) bvv[j] = Bs[k * 132 + tx * 8 + j];
#pragma unroll
            for (int i = 0; i < 8; i++)
#pragma unroll
                for (int j = 0; j < 8; j++)
                    acc[i][j] = fmaf(a[i], bvv[j], acc[i][j]);
        }
        __syncthreads();
    }
#pragma unroll
    for (int i = 0; i < 8; i++) {
        int row = m0 + ty * 8 + i;
#pragma unroll
        for (int jj = 0; jj < 8; jj += 4) {
            float4 r4 = make_float4(acc[i][jj], acc[i][jj + 1], acc[i][jj + 2], acc[i][jj + 3]);
            *(float4*)(C + (size_t)row * N + n0 + tx * 8 + jj) = r4;
        }
    }
#endif
}

// ---------------------------------------------------------------------------
// QKV epilogue: add bias, scatter token layout [M,D] -> heads [B,H,S,hd]
// ---------------------------------------------------------------------------
__global__ __launch_bounds__(256) void scatter_bias_kernel(
    const float* __restrict__ in, const float* __restrict__ bias,
    float* __restrict__ out)
{
    const int row = blockIdx.x;
    const int col = threadIdx.x * 4;
    float4 v = *(const float4*)(in + (size_t)row * DD + col);
    float4 bv = *(const float4*)(bias + col);
    v.x += bv.x; v.y += bv.y; v.z += bv.z; v.w += bv.w;
    int b_ = row >> 11;
    int s_ = row & (SS - 1);
    int h_ = col >> 6;
    int dh = col & (HD - 1);
    *(float4*)(out + (((size_t)b_ * HH + h_) * SS + s_) * HD + dh) = v;
}

// FFN1 epilogue: in-place bias + ReLU over [M, FF]
__global__ __launch_bounds__(256) void bias_relu_kernel(
    float* __restrict__ io, const float* __restrict__ bias)
{
    size_t idx = ((size_t)blockIdx.x * 256 + threadIdx.x) * 4;
    int col = (int)(idx & (FF - 1));
    float4 v = *(const float4*)(io + idx);
    float4 bv = *(const float4*)(bias + col);
    v.x = fmaxf(v.x + bv.x, 0.0f);
    v.y = fmaxf(v.y + bv.y, 0.0f);
    v.z = fmaxf(v.z + bv.z, 0.0f);
    v.w = fmaxf(v.w + bv.w, 0.0f);
    *(float4*)(io + idx) = v;
}

// ---------------------------------------------------------------------------
// Flash attention (fp32, unchanged — verified in rounds 1-2)
// ---------------------------------------------------------------------------
__global__ __launch_bounds__(256) void flash_kernel(
    const float* __restrict__ q, const float* __restrict__ k,
    const float* __restrict__ v, const int* __restrict__ mask,
    float* __restrict__ out)
{
    __shared__ float Qs[64][64];
    __shared__ float Ks[32][68];
    __shared__ float Vs[32][64];
    __shared__ float Ssm[64][32];

    const int tid = threadIdx.x;
    const int tx = tid & 15;
    const int ty = tid >> 4;
    const int bh = blockIdx.y;
    const int b_ = bh >> 4;
    const int h_ = bh & (HH - 1);
    const int q0 = blockIdx.x * 64;

    const float* qb = q + ((size_t)bh * SS + q0) * HD;
#pragma unroll
    for (int i = 0; i < 4; i++) {
        int f = tid + i * 256;
        ((float4*)Qs)[f] = ((const float4*)qb)[f];
    }

    float m_i[4], l_i[4];
    float4 o_acc[4];
#pragma unroll
    for (int i = 0; i < 4; i++) {
        m_i[i] = -1e30f;
        l_i[i] = 0.0f;
        o_acc[i] = make_float4(0.f, 0.f, 0.f, 0.f);
    }

    for (int kc = 0; kc < SS / 32; kc++) {
        const float* kb = k + ((size_t)bh * SS + kc * 32) * HD;
        const float* vb = v + ((size_t)bh * SS + kc * 32) * HD;
#pragma unroll
        for (int i = 0; i < 2; i++) {
            int f = tid + i * 256;
            int r = f >> 4, c4 = f & 15;
            *(float4*)(&Ks[r][c4 * 4]) = ((const float4*)kb)[f];
            ((float4*)Vs)[f] = ((const float4*)vb)[f];
        }
        __syncthreads();

        float sc0[4] = {0.f, 0.f, 0.f, 0.f};
        float sc1[4] = {0.f, 0.f, 0.f, 0.f};
#pragma unroll
        for (int d4 = 0; d4 < 16; d4++) {
            float4 ka = *(const float4*)(&Ks[tx][d4 * 4]);
            float4 kbv = *(const float4*)(&Ks[tx + 16][d4 * 4]);
#pragma unroll
            for (int i = 0; i < 4; i++) {
                float4 qv = *(const float4*)(&Qs[ty * 4 + i][d4 * 4]);
                sc0[i] = fmaf(qv.x, ka.x, sc0[i]);
                sc0[i] = fmaf(qv.y, ka.y, sc0[i]);
                sc0[i] = fmaf(qv.z, ka.z, sc0[i]);
                sc0[i] = fmaf(qv.w, ka.w, sc0[i]);
                sc1[i] = fmaf(qv.x, kbv.x, sc1[i]);
                sc1[i] = fmaf(qv.y, kbv.y, sc1[i]);
                sc1[i] = fmaf(qv.z, kbv.z, sc1[i]);
                sc1[i] = fmaf(qv.w, kbv.w, sc1[i]);
            }
        }

        const int mk0 = mask[b_ * SS + kc * 32 + tx];
        const int mk1 = mask[b_ * SS + kc * 32 + tx + 16];

#pragma unroll
        for (int i = 0; i < 4; i++) {
            float s0 = sc0[i] * 0.125f;
            float s1 = sc1[i] * 0.125f;
            if (mk0 == 0) s0 = -1e9f;
            if (mk1 == 0) s1 = -1e9f;
            float mx = fmaxf(s0, s1);
#pragma unroll
            for (int off = 8; off >= 1; off >>= 1)
                mx = fmaxf(mx, __shfl_xor_sync(0xffffffffu, mx, off, 16));
            float mnew = fmaxf(m_i[i], mx);
            float corr = __expf(m_i[i] - mnew);
            float p0 = __expf(s0 - mnew);
            float p1 = __expf(s1 - mnew);
            Ssm[ty * 4 + i][tx] = p0;
            Ssm[ty * 4 + i][tx + 16] = p1;
            float ps = p0 + p1;
#pragma unroll
            for (int off = 8; off >= 1; off >>= 1)
                ps += __shfl_xor_sync(0xffffffffu, ps, off, 16);
            l_i[i] = l_i[i] * corr + ps;
            m_i[i] = mnew;
            o_acc[i].x *= corr;
            o_acc[i].y *= corr;
            o_acc[i].z *= corr;
            o_acc[i].w *= corr;
        }
        __syncthreads();

#pragma unroll
        for (int c4 = 0; c4 < 8; c4++) {
            float4 v0 = *(const float4*)(&Vs[c4 * 4 + 0][tx * 4]);
            float4 v1 = *(const float4*)(&Vs[c4 * 4 + 1][tx * 4]);
            float4 v2 = *(const float4*)(&Vs[c4 * 4 + 2][tx * 4]);
            float4 v3 = *(const float4*)(&Vs[c4 * 4 + 3][tx * 4]);
#pragma unroll
            for (int i = 0; i < 4; i++) {
                float4 pp = *(const float4*)(&Ssm[ty * 4 + i][c4 * 4]);
                o_acc[i].x = fmaf(pp.x, v0.x, o_acc[i].x);
                o_acc[i].y = fmaf(pp.x, v0.y, o_acc[i].y);
                o_acc[i].z = fmaf(pp.x, v0.z, o_acc[i].z);
                o_acc[i].w = fmaf(pp.x, v0.w, o_acc[i].w);
                o_acc[i].x = fmaf(pp.y, v1.x, o_acc[i].x);
                o_acc[i].y = fmaf(pp.y, v1.y, o_acc[i].y);
                o_acc[i].z = fmaf(pp.y, v1.z, o_acc[i].z);
                o_acc[i].w = fmaf(pp.y, v1.w, o_acc[i].w);
                o_acc[i].x = fmaf(pp.z, v2.x, o_acc[i].x);
                o_acc[i].y = fmaf(pp.z, v2.y, o_acc[i].y);
                o_acc[i].z = fmaf(pp.z, v2.z, o_acc[i].z);
                o_acc[i].w = fmaf(pp.z, v2.w, o_acc[i].w);
                o_acc[i].x = fmaf(pp.w, v3.x, o_acc[i].x);
                o_acc[i].y = fmaf(pp.w, v3.y, o_acc[i].y);
                o_acc[i].z = fmaf(pp.w, v3.z, o_acc[i].z);
                o_acc[i].w = fmaf(pp.w, v3.w, o_acc[i].w);
            }
        }
        __syncthreads();
    }

#pragma unroll
    for (int i = 0; i < 4; i++) {
        float inv = 1.0f / l_i[i];
        int row = q0 + ty * 4 + i;
        float4 r4 = make_float4(o_acc[i].x * inv, o_acc[i].y * inv,
                                o_acc[i].z * inv, o_acc[i].w * inv);
        *(float4*)(out + ((size_t)(b_ * SS + row)) * DD + h_ * HD + tx * 4) = r4;
    }
}

// ---------------------------------------------------------------------------
// Fused residual + bias + LayerNorm: out = LN(a + b + bias) * g + be
// ---------------------------------------------------------------------------
__global__ __launch_bounds__(256) void add_ln_kernel(
    const float* __restrict__ a, const float* __restrict__ b,
    const float* __restrict__ bias,
    const float* __restrict__ g, const float* __restrict__ be,
    float* __restrict__ out)
{
    __shared__ float sh[10];
    const int row = blockIdx.x;
    const int tid = threadIdx.x;
    const int wid = tid >> 5, lane = tid & 31;
    const size_t base = (size_t)row * DD + tid * 4;

    float4 av = *(const float4*)(a + base);
    float4 bv = *(const float4*)(b + base);
    float4 cv = *(const float4*)(bias + tid * 4);
    float4 t = make_float4(av.x + bv.x + cv.x, av.y + bv.y + cv.y,
                           av.z + bv.z + cv.z, av.w + bv.w + cv.w);

    float s = t.x + t.y + t.z + t.w;
#pragma unroll
    for (int off = 16; off >= 1; off >>= 1)
        s += __shfl_xor_sync(0xffffffffu, s, off);
    if (lane == 0) sh[wid] = s;
    __syncthreads();
    if (tid == 0) {
        float t2 = 0.f;
#pragma unroll
        for (int w = 0; w < 8; w++) t2 += sh[w];
        sh[8] = t2 * (1.0f / 1024.0f);
    }
    __syncthreads();
    float mu = sh[8];

    float dx = t.x - mu, dy = t.y - mu, dz = t.z - mu, dw = t.w - mu;
    float sq = dx * dx + dy * dy + dz * dz + dw * dw;
#pragma unroll
    for (int off = 16; off >= 1; off >>= 1)
        sq += __shfl_xor_sync(0xffffffffu, sq, off);
    if (lane == 0) sh[wid] = sq;
    __syncthreads();
    if (tid == 0) {
        float t2 = 0.f;
#pragma unroll
        for (int w = 0; w < 8; w++) t2 += sh[w];
        sh[9] = rsqrtf(t2 * (1.0f / 1024.0f) + 1e-5f);
    }
    __syncthreads();
    float inv = sh[9];

    float4 gv = *(const float4*)(g + tid * 4);
    float4 bev = *(const float4*)(be + tid * 4);
    float4 r = make_float4(dx * inv * gv.x + bev.x,
                           dy * inv * gv.y + bev.y,
                           dz * inv * gv.z + bev.z,
                           dw * inv * gv.w + bev.w);
    *(float4*)(out + base) = r;
}

// ---------------------------------------------------------------------------
extern "C" void kernel_launch(void* const* d_in, const int* in_sizes, int n_in,
                              void* d_out, int out_size)
{
    const float* x   = (const float*)d_in[0];
    const int*   msk = (const int*)d_in[1];
    const float* Wq  = (const float*)d_in[2];
    const float* bq  = (const float*)d_in[3];
    const float* Wk  = (const float*)d_in[4];
    const float* bk  = (const float*)d_in[5];
    const float* Wv  = (const float*)d_in[6];
    const float* bv  = (const float*)d_in[7];
    const float* Wo  = (const float*)d_in[8];
    const float* bo  = (const float*)d_in[9];
    const float* W1  = (const float*)d_in[10];
    const float* b1  = (const float*)d_in[11];
    const float* W2  = (const float*)d_in[12];
    const float* b2  = (const float*)d_in[13];
    const float* g1  = (const float*)d_in[14];
    const float* be1 = (const float*)d_in[15];
    const float* g2  = (const float*)d_in[16];
    const float* be2 = (const float*)d_in[17];
    float* out = (float*)d_out;

    float *q, *kb, *vb, *attn, *ffh;
    __nv_bfloat16 *wh, *wl;
    cudaGetSymbolAddress((void**)&q,    g_q);
    cudaGetSymbolAddress((void**)&kb,   g_k);
    cudaGetSymbolAddress((void**)&vb,   g_v);
    cudaGetSymbolAddress((void**)&attn, g_attn);
    cudaGetSymbolAddress((void**)&ffh,  g_ff);
    cudaGetSymbolAddress((void**)&wh,   g_wh);
    cudaGetSymbolAddress((void**)&wl,   g_wl);

    cudaFuncSetAttribute(gemm_tc_kernel,
                         cudaFuncAttributeMaxDynamicSharedMemorySize, GEMM_SMEM_BYTES);

    dim3 blk(256);
    dim3 pw(32, 8);

    // Weight prep: transpose + bf16 hi/lo split
    prep_w_kernel<<<dim3(DD / 32, DD / 32), pw>>>(Wq, wh + WQ_OFF, wl + WQ_OFF, DD, DD);
    prep_w_kernel<<<dim3(DD / 32, DD / 32), pw>>>(Wk, wh + WK_OFF, wl + WK_OFF, DD, DD);
    prep_w_kernel<<<dim3(DD / 32, DD / 32), pw>>>(Wv, wh + WV_OFF, wl + WV_OFF, DD, DD);
    prep_w_kernel<<<dim3(DD / 32, DD / 32), pw>>>(Wo, wh + WO_OFF, wl + WO_OFF, DD, DD);
    prep_w_kernel<<<dim3(FF / 32, DD / 32), pw>>>(W1, wh + W1_OFF, wl + W1_OFF, DD, FF);
    prep_w_kernel<<<dim3(DD / 32, FF / 32), pw>>>(W2, wh + W2_OFF, wl + W2_OFF, FF, DD);

    dim3 gD(DD / 128, MM / 128);   // (8, 64)
    dim3 gF(FF / 128, MM / 128);   // (32, 64)

    // QKV projections -> stage -> scatter to head layout
    gemm_tc_kernel<<<gD, blk, GEMM_SMEM_BYTES>>>(x, wh + WQ_OFF, wl + WQ_OFF, attn, MM, DD, DD);
    scatter_bias_kernel<<<MM, blk>>>(attn, bq, q);
    gemm_tc_kernel<<<gD, blk, GEMM_SMEM_BYTES>>>(x, wh + WK_OFF, wl + WK_OFF, attn, MM, DD, DD);
    scatter_bias_kernel<<<MM, blk>>>(attn, bk, kb);
    gemm_tc_kernel<<<gD, blk, GEMM_SMEM_BYTES>>>(x, wh + WV_OFF, wl + WV_OFF, attn, MM, DD, DD);
    scatter_bias_kernel<<<MM, blk>>>(attn, bv, vb);

    // Flash attention -> token layout [M, D]
    flash_kernel<<<dim3(SS / 64, BB * HH), blk>>>(q, kb, vb, msk, attn);

    // Output projection; h = LN(x + o + bo) -> g_q
    gemm_tc_kernel<<<gD, blk, GEMM_SMEM_BYTES>>>(attn, wh + WO_OFF, wl + WO_OFF, ffh, MM, DD, DD);
    add_ln_kernel<<<MM, blk>>>(x, ffh, bo, g1, be1, q);

    // FFN
    gemm_tc_kernel<<<gF, blk, GEMM_SMEM_BYTES>>>(q, wh + W1_OFF, wl + W1_OFF, ffh, MM, FF, DD);
    bias_relu_kernel<<<(size_t)MM * FF / 1024, blk>>>(ffh, b1);
    gemm_tc_kernel<<<gD, blk, GEMM_SMEM_BYTES>>>(ffh, wh + W2_OFF, wl + W2_OFF, kb, MM, DD, FF);

    // out = LN(h + ffn + b2)
    add_ln_kernel<<<MM, blk>>>(q, kb, b2, g2, be2, out);
}

// round 8
// speedup vs baseline: 3.4019x; 1.7389x over previous
#include <cuda_runtime.h>
#include <cuda_bf16.h>
#include <math.h>
#include <stdint.h>

constexpr int BB = 4;
constexpr int SS = 2048;
constexpr int DD = 1024;
constexpr int HH = 16;
constexpr int HD = 64;
constexpr int FF = 4096;
constexpr int MM = BB * SS;

#if defined(__CUDA_ARCH_FEAT_SM103_ALL) || defined(__CUDA_ARCH_FEAT_SM100_ALL)
#define HAS_TCGEN05 1
#else
#define HAS_TCGEN05 0
#endif

// scratch
__device__ float g_q[(size_t)MM * DD];
__device__ float g_k[(size_t)MM * DD];
__device__ float g_attn[(size_t)MM * DD];
__device__ float g_ff[(size_t)MM * FF];
__device__ __nv_bfloat16 g_qb[(size_t)MM * DD];
__device__ __nv_bfloat16 g_kb[(size_t)MM * DD];
__device__ __nv_bfloat16 g_vb[(size_t)MM * DD];

constexpr size_t WQ_OFF = 0;
constexpr size_t WK_OFF = 1048576;
constexpr size_t WV_OFF = 2097152;
constexpr size_t WO_OFF = 3145728;
constexpr size_t W1_OFF = 4194304;
constexpr size_t W2_OFF = 8388608;
constexpr size_t WTOT   = 12582912;
__device__ __nv_bfloat16 g_wh[WTOT];
__device__ __nv_bfloat16 g_wl[WTOT];

__device__ __forceinline__ uint32_t smem_u32(const void* p) {
    uint32_t a;
    asm("{ .reg .u64 t; cvta.to.shared.u64 t, %1; cvt.u32.u64 %0, t; }" : "=r"(a) : "l"(p));
    return a;
}
__device__ __forceinline__ uint32_t swz128(uint32_t off) { return off ^ ((off >> 3) & 0x70); }
__device__ __forceinline__ uint32_t pack_bf2(__nv_bfloat16 a, __nv_bfloat16 b) {
    __nv_bfloat162 t; t.x = a; t.y = b; return *(uint32_t*)&t;
}

#if HAS_TCGEN05
__device__ __forceinline__ uint32_t elect_one_pred() {
    uint32_t pred;
    asm volatile("{\n\t.reg .pred p;\n\telect.sync _|p, 0xFFFFFFFF;\n\tselp.b32 %0, 1, 0, p;\n\t}" : "=r"(pred));
    return pred;
}
#define TCGEN05_ALLOC(smem_addr, nCols) \
    asm volatile("tcgen05.alloc.cta_group::1.sync.aligned.shared::cta.b32 [%0], %1;" \
        :: "r"((uint32_t)(smem_addr)), "r"((uint32_t)(nCols)) : "memory")
#define TCGEN05_DEALLOC(tmem_addr, nCols) \
    asm volatile("tcgen05.dealloc.cta_group::1.sync.aligned.b32 %0, %1;" \
        :: "r"(tmem_addr), "r"((uint32_t)(nCols)))
#define TCGEN05_COMMIT(mbar) \
    asm volatile("tcgen05.commit.cta_group::1.mbarrier::arrive::one.shared::cluster.b64 [%0];" \
        :: "r"((uint32_t)(mbar)) : "memory")
#define TCGEN05_WAIT_LD()  asm volatile("tcgen05.wait::ld.sync.aligned;" ::: "memory")
#define TCGEN05_FENCE_BEFORE() asm volatile("tcgen05.fence::before_thread_sync;" ::: "memory")
#define TCGEN05_FENCE_AFTER()  asm volatile("tcgen05.fence::after_thread_sync;" ::: "memory")
#define FENCE_ASYNC_SHARED() asm volatile("fence.proxy.async.shared::cta;" ::: "memory")
#define MBARRIER_INIT(mbar, cnt) \
    asm volatile("mbarrier.init.shared.b64 [%0], %1;" :: "r"((uint32_t)(mbar)), "r"((uint32_t)(cnt)) : "memory")
#define MBARRIER_INVAL(mbar) \
    asm volatile("mbarrier.inval.shared.b64 [%0];" :: "r"((uint32_t)(mbar)) : "memory")
#define MBARRIER_WAIT_PARITY(mbar, parity) do {                                    \
    uint32_t _mb = (uint32_t)(mbar);                                               \
    uint32_t _pa = (uint32_t)(parity);                                             \
    uint32_t _done;                                                                \
    asm volatile(                                                                  \
        "{\n\t.reg .pred p;\n\t"                                                   \
        "mbarrier.try_wait.parity.acquire.cta.shared::cta.b64 p, [%1], %2;\n\t"    \
        "selp.b32 %0, 1, 0, p;\n\t}"                                               \
        : "=r"(_done) : "r"(_mb), "r"(_pa) : "memory");                            \
    if (!_done) {                                                                  \
        asm volatile(                                                              \
            "{\n\t.reg .pred P1;\n\t"                                              \
            "WL_%=:\n\t"                                                           \
            "mbarrier.try_wait.parity.acquire.cta.shared::cta.b64 P1, [%0], %1, 0x989680;\n\t" \
            "@P1 bra.uni WD_%=;\n\t"                                               \
            "bra.uni WL_%=;\n\t"                                                   \
            "WD_%=:\n\t}"                                                          \
            :: "r"(_mb), "r"(_pa) : "memory");                                     \
    }                                                                              \
} while (0)
#define TCGEN05_LD_X32(r, addr) \
    asm volatile( \
        "tcgen05.ld.sync.aligned.32x32b.x32.b32 " \
        "{%0, %1, %2, %3, %4, %5, %6, %7, " \
        " %8, %9, %10, %11, %12, %13, %14, %15, " \
        " %16, %17, %18, %19, %20, %21, %22, %23, " \
        " %24, %25, %26, %27, %28, %29, %30, %31}, [%32];" \
        : "=r"((r)[0]),  "=r"((r)[1]),  "=r"((r)[2]),  "=r"((r)[3]), \
          "=r"((r)[4]),  "=r"((r)[5]),  "=r"((r)[6]),  "=r"((r)[7]), \
          "=r"((r)[8]),  "=r"((r)[9]),  "=r"((r)[10]), "=r"((r)[11]), \
          "=r"((r)[12]), "=r"((r)[13]), "=r"((r)[14]), "=r"((r)[15]), \
          "=r"((r)[16]), "=r"((r)[17]), "=r"((r)[18]), "=r"((r)[19]), \
          "=r"((r)[20]), "=r"((r)[21]), "=r"((r)[22]), "=r"((r)[23]), \
          "=r"((r)[24]), "=r"((r)[25]), "=r"((r)[26]), "=r"((r)[27]), \
          "=r"((r)[28]), "=r"((r)[29]), "=r"((r)[30]), "=r"((r)[31]) \
        : "r"(addr))

__device__ __forceinline__ uint64_t make_desc_sw128(uint32_t addr) {
    constexpr uint64_t BASE =
        (uint64_t(2) << 61) | (uint64_t(1) << 46) | (uint64_t(64) << 32) | (uint64_t(1) << 16);
    return BASE | ((uint64_t)(addr >> 4) & 0x3FFF);
}
__device__ __forceinline__ void mma_bf16_ss(uint32_t d, uint64_t ad, uint64_t bd,
                                            uint32_t idesc, bool acc) {
    uint32_t en = acc ? 1u : 0u;
    asm volatile(
        "{\n\t.reg .pred p;\n\t"
        "setp.ne.u32 p, %5, 0;\n\t"
        "tcgen05.mma.cta_group::1.kind::f16 [%0], %1, %2, %3, {%4, %4, %4, %4}, p;\n\t}"
        :: "r"(d), "l"(ad), "l"(bd), "r"(idesc), "r"(0u), "r"(en) : "memory");
}
#endif

constexpr uint32_t GEMM_IDESC =
    (1u << 4) | (1u << 7) | (1u << 10) | ((128 / 8) << 17) | ((128 / 16) << 24);
constexpr uint32_t IDESC_N64 =
    (1u << 4) | (1u << 7) | (1u << 10) | ((64 / 8) << 17) | ((128 / 16) << 24);

// ---------------- weight prep (unchanged) ----------------
__global__ void prep_w_kernel(const float* __restrict__ W,
                              __nv_bfloat16* __restrict__ Bh,
                              __nv_bfloat16* __restrict__ Bl, int K, int N)
{
    __shared__ float t[32][33];
    const int n0 = blockIdx.x * 32, k0 = blockIdx.y * 32;
#pragma unroll
    for (int i = 0; i < 4; i++)
        t[threadIdx.y + i * 8][threadIdx.x] =
            W[(size_t)(k0 + threadIdx.y + i * 8) * N + n0 + threadIdx.x];
    __syncthreads();
#pragma unroll
    for (int i = 0; i < 4; i++) {
        int n = threadIdx.y + i * 8;
        float v = t[threadIdx.x][n];
        __nv_bfloat16 h = __float2bfloat16(v);
        size_t idx = (size_t)(n0 + n) * K + k0 + threadIdx.x;
        Bh[idx] = h;
        Bl[idx] = __float2bfloat16(v - __bfloat162float(h));
    }
}

// ---------------- tcgen05 GEMM (unchanged, proven) ----------------
constexpr int GEMM_SMEM_BYTES = 131072 + 1024;

__global__ __launch_bounds__(256, 1) void gemm_tc_kernel(
    const float* __restrict__ A,
    const __nv_bfloat16* __restrict__ Bh, const __nv_bfloat16* __restrict__ Bl,
    float* __restrict__ C, int M, int N, int K)
{
    extern __shared__ char dsmem[];
    uintptr_t p = ((uintptr_t)dsmem + 1023) & ~(uintptr_t)1023;
    char* buf = (char*)p;
    const int tid = threadIdx.x;
    const int wid = tid >> 5;
    const int lane = tid & 31;
    const int m0 = blockIdx.y << 7;
    const int n0 = blockIdx.x << 7;

#if HAS_TCGEN05
    __shared__ alignas(16) unsigned long long ctrlq[4];
    const uint32_t sbuf = smem_u32(buf);
    const uint32_t ctrl = smem_u32(ctrlq);

    if (wid == 0) TCGEN05_ALLOC(ctrl, 128);
    if (tid == 0) { MBARRIER_INIT(ctrl + 8, 1); MBARRIER_INIT(ctrl + 16, 1); MBARRIER_INIT(ctrl + 24, 1); }
    __syncthreads();
    uint32_t tmem;
    asm volatile("ld.shared.b32 %0, [%1];" : "=r"(tmem) : "r"(ctrl));

    const int NC = K >> 6;
    int ph0 = 0, ph1 = 0;
    const float* Ab = A + (size_t)m0 * K;
    const __nv_bfloat16* Bhb = Bh + (size_t)n0 * K;
    const __nv_bfloat16* Blb = Bl + (size_t)n0 * K;

    for (int i = 0; i < NC; i++) {
        const int b = i & 1;
        const uint32_t boff = (uint32_t)b << 16;
        const int k0 = i << 6;
        if (i >= 2) {
            if (b == 0) { MBARRIER_WAIT_PARITY(ctrl + 8, ph0); ph0 ^= 1; }
            else        { MBARRIER_WAIT_PARITY(ctrl + 16, ph1); ph1 ^= 1; }
        }
        float4 af[8];
#pragma unroll
        for (int j = 0; j < 2; j++) {
            int u = tid + j * 256;
            int r = u >> 2, kq = (u & 3) * 16;
            const float* ap = Ab + (size_t)r * K + k0 + kq;
#pragma unroll
            for (int t = 0; t < 4; t++) af[j * 4 + t] = *(const float4*)(ap + t * 4);
        }
        uint4 bhr[4], blr[4];
#pragma unroll
        for (int j = 0; j < 4; j++) {
            int u = tid + j * 256;
            int r = u >> 3, kk = (u & 7) * 8;
            bhr[j] = *(const uint4*)(Bhb + (size_t)r * K + k0 + kk);
            blr[j] = *(const uint4*)(Blb + (size_t)r * K + k0 + kk);
        }
#pragma unroll
        for (int j = 0; j < 2; j++) {
            int u = tid + j * 256;
            int r = u >> 2, kq = (u & 3) * 16;
            uint32_t hi[8], lo[8];
            const float* fv = (const float*)&af[j * 4];
#pragma unroll
            for (int e = 0; e < 8; e++) {
                float x = fv[2 * e], y = fv[2 * e + 1];
                __nv_bfloat16 hx = __float2bfloat16(x), hy = __float2bfloat16(y);
                hi[e] = pack_bf2(hx, hy);
                lo[e] = pack_bf2(__float2bfloat16(x - __bfloat162float(hx)),
                                 __float2bfloat16(y - __bfloat162float(hy)));
            }
            uint32_t o0 = (uint32_t)(r * 128 + kq * 2);
            *(uint4*)(buf + boff + swz128(o0))              = make_uint4(hi[0], hi[1], hi[2], hi[3]);
            *(uint4*)(buf + boff + swz128(o0 + 16))         = make_uint4(hi[4], hi[5], hi[6], hi[7]);
            *(uint4*)(buf + boff + 16384 + swz128(o0))      = make_uint4(lo[0], lo[1], lo[2], lo[3]);
            *(uint4*)(buf + boff + 16384 + swz128(o0 + 16)) = make_uint4(lo[4], lo[5], lo[6], lo[7]);
        }
#pragma unroll
        for (int j = 0; j < 4; j++) {
            int u = tid + j * 256;
            int r = u >> 3, kk = (u & 7) * 8;
            uint32_t o = swz128((uint32_t)(r * 128 + kk * 2));
            *(uint4*)(buf + boff + 32768 + o) = bhr[j];
            *(uint4*)(buf + boff + 49152 + o) = blr[j];
        }
        FENCE_ASYNC_SHARED();
        __syncthreads();
        if (wid == 0 && elect_one_pred()) {
            uint64_t dAh = make_desc_sw128(sbuf + boff);
            uint64_t dAl = make_desc_sw128(sbuf + boff + 16384);
            uint64_t dBh = make_desc_sw128(sbuf + boff + 32768);
            uint64_t dBl = make_desc_sw128(sbuf + boff + 49152);
#pragma unroll
            for (int ks = 0; ks < 4; ks++)
                mma_bf16_ss(tmem, dAh + ks * 2, dBh + ks * 2, GEMM_IDESC, !(i == 0 && ks == 0));
#pragma unroll
            for (int ks = 0; ks < 4; ks++)
                mma_bf16_ss(tmem, dAl + ks * 2, dBh + ks * 2, GEMM_IDESC, true);
#pragma unroll
            for (int ks = 0; ks < 4; ks++)
                mma_bf16_ss(tmem, dAh + ks * 2, dBl + ks * 2, GEMM_IDESC, true);
            TCGEN05_COMMIT(ctrl + 8 + (b << 3));
        }
    }
    if (wid == 0 && elect_one_pred()) TCGEN05_COMMIT(ctrl + 24);
    MBARRIER_WAIT_PARITY(ctrl + 24, 0);
    TCGEN05_FENCE_AFTER();
    {
        const int sp = wid & 3;
        const int ch = wid >> 2;
        uint32_t r[64];
        TCGEN05_LD_X32(r, tmem + ch * 64);
        TCGEN05_LD_X32(r + 32, tmem + ch * 64 + 32);
        TCGEN05_WAIT_LD();
        TCGEN05_FENCE_BEFORE();
        const int row = m0 + sp * 32 + lane;
        float* cp = C + (size_t)row * N + n0 + ch * 64;
#pragma unroll
        for (int c = 0; c < 16; c++) {
            float4 v;
            v.x = __uint_as_float(r[4 * c + 0]);
            v.y = __uint_as_float(r[4 * c + 1]);
            v.z = __uint_as_float(r[4 * c + 2]);
            v.w = __uint_as_float(r[4 * c + 3]);
            *(float4*)(cp + 4 * c) = v;
        }
    }
    __syncthreads();
    if (tid == 0) { MBARRIER_INVAL(ctrl + 8); MBARRIER_INVAL(ctrl + 16); MBARRIER_INVAL(ctrl + 24); }
    __syncthreads();
    if (wid == 0) TCGEN05_DEALLOC(tmem, 128);
#else
    float* As = (float*)buf;
    float* Bs = As + 16 * 132;
    const int tx = tid & 15, ty = tid >> 4;
    float acc[8][8];
#pragma unroll
    for (int i = 0; i < 8; i++)
#pragma unroll
        for (int j = 0; j < 8; j++) acc[i][j] = 0.0f;
    for (int k0 = 0; k0 < K; k0 += 16) {
        int r = tid >> 2, qd = (tid & 3) * 4;
#pragma unroll
        for (int i = 0; i < 2; i++) {
            int rr = r + i * 64;
            float4 v = *(const float4*)(A + (size_t)(m0 + rr) * K + k0 + qd);
            As[(qd + 0) * 132 + rr] = v.x; As[(qd + 1) * 132 + rr] = v.y;
            As[(qd + 2) * 132 + rr] = v.z; As[(qd + 3) * 132 + rr] = v.w;
        }
        int n = tid >> 1, half = (tid & 1) * 8;
        const __nv_bfloat16* bhp = Bh + (size_t)(n0 + n) * K + k0 + half;
        const __nv_bfloat16* blp = Bl + (size_t)(n0 + n) * K + k0 + half;
#pragma unroll
        for (int e = 0; e < 8; e++)
            Bs[(half + e) * 132 + n] = __bfloat162float(bhp[e]) + __bfloat162float(blp[e]);
        __syncthreads();
#pragma unroll
        for (int k = 0; k < 16; k++) {
            float a[8], bb[8];
#pragma unroll
            for (int i = 0; i < 8; i++) a[i] = As[k * 132 + ty * 8 + i];
#pragma unroll
            for (int j = 0; j < 8; j++) bb[j] = Bs[k * 132 + tx * 8 + j];
#pragma unroll
            for (int i = 0; i < 8; i++)
#pragma unroll
                for (int j = 0; j < 8; j++) acc[i][j] = fmaf(a[i], bb[j], acc[i][j]);
        }
        __syncthreads();
    }
#pragma unroll
    for (int i = 0; i < 8; i++) {
        int row = m0 + ty * 8 + i;
#pragma unroll
        for (int jj = 0; jj < 8; jj += 4)
            *(float4*)(C + (size_t)row * N + n0 + tx * 8 + jj) =
                make_float4(acc[i][jj], acc[i][jj + 1], acc[i][jj + 2], acc[i][jj + 3]);
    }
#endif
}

// ---------------- QKV epilogue -> bf16 head layout ----------------
__global__ __launch_bounds__(256) void scatter_bias_kernel(
    const float* __restrict__ in, const float* __restrict__ bias,
    __nv_bfloat16* __restrict__ out)
{
    const int row = blockIdx.x;
    const int col = threadIdx.x * 4;
    float4 v = *(const float4*)(in + (size_t)row * DD + col);
    float4 bv = *(const float4*)(bias + col);
    int b_ = row >> 11, s_ = row & (SS - 1);
    int h_ = col >> 6, dh = col & (HD - 1);
    size_t dst = (((size_t)b_ * HH + h_) * SS + s_) * HD + dh;
    *(uint2*)(out + dst) = make_uint2(
        pack_bf2(__float2bfloat16(v.x + bv.x), __float2bfloat16(v.y + bv.y)),
        pack_bf2(__float2bfloat16(v.z + bv.z), __float2bfloat16(v.w + bv.w)));
}

__global__ __launch_bounds__(256) void bias_relu_kernel(
    float* __restrict__ io, const float* __restrict__ bias)
{
    size_t idx = ((size_t)blockIdx.x * 256 + threadIdx.x) * 4;
    int col = (int)(idx & (FF - 1));
    float4 v = *(const float4*)(io + idx);
    float4 bv = *(const float4*)(bias + col);
    v.x = fmaxf(v.x + bv.x, 0.0f); v.y = fmaxf(v.y + bv.y, 0.0f);
    v.z = fmaxf(v.z + bv.z, 0.0f); v.w = fmaxf(v.w + bv.w, 0.0f);
    *(float4*)(io + idx) = v;
}

// ---------------- tcgen05 flash attention ----------------
// CTA: 128 q-rows of one (b,h). grid (SS/128, B*H). 256 threads.
// smem: Q 16K | K 16K | VT 16K | P 32K | ctrl/mask/lsum
constexpr int FL_Q = 0, FL_K = 16384, FL_VT = 32768, FL_P = 49152, FL_CT = 81920;
constexpr int FL_SMEM = FL_CT + 2048 + 1024;

__global__ __launch_bounds__(256, 2) void flash_tc_kernel(
    const __nv_bfloat16* __restrict__ qg, const __nv_bfloat16* __restrict__ kg,
    const __nv_bfloat16* __restrict__ vg, const int* __restrict__ mask,
    float* __restrict__ out)
{
    extern __shared__ char dsmem[];
    uintptr_t pb = ((uintptr_t)dsmem + 1023) & ~(uintptr_t)1023;
    char* buf = (char*)pb;
    const int tid = threadIdx.x;
    const int wid = tid >> 5;
    const int lane = tid & 31;
    const int bh = blockIdx.y;
    const int b_ = bh >> 4;
    const int h_ = bh & (HH - 1);
    const int q0 = blockIdx.x * 128;

#if HAS_TCGEN05
    const int sp = wid & 3;
    const int chf = wid >> 2;
    const uint32_t sbuf = smem_u32(buf);
    const uint32_t ctrl = sbuf + FL_CT;
    int* msk_s = (int*)(buf + FL_CT + 32);
    float* lpart = (float*)(buf + FL_CT + 544);

    if (wid == 0) TCGEN05_ALLOC(ctrl, 256);
    if (tid == 0) { MBARRIER_INIT(ctrl + 8, 1); MBARRIER_INIT(ctrl + 16, 1); }
    __syncthreads();
    uint32_t tmem;
    asm volatile("ld.shared.b32 %0, [%1];" : "=r"(tmem) : "r"(ctrl));

    // Q tile [128 rows][64 bf16], SW128
    {
        int r = tid >> 1, half = (tid & 1) * 32;
        const __nv_bfloat16* qp = qg + ((size_t)(bh * SS + q0 + r)) * HD + half;
#pragma unroll
        for (int j = 0; j < 4; j++)
            *(uint4*)(buf + FL_Q + swz128((uint32_t)(r * 128 + half * 2 + j * 16))) =
                *(const uint4*)(qp + j * 8);
    }

    const uint64_t dQ  = make_desc_sw128(sbuf + FL_Q);
    const uint64_t dK  = make_desc_sw128(sbuf + FL_K);
    const uint64_t dP  = make_desc_sw128(sbuf + FL_P);
    const uint64_t dVT = make_desc_sw128(sbuf + FL_VT);
    const int pOff[8] = {0, 2, 4, 6, 1024, 1026, 1028, 1030};
    const int vOff[8] = {0, 2, 4, 6, 512, 514, 516, 518};

    float lsum = 0.0f;
    int phS = 0, phO = 0;

    for (int kbk = 0; kbk < SS / 128; kbk++) {
        if (kbk > 0) { MBARRIER_WAIT_PARITY(ctrl + 16, phO); phO ^= 1; }

        // K tile [128 keys][64 dims]
        {
            int r = tid >> 1, half = (tid & 1) * 32;
            const __nv_bfloat16* kp = kg + ((size_t)(bh * SS + kbk * 128 + r)) * HD + half;
#pragma unroll
            for (int j = 0; j < 4; j++)
                *(uint4*)(buf + FL_K + swz128((uint32_t)(r * 128 + half * 2 + j * 16))) =
                    *(const uint4*)(kp + j * 8);
        }
        // V^T tile: [64 dim-rows][128 keys], blocked atoms (8x64 bf16), col stride 8192B
#pragma unroll
        for (int j = 0; j < 4; j++) {
            int u = tid + j * 256;
            int k0 = (u & 63) * 2, d0 = (u >> 6) * 4;
            const __nv_bfloat16* vp = vg + ((size_t)(bh * SS + kbk * 128 + k0)) * HD + d0;
            uint2 a = *(const uint2*)vp;
            uint2 b = *(const uint2*)(vp + HD);
            __nv_bfloat162 A0 = *(__nv_bfloat162*)&a.x, A1 = *(__nv_bfloat162*)&a.y;
            __nv_bfloat162 B0 = *(__nv_bfloat162*)&b.x, B1 = *(__nv_bfloat162*)&b.y;
            int ac = k0 >> 6, cb = (k0 & 63) * 2;
#pragma unroll
            for (int dd = 0; dd < 4; dd++) {
                __nv_bfloat16 va = (dd == 0) ? A0.x : (dd == 1) ? A0.y : (dd == 2) ? A1.x : A1.y;
                __nv_bfloat16 vbq = (dd == 0) ? B0.x : (dd == 1) ? B0.y : (dd == 2) ? B1.x : B1.y;
                int d = d0 + dd;
                uint32_t o = (uint32_t)((ac * 8 + (d >> 3)) * 1024 + (d & 7) * 128 + cb);
                *(uint32_t*)(buf + FL_VT + swz128(o)) = pack_bf2(va, vbq);
            }
        }
        if (tid < 128) msk_s[tid] = mask[b_ * SS + kbk * 128 + tid];
        FENCE_ASYNC_SHARED();
        __syncthreads();

        // S = Q K^T  (M=128, N=128, K=64)
        if (wid == 0 && elect_one_pred()) {
#pragma unroll
            for (int s = 0; s < 4; s++)
                mma_bf16_ss(tmem, dQ + s * 2, dK + s * 2, GEMM_IDESC, s != 0);
            TCGEN05_COMMIT(ctrl + 8);
        }
        MBARRIER_WAIT_PARITY(ctrl + 8, phS);
        phS ^= 1;
        TCGEN05_FENCE_AFTER();

        // S -> P = exp(s/8) (no max-subtract; scores bounded), bf16 to smem
        const int r = sp * 32 + lane;
#pragma unroll
        for (int h2 = 0; h2 < 2; h2++) {
            uint32_t sr[32];
            TCGEN05_LD_X32(sr, tmem + chf * 64 + h2 * 32);
            TCGEN05_WAIT_LD();
            const int cbase = chf * 64 + h2 * 32;
            uint32_t ppk[16];
#pragma unroll
            for (int j = 0; j < 16; j++) {
                float p0 = msk_s[cbase + 2 * j]     ? __expf(__uint_as_float(sr[2 * j])     * 0.125f) : 0.0f;
                float p1 = msk_s[cbase + 2 * j + 1] ? __expf(__uint_as_float(sr[2 * j + 1]) * 0.125f) : 0.0f;
                __nv_bfloat16 bp0 = __float2bfloat16(p0), bp1 = __float2bfloat16(p1);
                ppk[j] = pack_bf2(bp0, bp1);
                lsum += __bfloat162float(bp0) + __bfloat162float(bp1);
            }
            uint32_t pbo = (uint32_t)((chf * 16 + (r >> 3)) * 1024 + (r & 7) * 128 + h2 * 64);
#pragma unroll
            for (int j = 0; j < 4; j++)
                *(uint4*)(buf + FL_P + swz128(pbo + j * 16)) =
                    make_uint4(ppk[4 * j], ppk[4 * j + 1], ppk[4 * j + 2], ppk[4 * j + 3]);
        }
        TCGEN05_FENCE_BEFORE();
        FENCE_ASYNC_SHARED();
        __syncthreads();

        // O += P V^T  (M=128, N=64, K=128)
        if (wid == 0 && elect_one_pred()) {
#pragma unroll
            for (int s = 0; s < 8; s++)
                mma_bf16_ss(tmem + 128, dP + pOff[s], dVT + vOff[s], IDESC_N64,
                            !(kbk == 0 && s == 0));
            TCGEN05_COMMIT(ctrl + 16);
        }
    }

    MBARRIER_WAIT_PARITY(ctrl + 16, phO);
    TCGEN05_FENCE_AFTER();
    lpart[chf * 128 + sp * 32 + lane] = lsum;
    __syncthreads();

    if (wid < 4) {
        uint32_t orr[64];
        TCGEN05_LD_X32(orr, tmem + 128);
        TCGEN05_LD_X32(orr + 32, tmem + 160);
        TCGEN05_WAIT_LD();
        TCGEN05_FENCE_BEFORE();
        const int r = sp * 32 + lane;
        float inv = 1.0f / (lpart[r] + lpart[128 + r]);
        float* op = out + ((size_t)(b_ * SS + q0 + r)) * DD + h_ * HD;
#pragma unroll
        for (int c = 0; c < 16; c++) {
            float4 v;
            v.x = __uint_as_float(orr[4 * c + 0]) * inv;
            v.y = __uint_as_float(orr[4 * c + 1]) * inv;
            v.z = __uint_as_float(orr[4 * c + 2]) * inv;
            v.w = __uint_as_float(orr[4 * c + 3]) * inv;
            *(float4*)(op + 4 * c) = v;
        }
    }
    __syncthreads();
    if (tid == 0) { MBARRIER_INVAL(ctrl + 8); MBARRIER_INVAL(ctrl + 16); }
    __syncthreads();
    if (wid == 0) TCGEN05_DEALLOC(tmem, 256);
#else
    // slow-but-correct fallback (never executed on sm_103a)
    if (tid < 128) {
        int r = q0 + tid;
        float qr[64], o[64], l = 0.0f;
        for (int d = 0; d < 64; d++) {
            qr[d] = __bfloat162float(qg[((size_t)(bh * SS + r)) * HD + d]);
            o[d] = 0.0f;
        }
        for (int key = 0; key < SS; key++) {
            if (!mask[b_ * SS + key]) continue;
            float s = 0.0f;
            const __nv_bfloat16* kp = kg + ((size_t)(bh * SS + key)) * HD;
            for (int d = 0; d < 64; d++) s += qr[d] * __bfloat162float(kp[d]);
            float pw = __expf(s * 0.125f);
            l += pw;
            const __nv_bfloat16* vp = vg + ((size_t)(bh * SS + key)) * HD;
            for (int d = 0; d < 64; d++) o[d] += pw * __bfloat162float(vp[d]);
        }
        float inv = 1.0f / l;
        for (int d = 0; d < 64; d++)
            out[((size_t)(b_ * SS + r)) * DD + h_ * HD + d] = o[d] * inv;
    }
#endif
}

// ---------------- residual + bias + LN ----------------
__global__ __launch_bounds__(256) void add_ln_kernel(
    const float* __restrict__ a, const float* __restrict__ b,
    const float* __restrict__ bias,
    const float* __restrict__ g, const float* __restrict__ be,
    float* __restrict__ out)
{
    __shared__ float sh[10];
    const int row = blockIdx.x;
    const int tid = threadIdx.x;
    const int wid = tid >> 5, lane = tid & 31;
    const size_t base = (size_t)row * DD + tid * 4;

    float4 av = *(const float4*)(a + base);
    float4 bv = *(const float4*)(b + base);
    float4 cv = *(const float4*)(bias + tid * 4);
    float4 t = make_float4(av.x + bv.x + cv.x, av.y + bv.y + cv.y,
                           av.z + bv.z + cv.z, av.w + bv.w + cv.w);
    float s = t.x + t.y + t.z + t.w;
#pragma unroll
    for (int off = 16; off >= 1; off >>= 1) s += __shfl_xor_sync(0xffffffffu, s, off);
    if (lane == 0) sh[wid] = s;
    __syncthreads();
    if (tid == 0) {
        float t2 = 0.f;
#pragma unroll
        for (int w = 0; w < 8; w++) t2 += sh[w];
        sh[8] = t2 * (1.0f / 1024.0f);
    }
    __syncthreads();
    float mu = sh[8];
    float dx = t.x - mu, dy = t.y - mu, dz = t.z - mu, dw = t.w - mu;
    float sq = dx * dx + dy * dy + dz * dz + dw * dw;
#pragma unroll
    for (int off = 16; off >= 1; off >>= 1) sq += __shfl_xor_sync(0xffffffffu, sq, off);
    if (lane == 0) sh[wid] = sq;
    __syncthreads();
    if (tid == 0) {
        float t2 = 0.f;
#pragma unroll
        for (int w = 0; w < 8; w++) t2 += sh[w];
        sh[9] = rsqrtf(t2 * (1.0f / 1024.0f) + 1e-5f);
    }
    __syncthreads();
    float inv = sh[9];
    float4 gv = *(const float4*)(g + tid * 4);
    float4 bev = *(const float4*)(be + tid * 4);
    *(float4*)(out + base) = make_float4(dx * inv * gv.x + bev.x, dy * inv * gv.y + bev.y,
                                         dz * inv * gv.z + bev.z, dw * inv * gv.w + bev.w);
}

// ---------------------------------------------------------------------------
extern "C" void kernel_launch(void* const* d_in, const int* in_sizes, int n_in,
                              void* d_out, int out_size)
{
    const float* x   = (const float*)d_in[0];
    const int*   msk = (const int*)d_in[1];
    const float* Wq  = (const float*)d_in[2];
    const float* bq  = (const float*)d_in[3];
    const float* Wk  = (const float*)d_in[4];
    const float* bk  = (const float*)d_in[5];
    const float* Wv  = (const float*)d_in[6];
    const float* bv  = (const float*)d_in[7];
    const float* Wo  = (const float*)d_in[8];
    const float* bo  = (const float*)d_in[9];
    const float* W1  = (const float*)d_in[10];
    const float* b1  = (const float*)d_in[11];
    const float* W2  = (const float*)d_in[12];
    const float* b2  = (const float*)d_in[13];
    const float* g1  = (const float*)d_in[14];
    const float* be1 = (const float*)d_in[15];
    const float* g2  = (const float*)d_in[16];
    const float* be2 = (const float*)d_in[17];
    float* out = (float*)d_out;

    float *q, *kb, *attn, *ffh;
    __nv_bfloat16 *wh, *wl, *qbb, *kbb, *vbb;
    cudaGetSymbolAddress((void**)&q,    g_q);
    cudaGetSymbolAddress((void**)&kb,   g_k);
    cudaGetSymbolAddress((void**)&attn, g_attn);
    cudaGetSymbolAddress((void**)&ffh,  g_ff);
    cudaGetSymbolAddress((void**)&wh,   g_wh);
    cudaGetSymbolAddress((void**)&wl,   g_wl);
    cudaGetSymbolAddress((void**)&qbb,  g_qb);
    cudaGetSymbolAddress((void**)&kbb,  g_kb);
    cudaGetSymbolAddress((void**)&vbb,  g_vb);

    cudaFuncSetAttribute(gemm_tc_kernel,
                         cudaFuncAttributeMaxDynamicSharedMemorySize, GEMM_SMEM_BYTES);
    cudaFuncSetAttribute(flash_tc_kernel,
                         cudaFuncAttributeMaxDynamicSharedMemorySize, FL_SMEM);

    dim3 blk(256);
    dim3 pw(32, 8);

    prep_w_kernel<<<dim3(DD / 32, DD / 32), pw>>>(Wq, wh + WQ_OFF, wl + WQ_OFF, DD, DD);
    prep_w_kernel<<<dim3(DD / 32, DD / 32), pw>>>(Wk, wh + WK_OFF, wl + WK_OFF, DD, DD);
    prep_w_kernel<<<dim3(DD / 32, DD / 32), pw>>>(Wv, wh + WV_OFF, wl + WV_OFF, DD, DD);
    prep_w_kernel<<<dim3(DD / 32, DD / 32), pw>>>(Wo, wh + WO_OFF, wl + WO_OFF, DD, DD);
    prep_w_kernel<<<dim3(FF / 32, DD / 32), pw>>>(W1, wh + W1_OFF, wl + W1_OFF, DD, FF);
    prep_w_kernel<<<dim3(DD / 32, FF / 32), pw>>>(W2, wh + W2_OFF, wl + W2_OFF, FF, DD);

    dim3 gD(DD / 128, MM / 128);
    dim3 gF(FF / 128, MM / 128);

    gemm_tc_kernel<<<gD, blk, GEMM_SMEM_BYTES>>>(x, wh + WQ_OFF, wl + WQ_OFF, attn, MM, DD, DD);
    scatter_bias_kernel<<<MM, blk>>>(attn, bq, qbb);
    gemm_tc_kernel<<<gD, blk, GEMM_SMEM_BYTES>>>(x, wh + WK_OFF, wl + WK_OFF, attn, MM, DD, DD);
    scatter_bias_kernel<<<MM, blk>>>(attn, bk, kbb);
    gemm_tc_kernel<<<gD, blk, GEMM_SMEM_BYTES>>>(x, wh + WV_OFF, wl + WV_OFF, attn, MM, DD, DD);
    scatter_bias_kernel<<<MM, blk>>>(attn, bv, vbb);

    flash_tc_kernel<<<dim3(SS / 128, BB * HH), blk, FL_SMEM>>>(qbb, kbb, vbb, msk, attn);

    gemm_tc_kernel<<<gD, blk, GEMM_SMEM_BYTES>>>(attn, wh + WO_OFF, wl + WO_OFF, ffh, MM, DD, DD);
    add_ln_kernel<<<MM, blk>>>(x, ffh, bo, g1, be1, q);

    gemm_tc_kernel<<<gF, blk, GEMM_SMEM_BYTES>>>(q, wh + W1_OFF, wl + W1_OFF, ffh, MM, FF, DD);
    bias_relu_kernel<<<(size_t)MM * FF / 1024, blk>>>(ffh, b1);
    gemm_tc_kernel<<<gD, blk, GEMM_SMEM_BYTES>>>(ffh, wh + W2_OFF, wl + W2_OFF, kb, MM, DD, FF);

    add_ln_kernel<<<MM, blk>>>(q, kb, b2, g2, be2, out);
}

// round 9
// speedup vs baseline: 4.9245x; 1.4476x over previous
#include <cuda_runtime.h>
#include <cuda_bf16.h>
#include <math.h>
#include <stdint.h>

constexpr int BB = 4;
constexpr int SS = 2048;
constexpr int DD = 1024;
constexpr int HH = 16;
constexpr int HD = 64;
constexpr int FF = 4096;
constexpr int MM = BB * SS;

#if defined(__CUDA_ARCH_FEAT_SM103_ALL) || defined(__CUDA_ARCH_FEAT_SM100_ALL)
#define HAS_TCGEN05 1
#else
#define HAS_TCGEN05 0
#endif

// ---------------- device scratch ----------------
__device__ __nv_bfloat16 g_xh[(size_t)MM * DD];
__device__ __nv_bfloat16 g_xl[(size_t)MM * DD];
__device__ __nv_bfloat16 g_qh[(size_t)MM * DD];   // q head layout
__device__ __nv_bfloat16 g_kh[(size_t)MM * DD];   // k head layout
__device__ __nv_bfloat16 g_vh[(size_t)MM * DD];   // v head layout
__device__ __nv_bfloat16 g_oh[(size_t)MM * DD];   // attn out hi
__device__ __nv_bfloat16 g_ol[(size_t)MM * DD];   // attn out lo
__device__ __nv_bfloat16 g_hb[(size_t)MM * DD];   // h hi
__device__ __nv_bfloat16 g_hl[(size_t)MM * DD];   // h lo
__device__ __nv_bfloat16 g_fh[(size_t)MM * FF];   // hidden hi
__device__ __nv_bfloat16 g_fl[(size_t)MM * FF];   // hidden lo
__device__ float g_f32a[(size_t)MM * DD];         // o-proj out
__device__ float g_f32b[(size_t)MM * DD];         // h fp32
__device__ float g_f32c[(size_t)MM * DD];         // ffn2 out

constexpr size_t WQ_OFF = 0;
constexpr size_t WK_OFF = 1048576;
constexpr size_t WV_OFF = 2097152;
constexpr size_t WO_OFF = 3145728;
constexpr size_t W1_OFF = 4194304;
constexpr size_t W2_OFF = 8388608;
constexpr size_t WTOT   = 12582912;
__device__ __nv_bfloat16 g_wh[WTOT];
__device__ __nv_bfloat16 g_wl[WTOT];

// ---------------- helpers ----------------
__device__ __forceinline__ uint32_t smem_u32(const void* p) {
    uint32_t a;
    asm("{ .reg .u64 t; cvta.to.shared.u64 t, %1; cvt.u32.u64 %0, t; }" : "=r"(a) : "l"(p));
    return a;
}
__device__ __forceinline__ uint32_t swz128(uint32_t off) { return off ^ ((off >> 3) & 0x70); }
__device__ __forceinline__ uint32_t pack_bf2(__nv_bfloat16 a, __nv_bfloat16 b) {
    __nv_bfloat162 t; t.x = a; t.y = b; return *(uint32_t*)&t;
}
#define CP_ASYNC16(saddr, gptr) \
    asm volatile("cp.async.cg.shared.global [%0], [%1], 16;" \
        :: "r"((uint32_t)(saddr)), "l"(gptr) : "memory")
#define CP_COMMIT() asm volatile("cp.async.commit_group;" ::: "memory")
#define CP_WAIT(n)  asm volatile("cp.async.wait_group %0;" :: "n"(n) : "memory")

#if HAS_TCGEN05
__device__ __forceinline__ uint32_t elect_one_pred() {
    uint32_t pred;
    asm volatile("{\n\t.reg .pred p;\n\telect.sync _|p, 0xFFFFFFFF;\n\tselp.b32 %0, 1, 0, p;\n\t}" : "=r"(pred));
    return pred;
}
#define TCGEN05_ALLOC(smem_addr, nCols) \
    asm volatile("tcgen05.alloc.cta_group::1.sync.aligned.shared::cta.b32 [%0], %1;" \
        :: "r"((uint32_t)(smem_addr)), "r"((uint32_t)(nCols)) : "memory")
#define TCGEN05_DEALLOC(tmem_addr, nCols) \
    asm volatile("tcgen05.dealloc.cta_group::1.sync.aligned.b32 %0, %1;" \
        :: "r"(tmem_addr), "r"((uint32_t)(nCols)))
#define TCGEN05_COMMIT(mbar) \
    asm volatile("tcgen05.commit.cta_group::1.mbarrier::arrive::one.shared::cluster.b64 [%0];" \
        :: "r"((uint32_t)(mbar)) : "memory")
#define TCGEN05_WAIT_LD()  asm volatile("tcgen05.wait::ld.sync.aligned;" ::: "memory")
#define TCGEN05_FENCE_BEFORE() asm volatile("tcgen05.fence::before_thread_sync;" ::: "memory")
#define TCGEN05_FENCE_AFTER()  asm volatile("tcgen05.fence::after_thread_sync;" ::: "memory")
#define FENCE_ASYNC_SHARED() asm volatile("fence.proxy.async.shared::cta;" ::: "memory")
#define MBARRIER_INIT(mbar, cnt) \
    asm volatile("mbarrier.init.shared.b64 [%0], %1;" :: "r"((uint32_t)(mbar)), "r"((uint32_t)(cnt)) : "memory")
#define MBARRIER_INVAL(mbar) \
    asm volatile("mbarrier.inval.shared.b64 [%0];" :: "r"((uint32_t)(mbar)) : "memory")
#define MBARRIER_WAIT_PARITY(mbar, parity) do {                                    \
    uint32_t _mb = (uint32_t)(mbar);                                               \
    uint32_t _pa = (uint32_t)(parity);                                             \
    uint32_t _done;                                                                \
    asm volatile(                                                                  \
        "{\n\t.reg .pred p;\n\t"                                                   \
        "mbarrier.try_wait.parity.acquire.cta.shared::cta.b64 p, [%1], %2;\n\t"    \
        "selp.b32 %0, 1, 0, p;\n\t}"                                               \
        : "=r"(_done) : "r"(_mb), "r"(_pa) : "memory");                            \
    if (!_done) {                                                                  \
        asm volatile(                                                              \
            "{\n\t.reg .pred P1;\n\t"                                              \
            "WL_%=:\n\t"                                                           \
            "mbarrier.try_wait.parity.acquire.cta.shared::cta.b64 P1, [%0], %1, 0x989680;\n\t" \
            "@P1 bra.uni WD_%=;\n\t"                                               \
            "bra.uni WL_%=;\n\t"                                                   \
            "WD_%=:\n\t}"                                                          \
            :: "r"(_mb), "r"(_pa) : "memory");                                     \
    }                                                                              \
} while (0)
#define TCGEN05_LD_X32(r, addr) \
    asm volatile( \
        "tcgen05.ld.sync.aligned.32x32b.x32.b32 " \
        "{%0, %1, %2, %3, %4, %5, %6, %7, " \
        " %8, %9, %10, %11, %12, %13, %14, %15, " \
        " %16, %17, %18, %19, %20, %21, %22, %23, " \
        " %24, %25, %26, %27, %28, %29, %30, %31}, [%32];" \
        : "=r"((r)[0]),  "=r"((r)[1]),  "=r"((r)[2]),  "=r"((r)[3]), \
          "=r"((r)[4]),  "=r"((r)[5]),  "=r"((r)[6]),  "=r"((r)[7]), \
          "=r"((r)[8]),  "=r"((r)[9]),  "=r"((r)[10]), "=r"((r)[11]), \
          "=r"((r)[12]), "=r"((r)[13]), "=r"((r)[14]), "=r"((r)[15]), \
          "=r"((r)[16]), "=r"((r)[17]), "=r"((r)[18]), "=r"((r)[19]), \
          "=r"((r)[20]), "=r"((r)[21]), "=r"((r)[22]), "=r"((r)[23]), \
          "=r"((r)[24]), "=r"((r)[25]), "=r"((r)[26]), "=r"((r)[27]), \
          "=r"((r)[28]), "=r"((r)[29]), "=r"((r)[30]), "=r"((r)[31]) \
        : "r"(addr))

__device__ __forceinline__ uint64_t make_desc_sw128(uint32_t addr) {
    constexpr uint64_t BASE =
        (uint64_t(2) << 61) | (uint64_t(1) << 46) | (uint64_t(64) << 32) | (uint64_t(1) << 16);
    return BASE | ((uint64_t)(addr >> 4) & 0x3FFF);
}
__device__ __forceinline__ void mma_bf16_ss(uint32_t d, uint64_t ad, uint64_t bd,
                                            uint32_t idesc, bool acc) {
    uint32_t en = acc ? 1u : 0u;
    asm volatile(
        "{\n\t.reg .pred p;\n\t"
        "setp.ne.u32 p, %5, 0;\n\t"
        "tcgen05.mma.cta_group::1.kind::f16 [%0], %1, %2, %3, {%4, %4, %4, %4}, p;\n\t}"
        :: "r"(d), "l"(ad), "l"(bd), "r"(idesc), "r"(0u), "r"(en) : "memory");
}
#endif

constexpr uint32_t GEMM_IDESC =
    (1u << 4) | (1u << 7) | (1u << 10) | ((128 / 8) << 17) | ((128 / 16) << 24);
constexpr uint32_t IDESC_N64 =
    (1u << 4) | (1u << 7) | (1u << 10) | ((64 / 8) << 17) | ((128 / 16) << 24);

// ---------------- weight prep ----------------
__global__ void prep_w_kernel(const float* __restrict__ W,
                              __nv_bfloat16* __restrict__ Bh,
                              __nv_bfloat16* __restrict__ Bl, int K, int N)
{
    __shared__ float t[32][33];
    const int n0 = blockIdx.x * 32, k0 = blockIdx.y * 32;
#pragma unroll
    for (int i = 0; i < 4; i++)
        t[threadIdx.y + i * 8][threadIdx.x] =
            W[(size_t)(k0 + threadIdx.y + i * 8) * N + n0 + threadIdx.x];
    __syncthreads();
#pragma unroll
    for (int i = 0; i < 4; i++) {
        int n = threadIdx.y + i * 8;
        float v = t[threadIdx.x][n];
        __nv_bfloat16 h = __float2bfloat16(v);
        size_t idx = (size_t)(n0 + n) * K + k0 + threadIdx.x;
        Bh[idx] = h;
        Bl[idx] = __float2bfloat16(v - __bfloat162float(h));
    }
}

// fp32 -> bf16 hi/lo split
__global__ __launch_bounds__(256) void split_kernel(
    const float* __restrict__ in,
    __nv_bfloat16* __restrict__ oh, __nv_bfloat16* __restrict__ ol)
{
    size_t i = ((size_t)blockIdx.x * 256 + threadIdx.x) * 4;
    float4 v = *(const float4*)(in + i);
    __nv_bfloat16 h0 = __float2bfloat16(v.x), h1 = __float2bfloat16(v.y);
    __nv_bfloat16 h2 = __float2bfloat16(v.z), h3 = __float2bfloat16(v.w);
    *(uint2*)(oh + i) = make_uint2(pack_bf2(h0, h1), pack_bf2(h2, h3));
    *(uint2*)(ol + i) = make_uint2(
        pack_bf2(__float2bfloat16(v.x - __bfloat162float(h0)),
                 __float2bfloat16(v.y - __bfloat162float(h1))),
        pack_bf2(__float2bfloat16(v.z - __bfloat162float(h2)),
                 __float2bfloat16(v.w - __bfloat162float(h3))));
}

// ---------------------------------------------------------------------------
// GEMM: C[M,N] = (Ah+Al) @ (Bh+Bl)^T, all bf16 [.][K] K-major, cp.async 3-stage
// EPI 0: Cf = v  (fp32, no bias)
// EPI 1: relu(v + bias0[col]) -> Ch/Cl hi/lo bf16 at [row][col]
// EPI 2: QKV combined N=3072: v + bias(mat)[col] -> head layout bf16 D0/D1/D2
// ---------------------------------------------------------------------------
constexpr int GEMM_NSTAGE = 3;
constexpr int GEMM_SMEM_BYTES = GEMM_NSTAGE * 65536 + 1024;

template <int EPI>
__global__ __launch_bounds__(256, 1) void gemm_bf(
    const __nv_bfloat16* __restrict__ Ah, const __nv_bfloat16* __restrict__ Al,
    const __nv_bfloat16* __restrict__ Bh, const __nv_bfloat16* __restrict__ Bl,
    float* __restrict__ Cf, __nv_bfloat16* __restrict__ Ch, __nv_bfloat16* __restrict__ Cl,
    __nv_bfloat16* __restrict__ D0, __nv_bfloat16* __restrict__ D1, __nv_bfloat16* __restrict__ D2,
    const float* __restrict__ bias0, const float* __restrict__ bias1, const float* __restrict__ bias2,
    int M, int N, int K)
{
    extern __shared__ char dsmem[];
    uintptr_t p = ((uintptr_t)dsmem + 1023) & ~(uintptr_t)1023;
    char* buf = (char*)p;
    const int tid = threadIdx.x;
    const int wid = tid >> 5;
    const int lane = tid & 31;
    const int m0 = blockIdx.y << 7;
    const int n0 = blockIdx.x << 7;

#if HAS_TCGEN05
    __shared__ alignas(16) unsigned long long ctrlq[5];
    const uint32_t sbuf = smem_u32(buf);
    const uint32_t ctrl = smem_u32(ctrlq);

    if (wid == 0) TCGEN05_ALLOC(ctrl, 128);
    if (tid == 0) {
        MBARRIER_INIT(ctrl + 8, 1);
        MBARRIER_INIT(ctrl + 16, 1);
        MBARRIER_INIT(ctrl + 24, 1);
        MBARRIER_INIT(ctrl + 32, 1);
    }
    __syncthreads();
    uint32_t tmem;
    asm volatile("ld.shared.b32 %0, [%1];" : "=r"(tmem) : "r"(ctrl));

    const int NC = K >> 6;

    auto load_chunk = [&](int ck, int st) {
        const uint32_t sb = sbuf + (uint32_t)st * 65536;
        const int k0 = ck << 6;
#pragma unroll
        for (int j = 0; j < 4; j++) {
            int u = tid + j * 256;
            int r = u >> 3, g = u & 7;
            uint32_t so = swz128((uint32_t)(r * 128 + g * 16));
            size_t ao = (size_t)(m0 + r) * K + k0 + g * 8;
            size_t bo = (size_t)(n0 + r) * K + k0 + g * 8;
            CP_ASYNC16(sb + so,         Ah + ao);
            CP_ASYNC16(sb + 16384 + so, Al + ao);
            CP_ASYNC16(sb + 32768 + so, Bh + bo);
            CP_ASYNC16(sb + 49152 + so, Bl + bo);
        }
    };

    // prologue: fill 3 stages
#pragma unroll
    for (int s = 0; s < GEMM_NSTAGE; s++) { load_chunk(s, s); CP_COMMIT(); }

    int ph[3] = {0, 0, 0};

    for (int i = 0; i < NC; i++) {
        const int st = i % 3;
        // wait for chunk i's data
        if (i < NC - 2)      CP_WAIT(2);
        else if (i == NC - 2) CP_WAIT(1);
        else                  CP_WAIT(0);
        __syncthreads();
        FENCE_ASYNC_SHARED();

        if (wid == 0 && elect_one_pred()) {
            const uint32_t boff = (uint32_t)st * 65536;
            uint64_t dAh = make_desc_sw128(sbuf + boff);
            uint64_t dAl = make_desc_sw128(sbuf + boff + 16384);
            uint64_t dBh = make_desc_sw128(sbuf + boff + 32768);
            uint64_t dBl = make_desc_sw128(sbuf + boff + 49152);
#pragma unroll
            for (int ks = 0; ks < 4; ks++)
                mma_bf16_ss(tmem, dAh + ks * 2, dBh + ks * 2, GEMM_IDESC, !(i == 0 && ks == 0));
#pragma unroll
            for (int ks = 0; ks < 4; ks++)
                mma_bf16_ss(tmem, dAl + ks * 2, dBh + ks * 2, GEMM_IDESC, true);
#pragma unroll
            for (int ks = 0; ks < 4; ks++)
                mma_bf16_ss(tmem, dAh + ks * 2, dBl + ks * 2, GEMM_IDESC, true);
            TCGEN05_COMMIT(ctrl + 8 + st * 8);
        }

        int ni = i + GEMM_NSTAGE;
        if (ni < NC) {
            // buffer st reusable once MMA of chunk i is done
            MBARRIER_WAIT_PARITY(ctrl + 8 + st * 8, ph[st]);
            ph[st] ^= 1;
            load_chunk(ni, st);
            CP_COMMIT();
        }
    }

    if (wid == 0 && elect_one_pred()) TCGEN05_COMMIT(ctrl + 32);
    MBARRIER_WAIT_PARITY(ctrl + 32, 0);
    TCGEN05_FENCE_AFTER();

    // epilogue
    {
        const int sp = wid & 3;
        const int chf = wid >> 2;
        uint32_t r[64];
        TCGEN05_LD_X32(r, tmem + chf * 64);
        TCGEN05_LD_X32(r + 32, tmem + chf * 64 + 32);
        TCGEN05_WAIT_LD();
        TCGEN05_FENCE_BEFORE();

        const int row = m0 + sp * 32 + lane;
        const int c0 = n0 + chf * 64;

        if (EPI == 0) {
            float* cp = Cf + (size_t)row * N + c0;
#pragma unroll
            for (int c = 0; c < 16; c++) {
                float4 v;
                v.x = __uint_as_float(r[4 * c + 0]);
                v.y = __uint_as_float(r[4 * c + 1]);
                v.z = __uint_as_float(r[4 * c + 2]);
                v.w = __uint_as_float(r[4 * c + 3]);
                *(float4*)(cp + 4 * c) = v;
            }
        } else if (EPI == 1) {
            size_t base = (size_t)row * N + c0;
#pragma unroll
            for (int j8 = 0; j8 < 8; j8++) {
                uint32_t hw[4], lw[4];
#pragma unroll
                for (int q = 0; q < 4; q++) {
                    int j = j8 * 8 + q * 2;
                    float v0 = fmaxf(__uint_as_float(r[j])     + bias0[c0 + j],     0.0f);
                    float v1 = fmaxf(__uint_as_float(r[j + 1]) + bias0[c0 + j + 1], 0.0f);
                    __nv_bfloat16 h0 = __float2bfloat16(v0), h1 = __float2bfloat16(v1);
                    hw[q] = pack_bf2(h0, h1);
                    lw[q] = pack_bf2(__float2bfloat16(v0 - __bfloat162float(h0)),
                                     __float2bfloat16(v1 - __bfloat162float(h1)));
                }
                *(uint4*)(Ch + base + j8 * 8) = make_uint4(hw[0], hw[1], hw[2], hw[3]);
                *(uint4*)(Cl + base + j8 * 8) = make_uint4(lw[0], lw[1], lw[2], lw[3]);
            }
        } else {  // EPI == 2: QKV combined -> head layout bf16
            const int mat = c0 >> 10;
            const int lc = c0 & 1023;
            const float* bs = (mat == 0) ? bias0 : (mat == 1) ? bias1 : bias2;
            __nv_bfloat16* Dd = (mat == 0) ? D0 : (mat == 1) ? D1 : D2;
            const int h_ = lc >> 6;
            const int b_ = row >> 11;
            const int s_ = row & (SS - 1);
            size_t base = (((size_t)b_ * HH + h_) * SS + s_) * HD;
#pragma unroll
            for (int j8 = 0; j8 < 8; j8++) {
                uint32_t hw[4];
#pragma unroll
                for (int q = 0; q < 4; q++) {
                    int j = j8 * 8 + q * 2;
                    float v0 = __uint_as_float(r[j])     + bs[lc + j];
                    float v1 = __uint_as_float(r[j + 1]) + bs[lc + j + 1];
                    hw[q] = pack_bf2(__float2bfloat16(v0), __float2bfloat16(v1));
                }
                *(uint4*)(Dd + base + j8 * 8) = make_uint4(hw[0], hw[1], hw[2], hw[3]);
            }
        }
    }

    __syncthreads();
    if (tid == 0) {
        MBARRIER_INVAL(ctrl + 8);
        MBARRIER_INVAL(ctrl + 16);
        MBARRIER_INVAL(ctrl + 24);
        MBARRIER_INVAL(ctrl + 32);
    }
    __syncthreads();
    if (wid == 0) TCGEN05_DEALLOC(tmem, 128);

#else  // ---------------- FFMA fallback ----------------
    float* As = (float*)buf;
    float* Bs = As + 16 * 132;
    const int tx = tid & 15, ty = tid >> 4;
    float acc[8][8];
#pragma unroll
    for (int i = 0; i < 8; i++)
#pragma unroll
        for (int j = 0; j < 8; j++) acc[i][j] = 0.0f;
    for (int k0 = 0; k0 < K; k0 += 16) {
        for (int it = 0; it < 8; it++) {
            int idx = tid + it * 256;
            int rr = idx >> 4, kk = idx & 15;
            As[kk * 132 + rr] =
                __bfloat162float(Ah[(size_t)(m0 + rr) * K + k0 + kk]) +
                __bfloat162float(Al[(size_t)(m0 + rr) * K + k0 + kk]);
            Bs[kk * 132 + rr] =
                __bfloat162float(Bh[(size_t)(n0 + rr) * K + k0 + kk]) +
                __bfloat162float(Bl[(size_t)(n0 + rr) * K + k0 + kk]);
        }
        __syncthreads();
#pragma unroll
        for (int k = 0; k < 16; k++) {
            float a[8], bb[8];
#pragma unroll
            for (int i = 0; i < 8; i++) a[i] = As[k * 132 + ty * 8 + i];
#pragma unroll
            for (int j = 0; j < 8; j++) bb[j] = Bs[k * 132 + tx * 8 + j];
#pragma unroll
            for (int i = 0; i < 8; i++)
#pragma unroll
                for (int j = 0; j < 8; j++) acc[i][j] = fmaf(a[i], bb[j], acc[i][j]);
        }
        __syncthreads();
    }
#pragma unroll
    for (int i = 0; i < 8; i++) {
        int row = m0 + ty * 8 + i;
#pragma unroll
        for (int j = 0; j < 8; j++) {
            int col = n0 + tx * 8 + j;
            float v = acc[i][j];
            if (EPI == 0) {
                Cf[(size_t)row * N + col] = v;
            } else if (EPI == 1) {
                v = fmaxf(v + bias0[col], 0.0f);
                __nv_bfloat16 h = __float2bfloat16(v);
                Ch[(size_t)row * N + col] = h;
                Cl[(size_t)row * N + col] = __float2bfloat16(v - __bfloat162float(h));
            } else {
                int mat = col >> 10, lc = col & 1023;
                const float* bs = (mat == 0) ? bias0 : (mat == 1) ? bias1 : bias2;
                __nv_bfloat16* Dd = (mat == 0) ? D0 : (mat == 1) ? D1 : D2;
                float vv = v + bs[lc];
                int h_ = lc >> 6, d = lc & 63;
                int b_ = row >> 11, s_ = row & (SS - 1);
                Dd[(((size_t)b_ * HH + h_) * SS + s_) * HD + d] = __float2bfloat16(vv);
            }
        }
    }
#endif
}

// ---------------- tcgen05 flash attention (proven; output now split bf16) ----
constexpr int FL_Q = 0, FL_K = 16384, FL_VT = 32768, FL_P = 49152, FL_CT = 81920;
constexpr int FL_SMEM = FL_CT + 2048 + 1024;

__global__ __launch_bounds__(256, 2) void flash_tc_kernel(
    const __nv_bfloat16* __restrict__ qg, const __nv_bfloat16* __restrict__ kg,
    const __nv_bfloat16* __restrict__ vg, const int* __restrict__ mask,
    __nv_bfloat16* __restrict__ outh, __nv_bfloat16* __restrict__ outl)
{
    extern __shared__ char dsmem[];
    uintptr_t pb = ((uintptr_t)dsmem + 1023) & ~(uintptr_t)1023;
    char* buf = (char*)pb;
    const int tid = threadIdx.x;
    const int wid = tid >> 5;
    const int lane = tid & 31;
    const int bh = blockIdx.y;
    const int b_ = bh >> 4;
    const int h_ = bh & (HH - 1);
    const int q0 = blockIdx.x * 128;

#if HAS_TCGEN05
    const int sp = wid & 3;
    const int chf = wid >> 2;
    const uint32_t sbuf = smem_u32(buf);
    const uint32_t ctrl = sbuf + FL_CT;
    int* msk_s = (int*)(buf + FL_CT + 32);
    float* lpart = (float*)(buf + FL_CT + 544);

    if (wid == 0) TCGEN05_ALLOC(ctrl, 256);
    if (tid == 0) { MBARRIER_INIT(ctrl + 8, 1); MBARRIER_INIT(ctrl + 16, 1); }
    __syncthreads();
    uint32_t tmem;
    asm volatile("ld.shared.b32 %0, [%1];" : "=r"(tmem) : "r"(ctrl));

    {
        int r = tid >> 1, half = (tid & 1) * 32;
        const __nv_bfloat16* qp = qg + ((size_t)(bh * SS + q0 + r)) * HD + half;
#pragma unroll
        for (int j = 0; j < 4; j++)
            *(uint4*)(buf + FL_Q + swz128((uint32_t)(r * 128 + half * 2 + j * 16))) =
                *(const uint4*)(qp + j * 8);
    }

    const uint64_t dQ  = make_desc_sw128(sbuf + FL_Q);
    const uint64_t dK  = make_desc_sw128(sbuf + FL_K);
    const uint64_t dP  = make_desc_sw128(sbuf + FL_P);
    const uint64_t dVT = make_desc_sw128(sbuf + FL_VT);
    const int pOff[8] = {0, 2, 4, 6, 1024, 1026, 1028, 1030};
    const int vOff[8] = {0, 2, 4, 6, 512, 514, 516, 518};

    float lsum = 0.0f;
    int phS = 0, phO = 0;

    for (int kbk = 0; kbk < SS / 128; kbk++) {
        if (kbk > 0) { MBARRIER_WAIT_PARITY(ctrl + 16, phO); phO ^= 1; }
        {
            int r = tid >> 1, half = (tid & 1) * 32;
            const __nv_bfloat16* kp = kg + ((size_t)(bh * SS + kbk * 128 + r)) * HD + half;
#pragma unroll
            for (int j = 0; j < 4; j++)
                *(uint4*)(buf + FL_K + swz128((uint32_t)(r * 128 + half * 2 + j * 16))) =
                    *(const uint4*)(kp + j * 8);
        }
#pragma unroll
        for (int j = 0; j < 4; j++) {
            int u = tid + j * 256;
            int k0 = (u & 63) * 2, d0 = (u >> 6) * 4;
            const __nv_bfloat16* vp = vg + ((size_t)(bh * SS + kbk * 128 + k0)) * HD + d0;
            uint2 a = *(const uint2*)vp;
            uint2 b = *(const uint2*)(vp + HD);
            __nv_bfloat162 A0 = *(__nv_bfloat162*)&a.x, A1 = *(__nv_bfloat162*)&a.y;
            __nv_bfloat162 B0 = *(__nv_bfloat162*)&b.x, B1 = *(__nv_bfloat162*)&b.y;
            int ac = k0 >> 6, cb = (k0 & 63) * 2;
#pragma unroll
            for (int dd = 0; dd < 4; dd++) {
                __nv_bfloat16 va = (dd == 0) ? A0.x : (dd == 1) ? A0.y : (dd == 2) ? A1.x : A1.y;
                __nv_bfloat16 vbq = (dd == 0) ? B0.x : (dd == 1) ? B0.y : (dd == 2) ? B1.x : B1.y;
                int d = d0 + dd;
                uint32_t o = (uint32_t)((ac * 8 + (d >> 3)) * 1024 + (d & 7) * 128 + cb);
                *(uint32_t*)(buf + FL_VT + swz128(o)) = pack_bf2(va, vbq);
            }
        }
        if (tid < 128) msk_s[tid] = mask[b_ * SS + kbk * 128 + tid];
        FENCE_ASYNC_SHARED();
        __syncthreads();

        if (wid == 0 && elect_one_pred()) {
#pragma unroll
            for (int s = 0; s < 4; s++)
                mma_bf16_ss(tmem, dQ + s * 2, dK + s * 2, GEMM_IDESC, s != 0);
            TCGEN05_COMMIT(ctrl + 8);
        }
        MBARRIER_WAIT_PARITY(ctrl + 8, phS);
        phS ^= 1;
        TCGEN05_FENCE_AFTER();

        const int r = sp * 32 + lane;
#pragma unroll
        for (int h2 = 0; h2 < 2; h2++) {
            uint32_t sr[32];
            TCGEN05_LD_X32(sr, tmem + chf * 64 + h2 * 32);
            TCGEN05_WAIT_LD();
            const int cbase = chf * 64 + h2 * 32;
            uint32_t ppk[16];
#pragma unroll
            for (int j = 0; j < 16; j++) {
                float p0 = msk_s[cbase + 2 * j]     ? __expf(__uint_as_float(sr[2 * j])     * 0.125f) : 0.0f;
                float p1 = msk_s[cbase + 2 * j + 1] ? __expf(__uint_as_float(sr[2 * j + 1]) * 0.125f) : 0.0f;
                __nv_bfloat16 bp0 = __float2bfloat16(p0), bp1 = __float2bfloat16(p1);
                ppk[j] = pack_bf2(bp0, bp1);
                lsum += __bfloat162float(bp0) + __bfloat162float(bp1);
            }
            uint32_t pbo = (uint32_t)((chf * 16 + (r >> 3)) * 1024 + (r & 7) * 128 + h2 * 64);
#pragma unroll
            for (int j = 0; j < 4; j++)
                *(uint4*)(buf + FL_P + swz128(pbo + j * 16)) =
                    make_uint4(ppk[4 * j], ppk[4 * j + 1], ppk[4 * j + 2], ppk[4 * j + 3]);
        }
        TCGEN05_FENCE_BEFORE();
        FENCE_ASYNC_SHARED();
        __syncthreads();

        if (wid == 0 && elect_one_pred()) {
#pragma unroll
            for (int s = 0; s < 8; s++)
                mma_bf16_ss(tmem + 128, dP + pOff[s], dVT + vOff[s], IDESC_N64,
                            !(kbk == 0 && s == 0));
            TCGEN05_COMMIT(ctrl + 16);
        }
    }

    MBARRIER_WAIT_PARITY(ctrl + 16, phO);
    TCGEN05_FENCE_AFTER();
    lpart[chf * 128 + sp * 32 + lane] = lsum;
    __syncthreads();

    if (wid < 4) {
        uint32_t orr[64];
        TCGEN05_LD_X32(orr, tmem + 128);
        TCGEN05_LD_X32(orr + 32, tmem + 160);
        TCGEN05_WAIT_LD();
        TCGEN05_FENCE_BEFORE();
        const int r = sp * 32 + lane;
        float inv = 1.0f / (lpart[r] + lpart[128 + r]);
        size_t base = ((size_t)(b_ * SS + q0 + r)) * DD + h_ * HD;
#pragma unroll
        for (int j8 = 0; j8 < 8; j8++) {
            uint32_t hw[4], lw[4];
#pragma unroll
            for (int q = 0; q < 4; q++) {
                int j = j8 * 8 + q * 2;
                float v0 = __uint_as_float(orr[j])     * inv;
                float v1 = __uint_as_float(orr[j + 1]) * inv;
                __nv_bfloat16 h0 = __float2bfloat16(v0), h1 = __float2bfloat16(v1);
                hw[q] = pack_bf2(h0, h1);
                lw[q] = pack_bf2(__float2bfloat16(v0 - __bfloat162float(h0)),
                                 __float2bfloat16(v1 - __bfloat162float(h1)));
            }
            *(uint4*)(outh + base + j8 * 8) = make_uint4(hw[0], hw[1], hw[2], hw[3]);
            *(uint4*)(outl + base + j8 * 8) = make_uint4(lw[0], lw[1], lw[2], lw[3]);
        }
    }
    __syncthreads();
    if (tid == 0) { MBARRIER_INVAL(ctrl + 8); MBARRIER_INVAL(ctrl + 16); }
    __syncthreads();
    if (wid == 0) TCGEN05_DEALLOC(tmem, 256);
#else
    if (tid < 128) {
        int r = q0 + tid;
        float qr[64], o[64], l = 0.0f;
        for (int d = 0; d < 64; d++) {
            qr[d] = __bfloat162float(qg[((size_t)(bh * SS + r)) * HD + d]);
            o[d] = 0.0f;
        }
        for (int key = 0; key < SS; key++) {
            if (!mask[b_ * SS + key]) continue;
            float s = 0.0f;
            const __nv_bfloat16* kp = kg + ((size_t)(bh * SS + key)) * HD;
            for (int d = 0; d < 64; d++) s += qr[d] * __bfloat162float(kp[d]);
            float pw = __expf(s * 0.125f);
            l += pw;
            const __nv_bfloat16* vp = vg + ((size_t)(bh * SS + key)) * HD;
            for (int d = 0; d < 64; d++) o[d] += pw * __bfloat162float(vp[d]);
        }
        float inv = 1.0f / l;
        for (int d = 0; d < 64; d++) {
            float v = o[d] * inv;
            __nv_bfloat16 h = __float2bfloat16(v);
            size_t idx = ((size_t)(b_ * SS + r)) * DD + h_ * HD + d;
            outh[idx] = h;
            outl[idx] = __float2bfloat16(v - __bfloat162float(h));
        }
    }
#endif
}

// ---------------- residual + bias + LN (optionally emits bf16 split) -------
template <bool SPLIT>
__global__ __launch_bounds__(256) void add_ln_kernel(
    const float* __restrict__ a, const float* __restrict__ b,
    const float* __restrict__ bias,
    const float* __restrict__ g, const float* __restrict__ be,
    float* __restrict__ out,
    __nv_bfloat16* __restrict__ oh, __nv_bfloat16* __restrict__ ol)
{
    __shared__ float sh[10];
    const int row = blockIdx.x;
    const int tid = threadIdx.x;
    const int wid = tid >> 5, lane = tid & 31;
    const size_t base = (size_t)row * DD + tid * 4;

    float4 av = *(const float4*)(a + base);
    float4 bv = *(const float4*)(b + base);
    float4 cv = *(const float4*)(bias + tid * 4);
    float4 t = make_float4(av.x + bv.x + cv.x, av.y + bv.y + cv.y,
                           av.z + bv.z + cv.z, av.w + bv.w + cv.w);
    float s = t.x + t.y + t.z + t.w;
#pragma unroll
    for (int off = 16; off >= 1; off >>= 1) s += __shfl_xor_sync(0xffffffffu, s, off);
    if (lane == 0) sh[wid] = s;
    __syncthreads();
    if (tid == 0) {
        float t2 = 0.f;
#pragma unroll
        for (int w = 0; w < 8; w++) t2 += sh[w];
        sh[8] = t2 * (1.0f / 1024.0f);
    }
    __syncthreads();
    float mu = sh[8];
    float dx = t.x - mu, dy = t.y - mu, dz = t.z - mu, dw = t.w - mu;
    float sq = dx * dx + dy * dy + dz * dz + dw * dw;
#pragma unroll
    for (int off = 16; off >= 1; off >>= 1) sq += __shfl_xor_sync(0xffffffffu, sq, off);
    if (lane == 0) sh[wid] = sq;
    __syncthreads();
    if (tid == 0) {
        float t2 = 0.f;
#pragma unroll
        for (int w = 0; w < 8; w++) t2 += sh[w];
        sh[9] = rsqrtf(t2 * (1.0f / 1024.0f) + 1e-5f);
    }
    __syncthreads();
    float inv = sh[9];
    float4 gv = *(const float4*)(g + tid * 4);
    float4 bev = *(const float4*)(be + tid * 4);
    float4 r = make_float4(dx * inv * gv.x + bev.x, dy * inv * gv.y + bev.y,
                           dz * inv * gv.z + bev.z, dw * inv * gv.w + bev.w);
    *(float4*)(out + base) = r;
    if (SPLIT) {
        __nv_bfloat16 h0 = __float2bfloat16(r.x), h1 = __float2bfloat16(r.y);
        __nv_bfloat16 h2 = __float2bfloat16(r.z), h3 = __float2bfloat16(r.w);
        *(uint2*)(oh + base) = make_uint2(pack_bf2(h0, h1), pack_bf2(h2, h3));
        *(uint2*)(ol + base) = make_uint2(
            pack_bf2(__float2bfloat16(r.x - __bfloat162float(h0)),
                     __float2bfloat16(r.y - __bfloat162float(h1))),
            pack_bf2(__float2bfloat16(r.z - __bfloat162float(h2)),
                     __float2bfloat16(r.w - __bfloat162float(h3))));
    }
}

// ---------------------------------------------------------------------------
extern "C" void kernel_launch(void* const* d_in, const int* in_sizes, int n_in,
                              void* d_out, int out_size)
{
    const float* x   = (const float*)d_in[0];
    const int*   msk = (const int*)d_in[1];
    const float* Wq  = (const float*)d_in[2];
    const float* bq  = (const float*)d_in[3];
    const float* Wk  = (const float*)d_in[4];
    const float* bk  = (const float*)d_in[5];
    const float* Wv  = (const float*)d_in[6];
    const float* bv  = (const float*)d_in[7];
    const float* Wo  = (const float*)d_in[8];
    const float* bo  = (const float*)d_in[9];
    const float* W1  = (const float*)d_in[10];
    const float* b1  = (const float*)d_in[11];
    const float* W2  = (const float*)d_in[12];
    const float* b2  = (const float*)d_in[13];
    const float* g1  = (const float*)d_in[14];
    const float* be1 = (const float*)d_in[15];
    const float* g2  = (const float*)d_in[16];
    const float* be2 = (const float*)d_in[17];
    float* out = (float*)d_out;

    __nv_bfloat16 *xh, *xl, *qh, *kh, *vh, *oh, *ol, *hb, *hl, *fh, *fl, *wh, *wl;
    float *f32a, *f32b, *f32c;
    cudaGetSymbolAddress((void**)&xh, g_xh);
    cudaGetSymbolAddress((void**)&xl, g_xl);
    cudaGetSymbolAddress((void**)&qh, g_qh);
    cudaGetSymbolAddress((void**)&kh, g_kh);
    cudaGetSymbolAddress((void**)&vh, g_vh);
    cudaGetSymbolAddress((void**)&oh, g_oh);
    cudaGetSymbolAddress((void**)&ol, g_ol);
    cudaGetSymbolAddress((void**)&hb, g_hb);
    cudaGetSymbolAddress((void**)&hl, g_hl);
    cudaGetSymbolAddress((void**)&fh, g_fh);
    cudaGetSymbolAddress((void**)&fl, g_fl);
    cudaGetSymbolAddress((void**)&wh, g_wh);
    cudaGetSymbolAddress((void**)&wl, g_wl);
    cudaGetSymbolAddress((void**)&f32a, g_f32a);
    cudaGetSymbolAddress((void**)&f32b, g_f32b);
    cudaGetSymbolAddress((void**)&f32c, g_f32c);

    cudaFuncSetAttribute(gemm_bf<0>, cudaFuncAttributeMaxDynamicSharedMemorySize, GEMM_SMEM_BYTES);
    cudaFuncSetAttribute(gemm_bf<1>, cudaFuncAttributeMaxDynamicSharedMemorySize, GEMM_SMEM_BYTES);
    cudaFuncSetAttribute(gemm_bf<2>, cudaFuncAttributeMaxDynamicSharedMemorySize, GEMM_SMEM_BYTES);
    cudaFuncSetAttribute(flash_tc_kernel, cudaFuncAttributeMaxDynamicSharedMemorySize, FL_SMEM);

    dim3 blk(256);
    dim3 pw(32, 8);

    // x -> bf16 hi/lo
    split_kernel<<<(size_t)MM * DD / 1024, blk>>>(x, xh, xl);

    // weights -> transposed bf16 hi/lo
    prep_w_kernel<<<dim3(DD / 32, DD / 32), pw>>>(Wq, wh + WQ_OFF, wl + WQ_OFF, DD, DD);
    prep_w_kernel<<<dim3(DD / 32, DD / 32), pw>>>(Wk, wh + WK_OFF, wl + WK_OFF, DD, DD);
    prep_w_kernel<<<dim3(DD / 32, DD / 32), pw>>>(Wv, wh + WV_OFF, wl + WV_OFF, DD, DD);
    prep_w_kernel<<<dim3(DD / 32, DD / 32), pw>>>(Wo, wh + WO_OFF, wl + WO_OFF, DD, DD);
    prep_w_kernel<<<dim3(FF / 32, DD / 32), pw>>>(W1, wh + W1_OFF, wl + W1_OFF, DD, FF);
    prep_w_kernel<<<dim3(DD / 32, FF / 32), pw>>>(W2, wh + W2_OFF, wl + W2_OFF, FF, DD);

    // QKV combined (N=3072) -> head-layout bf16 with bias
    gemm_bf<2><<<dim3(24, 64), blk, GEMM_SMEM_BYTES>>>(
        xh, xl, wh + WQ_OFF, wl + WQ_OFF,
        nullptr, nullptr, nullptr, qh, kh, vh, bq, bk, bv, MM, 3 * DD, DD);

    // flash attention -> token-layout bf16 hi/lo
    flash_tc_kernel<<<dim3(SS / 128, BB * HH), blk, FL_SMEM>>>(qh, kh, vh, msk, oh, ol);

    // O projection (fp32 out, bias folded into LN)
    gemm_bf<0><<<dim3(8, 64), blk, GEMM_SMEM_BYTES>>>(
        oh, ol, wh + WO_OFF, wl + WO_OFF,
        f32a, nullptr, nullptr, nullptr, nullptr, nullptr, nullptr, nullptr, nullptr,
        MM, DD, DD);

    // h = LN(x + o + bo): fp32 + bf16 split
    add_ln_kernel<true><<<MM, blk>>>(x, f32a, bo, g1, be1, f32b, hb, hl);

    // FFN1: relu(h W1 + b1) -> bf16 hi/lo
    gemm_bf<1><<<dim3(32, 64), blk, GEMM_SMEM_BYTES>>>(
        hb, hl, wh + W1_OFF, wl + W1_OFF,
        nullptr, fh, fl, nullptr, nullptr, nullptr, b1, nullptr, nullptr, MM, FF, DD);

    // FFN2 (fp32 out)
    gemm_bf<0><<<dim3(8, 64), blk, GEMM_SMEM_BYTES>>>(
        fh, fl, wh + W2_OFF, wl + W2_OFF,
        f32c, nullptr, nullptr, nullptr, nullptr, nullptr, nullptr, nullptr, nullptr,
        MM, DD, FF);

    // out = LN(h + ffn + b2)
    add_ln_kernel<false><<<MM, blk>>>(f32b, f32c, b2, g2, be2, out, nullptr, nullptr);
}

// round 10
// speedup vs baseline: 5.4009x; 1.0967x over previous
#include <cuda_runtime.h>
#include <cuda_bf16.h>
#include <math.h>
#include <stdint.h>

constexpr int BB = 4;
constexpr int SS = 2048;
constexpr int DD = 1024;
constexpr int HH = 16;
constexpr int HD = 64;
constexpr int FF = 4096;
constexpr int MM = BB * SS;

#if defined(__CUDA_ARCH_FEAT_SM103_ALL) || defined(__CUDA_ARCH_FEAT_SM100_ALL)
#define HAS_TCGEN05 1
#else
#define HAS_TCGEN05 0
#endif

// ---------------- device scratch ----------------
__device__ __nv_bfloat16 g_xh[(size_t)MM * DD];
__device__ __nv_bfloat16 g_xl[(size_t)MM * DD];
__device__ __nv_bfloat16 g_qh[(size_t)MM * DD];
__device__ __nv_bfloat16 g_kh[(size_t)MM * DD];
__device__ __nv_bfloat16 g_vh[(size_t)MM * DD];
__device__ __nv_bfloat16 g_oh[(size_t)MM * DD];
__device__ __nv_bfloat16 g_ol[(size_t)MM * DD];
__device__ __nv_bfloat16 g_hb[(size_t)MM * DD];
__device__ __nv_bfloat16 g_hl[(size_t)MM * DD];
__device__ __nv_bfloat16 g_fh[(size_t)MM * FF];
__device__ __nv_bfloat16 g_fl[(size_t)MM * FF];
__device__ float g_f32a[(size_t)MM * DD];
__device__ float g_f32b[(size_t)MM * DD];
__device__ float g_f32c[(size_t)MM * DD];

constexpr size_t WQ_OFF = 0;
constexpr size_t WK_OFF = 1048576;
constexpr size_t WV_OFF = 2097152;
constexpr size_t WO_OFF = 3145728;
constexpr size_t W1_OFF = 4194304;
constexpr size_t W2_OFF = 8388608;
constexpr size_t WTOT   = 12582912;
__device__ __nv_bfloat16 g_wh[WTOT];
__device__ __nv_bfloat16 g_wl[WTOT];

// ---------------- helpers ----------------
__device__ __forceinline__ uint32_t smem_u32(const void* p) {
    uint32_t a;
    asm("{ .reg .u64 t; cvta.to.shared.u64 t, %1; cvt.u32.u64 %0, t; }" : "=r"(a) : "l"(p));
    return a;
}
__device__ __forceinline__ uint32_t swz128(uint32_t off) { return off ^ ((off >> 3) & 0x70); }
__device__ __forceinline__ uint32_t pack_bf2(__nv_bfloat16 a, __nv_bfloat16 b) {
    __nv_bfloat162 t; t.x = a; t.y = b; return *(uint32_t*)&t;
}
#define CP_ASYNC16(saddr, gptr) \
    asm volatile("cp.async.cg.shared.global [%0], [%1], 16;" \
        :: "r"((uint32_t)(saddr)), "l"(gptr) : "memory")
#define CP_COMMIT() asm volatile("cp.async.commit_group;" ::: "memory")
#define CP_WAIT(n)  asm volatile("cp.async.wait_group %0;" :: "n"(n) : "memory")

#if HAS_TCGEN05
__device__ __forceinline__ uint32_t elect_one_pred() {
    uint32_t pred;
    asm volatile("{\n\t.reg .pred p;\n\telect.sync _|p, 0xFFFFFFFF;\n\tselp.b32 %0, 1, 0, p;\n\t}" : "=r"(pred));
    return pred;
}
#define TCGEN05_ALLOC(smem_addr, nCols) \
    asm volatile("tcgen05.alloc.cta_group::1.sync.aligned.shared::cta.b32 [%0], %1;" \
        :: "r"((uint32_t)(smem_addr)), "r"((uint32_t)(nCols)) : "memory")
#define TCGEN05_DEALLOC(tmem_addr, nCols) \
    asm volatile("tcgen05.dealloc.cta_group::1.sync.aligned.b32 %0, %1;" \
        :: "r"(tmem_addr), "r"((uint32_t)(nCols)))
#define TCGEN05_COMMIT(mbar) \
    asm volatile("tcgen05.commit.cta_group::1.mbarrier::arrive::one.shared::cluster.b64 [%0];" \
        :: "r"((uint32_t)(mbar)) : "memory")
#define TCGEN05_WAIT_LD()  asm volatile("tcgen05.wait::ld.sync.aligned;" ::: "memory")
#define TCGEN05_FENCE_BEFORE() asm volatile("tcgen05.fence::before_thread_sync;" ::: "memory")
#define TCGEN05_FENCE_AFTER()  asm volatile("tcgen05.fence::after_thread_sync;" ::: "memory")
#define FENCE_ASYNC_SHARED() asm volatile("fence.proxy.async.shared::cta;" ::: "memory")
#define MBARRIER_INIT(mbar, cnt) \
    asm volatile("mbarrier.init.shared.b64 [%0], %1;" :: "r"((uint32_t)(mbar)), "r"((uint32_t)(cnt)) : "memory")
#define MBARRIER_INVAL(mbar) \
    asm volatile("mbarrier.inval.shared.b64 [%0];" :: "r"((uint32_t)(mbar)) : "memory")
#define MBARRIER_WAIT_PARITY(mbar, parity) do {                                    \
    uint32_t _mb = (uint32_t)(mbar);                                               \
    uint32_t _pa = (uint32_t)(parity);                                             \
    uint32_t _done;                                                                \
    asm volatile(                                                                  \
        "{\n\t.reg .pred p;\n\t"                                                   \
        "mbarrier.try_wait.parity.acquire.cta.shared::cta.b64 p, [%1], %2;\n\t"    \
        "selp.b32 %0, 1, 0, p;\n\t}"                                               \
        : "=r"(_done) : "r"(_mb), "r"(_pa) : "memory");                            \
    if (!_done) {                                                                  \
        asm volatile(                                                              \
            "{\n\t.reg .pred P1;\n\t"                                              \
            "WL_%=:\n\t"                                                           \
            "mbarrier.try_wait.parity.acquire.cta.shared::cta.b64 P1, [%0], %1, 0x989680;\n\t" \
            "@P1 bra.uni WD_%=;\n\t"                                               \
            "bra.uni WL_%=;\n\t"                                                   \
            "WD_%=:\n\t}"                                                          \
            :: "r"(_mb), "r"(_pa) : "memory");                                     \
    }                                                                              \
} while (0)
#define TCGEN05_LD_X32(r, addr) \
    asm volatile( \
        "tcgen05.ld.sync.aligned.32x32b.x32.b32 " \
        "{%0, %1, %2, %3, %4, %5, %6, %7, " \
        " %8, %9, %10, %11, %12, %13, %14, %15, " \
        " %16, %17, %18, %19, %20, %21, %22, %23, " \
        " %24, %25, %26, %27, %28, %29, %30, %31}, [%32];" \
        : "=r"((r)[0]),  "=r"((r)[1]),  "=r"((r)[2]),  "=r"((r)[3]), \
          "=r"((r)[4]),  "=r"((r)[5]),  "=r"((r)[6]),  "=r"((r)[7]), \
          "=r"((r)[8]),  "=r"((r)[9]),  "=r"((r)[10]), "=r"((r)[11]), \
          "=r"((r)[12]), "=r"((r)[13]), "=r"((r)[14]), "=r"((r)[15]), \
          "=r"((r)[16]), "=r"((r)[17]), "=r"((r)[18]), "=r"((r)[19]), \
          "=r"((r)[20]), "=r"((r)[21]), "=r"((r)[22]), "=r"((r)[23]), \
          "=r"((r)[24]), "=r"((r)[25]), "=r"((r)[26]), "=r"((r)[27]), \
          "=r"((r)[28]), "=r"((r)[29]), "=r"((r)[30]), "=r"((r)[31]) \
        : "r"(addr))

__device__ __forceinline__ uint64_t make_desc_sw128(uint32_t addr) {
    constexpr uint64_t BASE =
        (uint64_t(2) << 61) | (uint64_t(1) << 46) | (uint64_t(64) << 32) | (uint64_t(1) << 16);
    return BASE | ((uint64_t)(addr >> 4) & 0x3FFF);
}
__device__ __forceinline__ void mma_bf16_ss(uint32_t d, uint64_t ad, uint64_t bd,
                                            uint32_t idesc, bool acc) {
    uint32_t en = acc ? 1u : 0u;
    asm volatile(
        "{\n\t.reg .pred p;\n\t"
        "setp.ne.u32 p, %5, 0;\n\t"
        "tcgen05.mma.cta_group::1.kind::f16 [%0], %1, %2, %3, {%4, %4, %4, %4}, p;\n\t}"
        :: "r"(d), "l"(ad), "l"(bd), "r"(idesc), "r"(0u), "r"(en) : "memory");
}
#endif

constexpr uint32_t GEMM_IDESC =
    (1u << 4) | (1u << 7) | (1u << 10) | ((128 / 8) << 17) | ((128 / 16) << 24);
constexpr uint32_t IDESC_N64 =
    (1u << 4) | (1u << 7) | (1u << 10) | ((64 / 8) << 17) | ((128 / 16) << 24);

// ---------------- weight prep ----------------
__global__ void prep_w_kernel(const float* __restrict__ W,
                              __nv_bfloat16* __restrict__ Bh,
                              __nv_bfloat16* __restrict__ Bl, int K, int N)
{
    __shared__ float t[32][33];
    const int n0 = blockIdx.x * 32, k0 = blockIdx.y * 32;
#pragma unroll
    for (int i = 0; i < 4; i++)
        t[threadIdx.y + i * 8][threadIdx.x] =
            W[(size_t)(k0 + threadIdx.y + i * 8) * N + n0 + threadIdx.x];
    __syncthreads();
#pragma unroll
    for (int i = 0; i < 4; i++) {
        int n = threadIdx.y + i * 8;
        float v = t[threadIdx.x][n];
        __nv_bfloat16 h = __float2bfloat16(v);
        size_t idx = (size_t)(n0 + n) * K + k0 + threadIdx.x;
        Bh[idx] = h;
        Bl[idx] = __float2bfloat16(v - __bfloat162float(h));
    }
}

// fp32 -> bf16 hi/lo split
__global__ __launch_bounds__(256) void split_kernel(
    const float* __restrict__ in,
    __nv_bfloat16* __restrict__ oh, __nv_bfloat16* __restrict__ ol)
{
    size_t i = ((size_t)blockIdx.x * 256 + threadIdx.x) * 4;
    float4 v = *(const float4*)(in + i);
    __nv_bfloat16 h0 = __float2bfloat16(v.x), h1 = __float2bfloat16(v.y);
    __nv_bfloat16 h2 = __float2bfloat16(v.z), h3 = __float2bfloat16(v.w);
    *(uint2*)(oh + i) = make_uint2(pack_bf2(h0, h1), pack_bf2(h2, h3));
    *(uint2*)(ol + i) = make_uint2(
        pack_bf2(__float2bfloat16(v.x - __bfloat162float(h0)),
                 __float2bfloat16(v.y - __bfloat162float(h1))),
        pack_bf2(__float2bfloat16(v.z - __bfloat162float(h2)),
                 __float2bfloat16(v.w - __bfloat162float(h3))));
}

// ---------------------------------------------------------------------------
// GEMM: C[M,N] = (Ah+Al) @ (Bh+Bl)^T, bf16 K-major, 256x128 CTA tile
// (two sequential M=128 MMA tiles -> TMEM cols 0 and 128), 2-stage cp.async.
// Stage layout (96KB): Ah 32K (256 rows) | Al 32K | Bh 16K | Bl 16K
// EPI 0: fp32 out.  EPI 1: relu+bias -> hi/lo bf16.  EPI 2: QKV head scatter.
// ---------------------------------------------------------------------------
constexpr int GEMM_STAGE = 98304;
constexpr int GEMM_SMEM_BYTES = 2 * GEMM_STAGE + 1024;

template <int EPI>
__global__ __launch_bounds__(256, 1) void gemm_bf(
    const __nv_bfloat16* __restrict__ Ah, const __nv_bfloat16* __restrict__ Al,
    const __nv_bfloat16* __restrict__ Bh, const __nv_bfloat16* __restrict__ Bl,
    float* __restrict__ Cf, __nv_bfloat16* __restrict__ Ch, __nv_bfloat16* __restrict__ Cl,
    __nv_bfloat16* __restrict__ D0, __nv_bfloat16* __restrict__ D1, __nv_bfloat16* __restrict__ D2,
    const float* __restrict__ bias0, const float* __restrict__ bias1, const float* __restrict__ bias2,
    int M, int N, int K)
{
    extern __shared__ char dsmem[];
    uintptr_t p = ((uintptr_t)dsmem + 1023) & ~(uintptr_t)1023;
    char* buf = (char*)p;
    const int tid = threadIdx.x;
    const int wid = tid >> 5;
    const int lane = tid & 31;
    const int m0 = blockIdx.y << 8;   // 256-row tile
    const int n0 = blockIdx.x << 7;   // 128-col tile

#if HAS_TCGEN05
    __shared__ alignas(16) unsigned long long ctrlq[4];
    const uint32_t sbuf = smem_u32(buf);
    const uint32_t ctrl = smem_u32(ctrlq);

    if (wid == 0) TCGEN05_ALLOC(ctrl, 256);
    if (tid == 0) {
        MBARRIER_INIT(ctrl + 8, 1);    // stage 0 mma done
        MBARRIER_INIT(ctrl + 16, 1);   // stage 1 mma done
        MBARRIER_INIT(ctrl + 24, 1);   // final
    }
    __syncthreads();
    uint32_t tmem;
    asm volatile("ld.shared.b32 %0, [%1];" : "=r"(tmem) : "r"(ctrl));

    const int NC = K >> 6;

    auto load_chunk = [&](int ck, int st) {
        const uint32_t sb = sbuf + (uint32_t)st * GEMM_STAGE;
        const int k0 = ck << 6;
        // A hi/lo: 256 rows x 8 groups = 2048 units each
#pragma unroll
        for (int j = 0; j < 8; j++) {
            int u = tid + j * 256;
            int r = u >> 3, g = u & 7;
            uint32_t so = swz128((uint32_t)(r * 128 + g * 16));
            size_t ao = (size_t)(m0 + r) * K + k0 + g * 8;
            CP_ASYNC16(sb + so,         Ah + ao);
            CP_ASYNC16(sb + 32768 + so, Al + ao);
        }
        // B hi/lo: 128 rows x 8 groups = 1024 units each
#pragma unroll
        for (int j = 0; j < 4; j++) {
            int u = tid + j * 256;
            int r = u >> 3, g = u & 7;
            uint32_t so = swz128((uint32_t)(r * 128 + g * 16));
            size_t bo = (size_t)(n0 + r) * K + k0 + g * 8;
            CP_ASYNC16(sb + 65536 + so, Bh + bo);
            CP_ASYNC16(sb + 81920 + so, Bl + bo);
        }
    };

    load_chunk(0, 0);
    CP_COMMIT();
    load_chunk(1, 1);
    CP_COMMIT();

    int ph[2] = {0, 0};

    for (int i = 0; i < NC; i++) {
        const int st = i & 1;
        if (i < NC - 1) CP_WAIT(1);
        else            CP_WAIT(0);
        __syncthreads();
        FENCE_ASYNC_SHARED();

        if (wid == 0 && elect_one_pred()) {
            const uint32_t sb = sbuf + (uint32_t)st * GEMM_STAGE;
            uint64_t dBh = make_desc_sw128(sb + 65536);
            uint64_t dBl = make_desc_sw128(sb + 81920);
#pragma unroll
            for (int mt = 0; mt < 2; mt++) {
                uint64_t dAh = make_desc_sw128(sb + mt * 16384);
                uint64_t dAl = make_desc_sw128(sb + 32768 + mt * 16384);
                uint32_t dst = tmem + mt * 128;
#pragma unroll
                for (int ks = 0; ks < 4; ks++)
                    mma_bf16_ss(dst, dAh + ks * 2, dBh + ks * 2, GEMM_IDESC, !(i == 0 && ks == 0));
#pragma unroll
                for (int ks = 0; ks < 4; ks++)
                    mma_bf16_ss(dst, dAl + ks * 2, dBh + ks * 2, GEMM_IDESC, true);
#pragma unroll
                for (int ks = 0; ks < 4; ks++)
                    mma_bf16_ss(dst, dAh + ks * 2, dBl + ks * 2, GEMM_IDESC, true);
            }
            TCGEN05_COMMIT(ctrl + 8 + st * 8);
        }

        if (i + 2 < NC) {
            MBARRIER_WAIT_PARITY(ctrl + 8 + st * 8, ph[st]);
            ph[st] ^= 1;
            load_chunk(i + 2, st);
            CP_COMMIT();
        }
    }

    if (wid == 0 && elect_one_pred()) TCGEN05_COMMIT(ctrl + 24);
    MBARRIER_WAIT_PARITY(ctrl + 24, 0);
    TCGEN05_FENCE_AFTER();

    // epilogue: 8 warps; per mt tile: sp = row group, chf = 64-col half
    {
        const int sp = wid & 3;
        const int chf = wid >> 2;
#pragma unroll
        for (int mt = 0; mt < 2; mt++) {
            uint32_t r[64];
            TCGEN05_LD_X32(r, tmem + mt * 128 + chf * 64);
            TCGEN05_LD_X32(r + 32, tmem + mt * 128 + chf * 64 + 32);
            TCGEN05_WAIT_LD();
            TCGEN05_FENCE_BEFORE();

            const int row = m0 + mt * 128 + sp * 32 + lane;
            const int c0 = n0 + chf * 64;

            if (EPI == 0) {
                float* cp = Cf + (size_t)row * N + c0;
#pragma unroll
                for (int c = 0; c < 16; c++) {
                    float4 v;
                    v.x = __uint_as_float(r[4 * c + 0]);
                    v.y = __uint_as_float(r[4 * c + 1]);
                    v.z = __uint_as_float(r[4 * c + 2]);
                    v.w = __uint_as_float(r[4 * c + 3]);
                    *(float4*)(cp + 4 * c) = v;
                }
            } else if (EPI == 1) {
                size_t base = (size_t)row * N + c0;
#pragma unroll
                for (int j8 = 0; j8 < 8; j8++) {
                    uint32_t hw[4], lw[4];
#pragma unroll
                    for (int q = 0; q < 4; q++) {
                        int j = j8 * 8 + q * 2;
                        float v0 = fmaxf(__uint_as_float(r[j])     + bias0[c0 + j],     0.0f);
                        float v1 = fmaxf(__uint_as_float(r[j + 1]) + bias0[c0 + j + 1], 0.0f);
                        __nv_bfloat16 h0 = __float2bfloat16(v0), h1 = __float2bfloat16(v1);
                        hw[q] = pack_bf2(h0, h1);
                        lw[q] = pack_bf2(__float2bfloat16(v0 - __bfloat162float(h0)),
                                         __float2bfloat16(v1 - __bfloat162float(h1)));
                    }
                    *(uint4*)(Ch + base + j8 * 8) = make_uint4(hw[0], hw[1], hw[2], hw[3]);
                    *(uint4*)(Cl + base + j8 * 8) = make_uint4(lw[0], lw[1], lw[2], lw[3]);
                }
            } else {  // EPI == 2: QKV -> head layout bf16
                const int mat = c0 >> 10;
                const int lc = c0 & 1023;
                const float* bs = (mat == 0) ? bias0 : (mat == 1) ? bias1 : bias2;
                __nv_bfloat16* Dd = (mat == 0) ? D0 : (mat == 1) ? D1 : D2;
                const int h_ = lc >> 6;
                const int b_ = row >> 11;
                const int s_ = row & (SS - 1);
                size_t base = (((size_t)b_ * HH + h_) * SS + s_) * HD;
#pragma unroll
                for (int j8 = 0; j8 < 8; j8++) {
                    uint32_t hw[4];
#pragma unroll
                    for (int q = 0; q < 4; q++) {
                        int j = j8 * 8 + q * 2;
                        float v0 = __uint_as_float(r[j])     + bs[lc + j];
                        float v1 = __uint_as_float(r[j + 1]) + bs[lc + j + 1];
                        hw[q] = pack_bf2(__float2bfloat16(v0), __float2bfloat16(v1));
                    }
                    *(uint4*)(Dd + base + j8 * 8) = make_uint4(hw[0], hw[1], hw[2], hw[3]);
                }
            }
        }
    }

    __syncthreads();
    if (tid == 0) {
        MBARRIER_INVAL(ctrl + 8);
        MBARRIER_INVAL(ctrl + 16);
        MBARRIER_INVAL(ctrl + 24);
    }
    __syncthreads();
    if (wid == 0) TCGEN05_DEALLOC(tmem, 256);

#else  // ---------------- FFMA fallback ----------------
    float* As = (float*)buf;
    float* Bs = As + 16 * 132;
    const int tx = tid & 15, ty = tid >> 4;
    for (int mt = 0; mt < 2; mt++) {
        const int mb = m0 + mt * 128;
        float acc[8][8];
#pragma unroll
        for (int i = 0; i < 8; i++)
#pragma unroll
            for (int j = 0; j < 8; j++) acc[i][j] = 0.0f;
        for (int k0 = 0; k0 < K; k0 += 16) {
            for (int it = 0; it < 8; it++) {
                int idx = tid + it * 256;
                int rr = idx >> 4, kk = idx & 15;
                As[kk * 132 + rr] =
                    __bfloat162float(Ah[(size_t)(mb + rr) * K + k0 + kk]) +
                    __bfloat162float(Al[(size_t)(mb + rr) * K + k0 + kk]);
                Bs[kk * 132 + rr] =
                    __bfloat162float(Bh[(size_t)(n0 + rr) * K + k0 + kk]) +
                    __bfloat162float(Bl[(size_t)(n0 + rr) * K + k0 + kk]);
            }
            __syncthreads();
#pragma unroll
            for (int k = 0; k < 16; k++) {
                float a[8], bb[8];
#pragma unroll
                for (int i = 0; i < 8; i++) a[i] = As[k * 132 + ty * 8 + i];
#pragma unroll
                for (int j = 0; j < 8; j++) bb[j] = Bs[k * 132 + tx * 8 + j];
#pragma unroll
                for (int i = 0; i < 8; i++)
#pragma unroll
                    for (int j = 0; j < 8; j++) acc[i][j] = fmaf(a[i], bb[j], acc[i][j]);
            }
            __syncthreads();
        }
#pragma unroll
        for (int i = 0; i < 8; i++) {
            int row = mb + ty * 8 + i;
#pragma unroll
            for (int j = 0; j < 8; j++) {
                int col = n0 + tx * 8 + j;
                float v = acc[i][j];
                if (EPI == 0) {
                    Cf[(size_t)row * N + col] = v;
                } else if (EPI == 1) {
                    v = fmaxf(v + bias0[col], 0.0f);
                    __nv_bfloat16 h = __float2bfloat16(v);
                    Ch[(size_t)row * N + col] = h;
                    Cl[(size_t)row * N + col] = __float2bfloat16(v - __bfloat162float(h));
                } else {
                    int mat = col >> 10, lc = col & 1023;
                    const float* bs = (mat == 0) ? bias0 : (mat == 1) ? bias1 : bias2;
                    __nv_bfloat16* Dd = (mat == 0) ? D0 : (mat == 1) ? D1 : D2;
                    float vv = v + bs[lc];
                    int h_ = lc >> 6, d = lc & 63;
                    int b_ = row >> 11, s_ = row & (SS - 1);
                    Dd[(((size_t)b_ * HH + h_) * SS + s_) * HD + d] = __float2bfloat16(vv);
                }
            }
        }
        __syncthreads();
    }
#endif
}

// ---------------- tcgen05 flash attention (proven) ----------------
constexpr int FL_Q = 0, FL_K = 16384, FL_VT = 32768, FL_P = 49152, FL_CT = 81920;
constexpr int FL_SMEM = FL_CT + 2048 + 1024;

__global__ __launch_bounds__(256, 2) void flash_tc_kernel(
    const __nv_bfloat16* __restrict__ qg, const __nv_bfloat16* __restrict__ kg,
    const __nv_bfloat16* __restrict__ vg, const int* __restrict__ mask,
    __nv_bfloat16* __restrict__ outh, __nv_bfloat16* __restrict__ outl)
{
    extern __shared__ char dsmem[];
    uintptr_t pb = ((uintptr_t)dsmem + 1023) & ~(uintptr_t)1023;
    char* buf = (char*)pb;
    const int tid = threadIdx.x;
    const int wid = tid >> 5;
    const int lane = tid & 31;
    const int bh = blockIdx.y;
    const int b_ = bh >> 4;
    const int h_ = bh & (HH - 1);
    const int q0 = blockIdx.x * 128;

#if HAS_TCGEN05
    const int sp = wid & 3;
    const int chf = wid >> 2;
    const uint32_t sbuf = smem_u32(buf);
    const uint32_t ctrl = sbuf + FL_CT;
    int* msk_s = (int*)(buf + FL_CT + 32);
    float* lpart = (float*)(buf + FL_CT + 544);

    if (wid == 0) TCGEN05_ALLOC(ctrl, 256);
    if (tid == 0) { MBARRIER_INIT(ctrl + 8, 1); MBARRIER_INIT(ctrl + 16, 1); }
    __syncthreads();
    uint32_t tmem;
    asm volatile("ld.shared.b32 %0, [%1];" : "=r"(tmem) : "r"(ctrl));

    {
        int r = tid >> 1, half = (tid & 1) * 32;
        const __nv_bfloat16* qp = qg + ((size_t)(bh * SS + q0 + r)) * HD + half;
#pragma unroll
        for (int j = 0; j < 4; j++)
            *(uint4*)(buf + FL_Q + swz128((uint32_t)(r * 128 + half * 2 + j * 16))) =
                *(const uint4*)(qp + j * 8);
    }

    const uint64_t dQ  = make_desc_sw128(sbuf + FL_Q);
    const uint64_t dK  = make_desc_sw128(sbuf + FL_K);
    const uint64_t dP  = make_desc_sw128(sbuf + FL_P);
    const uint64_t dVT = make_desc_sw128(sbuf + FL_VT);
    const int pOff[8] = {0, 2, 4, 6, 1024, 1026, 1028, 1030};
    const int vOff[8] = {0, 2, 4, 6, 512, 514, 516, 518};

    float lsum = 0.0f;
    int phS = 0, phO = 0;

    for (int kbk = 0; kbk < SS / 128; kbk++) {
        if (kbk > 0) { MBARRIER_WAIT_PARITY(ctrl + 16, phO); phO ^= 1; }
        {
            int r = tid >> 1, half = (tid & 1) * 32;
            const __nv_bfloat16* kp = kg + ((size_t)(bh * SS + kbk * 128 + r)) * HD + half;
#pragma unroll
            for (int j = 0; j < 4; j++)
                *(uint4*)(buf + FL_K + swz128((uint32_t)(r * 128 + half * 2 + j * 16))) =
                    *(const uint4*)(kp + j * 8);
        }
#pragma unroll
        for (int j = 0; j < 4; j++) {
            int u = tid + j * 256;
            int k0 = (u & 63) * 2, d0 = (u >> 6) * 4;
            const __nv_bfloat16* vp = vg + ((size_t)(bh * SS + kbk * 128 + k0)) * HD + d0;
            uint2 a = *(const uint2*)vp;
            uint2 b = *(const uint2*)(vp + HD);
            __nv_bfloat162 A0 = *(__nv_bfloat162*)&a.x, A1 = *(__nv_bfloat162*)&a.y;
            __nv_bfloat162 B0 = *(__nv_bfloat162*)&b.x, B1 = *(__nv_bfloat162*)&b.y;
            int ac = k0 >> 6, cb = (k0 & 63) * 2;
#pragma unroll
            for (int dd = 0; dd < 4; dd++) {
                __nv_bfloat16 va = (dd == 0) ? A0.x : (dd == 1) ? A0.y : (dd == 2) ? A1.x : A1.y;
                __nv_bfloat16 vbq = (dd == 0) ? B0.x : (dd == 1) ? B0.y : (dd == 2) ? B1.x : B1.y;
                int d = d0 + dd;
                uint32_t o = (uint32_t)((ac * 8 + (d >> 3)) * 1024 + (d & 7) * 128 + cb);
                *(uint32_t*)(buf + FL_VT + swz128(o)) = pack_bf2(va, vbq);
            }
        }
        if (tid < 128) msk_s[tid] = mask[b_ * SS + kbk * 128 + tid];
        FENCE_ASYNC_SHARED();
        __syncthreads();

        if (wid == 0 && elect_one_pred()) {
#pragma unroll
            for (int s = 0; s < 4; s++)
                mma_bf16_ss(tmem, dQ + s * 2, dK + s * 2, GEMM_IDESC, s != 0);
            TCGEN05_COMMIT(ctrl + 8);
        }
        MBARRIER_WAIT_PARITY(ctrl + 8, phS);
        phS ^= 1;
        TCGEN05_FENCE_AFTER();

        const int r = sp * 32 + lane;
#pragma unroll
        for (int h2 = 0; h2 < 2; h2++) {
            uint32_t sr[32];
            TCGEN05_LD_X32(sr, tmem + chf * 64 + h2 * 32);
            TCGEN05_WAIT_LD();
            const int cbase = chf * 64 + h2 * 32;
            uint32_t ppk[16];
#pragma unroll
            for (int j = 0; j < 16; j++) {
                float p0 = msk_s[cbase + 2 * j]     ? __expf(__uint_as_float(sr[2 * j])     * 0.125f) : 0.0f;
                float p1 = msk_s[cbase + 2 * j + 1] ? __expf(__uint_as_float(sr[2 * j + 1]) * 0.125f) : 0.0f;
                __nv_bfloat16 bp0 = __float2bfloat16(p0), bp1 = __float2bfloat16(p1);
                ppk[j] = pack_bf2(bp0, bp1);
                lsum += __bfloat162float(bp0) + __bfloat162float(bp1);
            }
            uint32_t pbo = (uint32_t)((chf * 16 + (r >> 3)) * 1024 + (r & 7) * 128 + h2 * 64);
#pragma unroll
            for (int j = 0; j < 4; j++)
                *(uint4*)(buf + FL_P + swz128(pbo + j * 16)) =
                    make_uint4(ppk[4 * j], ppk[4 * j + 1], ppk[4 * j + 2], ppk[4 * j + 3]);
        }
        TCGEN05_FENCE_BEFORE();
        FENCE_ASYNC_SHARED();
        __syncthreads();

        if (wid == 0 && elect_one_pred()) {
#pragma unroll
            for (int s = 0; s < 8; s++)
                mma_bf16_ss(tmem + 128, dP + pOff[s], dVT + vOff[s], IDESC_N64,
                            !(kbk == 0 && s == 0));
            TCGEN05_COMMIT(ctrl + 16);
        }
    }

    MBARRIER_WAIT_PARITY(ctrl + 16, phO);
    TCGEN05_FENCE_AFTER();
    lpart[chf * 128 + sp * 32 + lane] = lsum;
    __syncthreads();

    if (wid < 4) {
        uint32_t orr[64];
        TCGEN05_LD_X32(orr, tmem + 128);
        TCGEN05_LD_X32(orr + 32, tmem + 160);
        TCGEN05_WAIT_LD();
        TCGEN05_FENCE_BEFORE();
        const int r = sp * 32 + lane;
        float inv = 1.0f / (lpart[r] + lpart[128 + r]);
        size_t base = ((size_t)(b_ * SS + q0 + r)) * DD + h_ * HD;
#pragma unroll
        for (int j8 = 0; j8 < 8; j8++) {
            uint32_t hw[4], lw[4];
#pragma unroll
            for (int q = 0; q < 4; q++) {
                int j = j8 * 8 + q * 2;
                float v0 = __uint_as_float(orr[j])     * inv;
                float v1 = __uint_as_float(orr[j + 1]) * inv;
                __nv_bfloat16 h0 = __float2bfloat16(v0), h1 = __float2bfloat16(v1);
                hw[q] = pack_bf2(h0, h1);
                lw[q] = pack_bf2(__float2bfloat16(v0 - __bfloat162float(h0)),
                                 __float2bfloat16(v1 - __bfloat162float(h1)));
            }
            *(uint4*)(outh + base + j8 * 8) = make_uint4(hw[0], hw[1], hw[2], hw[3]);
            *(uint4*)(outl + base + j8 * 8) = make_uint4(lw[0], lw[1], lw[2], lw[3]);
        }
    }
    __syncthreads();
    if (tid == 0) { MBARRIER_INVAL(ctrl + 8); MBARRIER_INVAL(ctrl + 16); }
    __syncthreads();
    if (wid == 0) TCGEN05_DEALLOC(tmem, 256);
#else
    if (tid < 128) {
        int r = q0 + tid;
        float qr[64], o[64], l = 0.0f;
        for (int d = 0; d < 64; d++) {
            qr[d] = __bfloat162float(qg[((size_t)(bh * SS + r)) * HD + d]);
            o[d] = 0.0f;
        }
        for (int key = 0; key < SS; key++) {
            if (!mask[b_ * SS + key]) continue;
            float s = 0.0f;
            const __nv_bfloat16* kp = kg + ((size_t)(bh * SS + key)) * HD;
            for (int d = 0; d < 64; d++) s += qr[d] * __bfloat162float(kp[d]);
            float pw = __expf(s * 0.125f);
            l += pw;
            const __nv_bfloat16* vp = vg + ((size_t)(bh * SS + key)) * HD;
            for (int d = 0; d < 64; d++) o[d] += pw * __bfloat162float(vp[d]);
        }
        float inv = 1.0f / l;
        for (int d = 0; d < 64; d++) {
            float v = o[d] * inv;
            __nv_bfloat16 h = __float2bfloat16(v);
            size_t idx = ((size_t)(b_ * SS + r)) * DD + h_ * HD + d;
            outh[idx] = h;
            outl[idx] = __float2bfloat16(v - __bfloat162float(h));
        }
    }
#endif
}

// ---------------- residual + bias + LN ----------------
template <bool SPLIT>
__global__ __launch_bounds__(256) void add_ln_kernel(
    const float* __restrict__ a, const float* __restrict__ b,
    const float* __restrict__ bias,
    const float* __restrict__ g, const float* __restrict__ be,
    float* __restrict__ out,
    __nv_bfloat16* __restrict__ oh, __nv_bfloat16* __restrict__ ol)
{
    __shared__ float sh[10];
    const int row = blockIdx.x;
    const int tid = threadIdx.x;
    const int wid = tid >> 5, lane = tid & 31;
    const size_t base = (size_t)row * DD + tid * 4;

    float4 av = *(const float4*)(a + base);
    float4 bv = *(const float4*)(b + base);
    float4 cv = *(const float4*)(bias + tid * 4);
    float4 t = make_float4(av.x + bv.x + cv.x, av.y + bv.y + cv.y,
                           av.z + bv.z + cv.z, av.w + bv.w + cv.w);
    float s = t.x + t.y + t.z + t.w;
#pragma unroll
    for (int off = 16; off >= 1; off >>= 1) s += __shfl_xor_sync(0xffffffffu, s, off);
    if (lane == 0) sh[wid] = s;
    __syncthreads();
    if (tid == 0) {
        float t2 = 0.f;
#pragma unroll
        for (int w = 0; w < 8; w++) t2 += sh[w];
        sh[8] = t2 * (1.0f / 1024.0f);
    }
    __syncthreads();
    float mu = sh[8];
    float dx = t.x - mu, dy = t.y - mu, dz = t.z - mu, dw = t.w - mu;
    float sq = dx * dx + dy * dy + dz * dz + dw * dw;
#pragma unroll
    for (int off = 16; off >= 1; off >>= 1) sq += __shfl_xor_sync(0xffffffffu, sq, off);
    if (lane == 0) sh[wid] = sq;
    __syncthreads();
    if (tid == 0) {
        float t2 = 0.f;
#pragma unroll
        for (int w = 0; w < 8; w++) t2 += sh[w];
        sh[9] = rsqrtf(t2 * (1.0f / 1024.0f) + 1e-5f);
    }
    __syncthreads();
    float inv = sh[9];
    float4 gv = *(const float4*)(g + tid * 4);
    float4 bev = *(const float4*)(be + tid * 4);
    float4 r = make_float4(dx * inv * gv.x + bev.x, dy * inv * gv.y + bev.y,
                           dz * inv * gv.z + bev.z, dw * inv * gv.w + bev.w);
    *(float4*)(out + base) = r;
    if (SPLIT) {
        __nv_bfloat16 h0 = __float2bfloat16(r.x), h1 = __float2bfloat16(r.y);
        __nv_bfloat16 h2 = __float2bfloat16(r.z), h3 = __float2bfloat16(r.w);
        *(uint2*)(oh + base) = make_uint2(pack_bf2(h0, h1), pack_bf2(h2, h3));
        *(uint2*)(ol + base) = make_uint2(
            pack_bf2(__float2bfloat16(r.x - __bfloat162float(h0)),
                     __float2bfloat16(r.y - __bfloat162float(h1))),
            pack_bf2(__float2bfloat16(r.z - __bfloat162float(h2)),
                     __float2bfloat16(r.w - __bfloat162float(h3))));
    }
}

// ---------------------------------------------------------------------------
extern "C" void kernel_launch(void* const* d_in, const int* in_sizes, int n_in,
                              void* d_out, int out_size)
{
    const float* x   = (const float*)d_in[0];
    const int*   msk = (const int*)d_in[1];
    const float* Wq  = (const float*)d_in[2];
    const float* bq  = (const float*)d_in[3];
    const float* Wk  = (const float*)d_in[4];
    const float* bk  = (const float*)d_in[5];
    const float* Wv  = (const float*)d_in[6];
    const float* bv  = (const float*)d_in[7];
    const float* Wo  = (const float*)d_in[8];
    const float* bo  = (const float*)d_in[9];
    const float* W1  = (const float*)d_in[10];
    const float* b1  = (const float*)d_in[11];
    const float* W2  = (const float*)d_in[12];
    const float* b2  = (const float*)d_in[13];
    const float* g1  = (const float*)d_in[14];
    const float* be1 = (const float*)d_in[15];
    const float* g2  = (const float*)d_in[16];
    const float* be2 = (const float*)d_in[17];
    float* out = (float*)d_out;

    __nv_bfloat16 *xh, *xl, *qh, *kh, *vh, *oh, *ol, *hb, *hl, *fh, *fl, *wh, *wl;
    float *f32a, *f32b, *f32c;
    cudaGetSymbolAddress((void**)&xh, g_xh);
    cudaGetSymbolAddress((void**)&xl, g_xl);
    cudaGetSymbolAddress((void**)&qh, g_qh);
    cudaGetSymbolAddress((void**)&kh, g_kh);
    cudaGetSymbolAddress((void**)&vh, g_vh);
    cudaGetSymbolAddress((void**)&oh, g_oh);
    cudaGetSymbolAddress((void**)&ol, g_ol);
    cudaGetSymbolAddress((void**)&hb, g_hb);
    cudaGetSymbolAddress((void**)&hl, g_hl);
    cudaGetSymbolAddress((void**)&fh, g_fh);
    cudaGetSymbolAddress((void**)&fl, g_fl);
    cudaGetSymbolAddress((void**)&wh, g_wh);
    cudaGetSymbolAddress((void**)&wl, g_wl);
    cudaGetSymbolAddress((void**)&f32a, g_f32a);
    cudaGetSymbolAddress((void**)&f32b, g_f32b);
    cudaGetSymbolAddress((void**)&f32c, g_f32c);

    cudaFuncSetAttribute(gemm_bf<0>, cudaFuncAttributeMaxDynamicSharedMemorySize, GEMM_SMEM_BYTES);
    cudaFuncSetAttribute(gemm_bf<1>, cudaFuncAttributeMaxDynamicSharedMemorySize, GEMM_SMEM_BYTES);
    cudaFuncSetAttribute(gemm_bf<2>, cudaFuncAttributeMaxDynamicSharedMemorySize, GEMM_SMEM_BYTES);
    cudaFuncSetAttribute(flash_tc_kernel, cudaFuncAttributeMaxDynamicSharedMemorySize, FL_SMEM);

    dim3 blk(256);
    dim3 pw(32, 8);

    // x -> bf16 hi/lo
    split_kernel<<<(size_t)MM * DD / 1024, blk>>>(x, xh, xl);

    // weights -> transposed bf16 hi/lo
    prep_w_kernel<<<dim3(DD / 32, DD / 32), pw>>>(Wq, wh + WQ_OFF, wl + WQ_OFF, DD, DD);
    prep_w_kernel<<<dim3(DD / 32, DD / 32), pw>>>(Wk, wh + WK_OFF, wl + WK_OFF, DD, DD);
    prep_w_kernel<<<dim3(DD / 32, DD / 32), pw>>>(Wv, wh + WV_OFF, wl + WV_OFF, DD, DD);
    prep_w_kernel<<<dim3(DD / 32, DD / 32), pw>>>(Wo, wh + WO_OFF, wl + WO_OFF, DD, DD);
    prep_w_kernel<<<dim3(FF / 32, DD / 32), pw>>>(W1, wh + W1_OFF, wl + W1_OFF, DD, FF);
    prep_w_kernel<<<dim3(DD / 32, FF / 32), pw>>>(W2, wh + W2_OFF, wl + W2_OFF, FF, DD);

    // QKV combined (N=3072) -> head-layout bf16 with bias  (M-tiles of 256)
    gemm_bf<2><<<dim3(24, 32), blk, GEMM_SMEM_BYTES>>>(
        xh, xl, wh + WQ_OFF, wl + WQ_OFF,
        nullptr, nullptr, nullptr, qh, kh, vh, bq, bk, bv, MM, 3 * DD, DD);

    // flash attention -> token-layout bf16 hi/lo
    flash_tc_kernel<<<dim3(SS / 128, BB * HH), blk, FL_SMEM>>>(qh, kh, vh, msk, oh, ol);

    // O projection (fp32 out, bias folded into LN)
    gemm_bf<0><<<dim3(8, 32), blk, GEMM_SMEM_BYTES>>>(
        oh, ol, wh + WO_OFF, wl + WO_OFF,
        f32a, nullptr, nullptr, nullptr, nullptr, nullptr, nullptr, nullptr, nullptr,
        MM, DD, DD);

    // h = LN(x + o + bo): fp32 + bf16 split
    add_ln_kernel<true><<<MM, blk>>>(x, f32a, bo, g1, be1, f32b, hb, hl);

    // FFN1: relu(h W1 + b1) -> bf16 hi/lo
    gemm_bf<1><<<dim3(32, 32), blk, GEMM_SMEM_BYTES>>>(
        hb, hl, wh + W1_OFF, wl + W1_OFF,
        nullptr, fh, fl, nullptr, nullptr, nullptr, b1, nullptr, nullptr, MM, FF, DD);

    // FFN2 (fp32 out)
    gemm_bf<0><<<dim3(8, 32), blk, GEMM_SMEM_BYTES>>>(
        fh, fl, wh + W2_OFF, wl + W2_OFF,
        f32c, nullptr, nullptr, nullptr, nullptr, nullptr, nullptr, nullptr, nullptr,
        MM, DD, FF);

    // out = LN(h + ffn + b2)
    add_ln_kernel<false><<<MM, blk>>>(f32b, f32c, b2, g2, be2, out, nullptr, nullptr);
}

// round 11
// speedup vs baseline: 6.7196x; 1.2442x over previous
#include <cuda_runtime.h>
#include <cuda_bf16.h>
#include <math.h>
#include <stdint.h>

constexpr int BB = 4;
constexpr int SS = 2048;
constexpr int DD = 1024;
constexpr int HH = 16;
constexpr int HD = 64;
constexpr int FF = 4096;
constexpr int MM = BB * SS;

#if defined(__CUDA_ARCH_FEAT_SM103_ALL) || defined(__CUDA_ARCH_FEAT_SM100_ALL)
#define HAS_TCGEN05 1
#else
#define HAS_TCGEN05 0
#endif

// ---------------- device scratch ----------------
__device__ __nv_bfloat16 g_xh[(size_t)MM * DD];
__device__ __nv_bfloat16 g_xl[(size_t)MM * DD];
__device__ __nv_bfloat16 g_qh[(size_t)MM * DD];
__device__ __nv_bfloat16 g_kh[(size_t)MM * DD];
__device__ __nv_bfloat16 g_vh[(size_t)MM * DD];
__device__ __nv_bfloat16 g_vt[(size_t)MM * DD];   // V transposed [B,H,HD,SS]
__device__ __nv_bfloat16 g_oh[(size_t)MM * DD];
__device__ __nv_bfloat16 g_ol[(size_t)MM * DD];
__device__ __nv_bfloat16 g_hb[(size_t)MM * DD];
__device__ __nv_bfloat16 g_hl[(size_t)MM * DD];
__device__ __nv_bfloat16 g_fh[(size_t)MM * FF];
__device__ __nv_bfloat16 g_fl[(size_t)MM * FF];
__device__ float g_f32a[(size_t)MM * DD];
__device__ float g_f32b[(size_t)MM * DD];
__device__ float g_f32c[(size_t)MM * DD];

constexpr size_t WQ_OFF = 0;
constexpr size_t WK_OFF = 1048576;
constexpr size_t WV_OFF = 2097152;
constexpr size_t WO_OFF = 3145728;
constexpr size_t W1_OFF = 4194304;
constexpr size_t W2_OFF = 8388608;
constexpr size_t WTOT   = 12582912;
__device__ __nv_bfloat16 g_wh[WTOT];
__device__ __nv_bfloat16 g_wl[WTOT];

// ---------------- helpers ----------------
__device__ __forceinline__ uint32_t smem_u32(const void* p) {
    uint32_t a;
    asm("{ .reg .u64 t; cvta.to.shared.u64 t, %1; cvt.u32.u64 %0, t; }" : "=r"(a) : "l"(p));
    return a;
}
__device__ __forceinline__ uint32_t swz128(uint32_t off) { return off ^ ((off >> 3) & 0x70); }
__device__ __forceinline__ uint32_t pack_bf2(__nv_bfloat16 a, __nv_bfloat16 b) {
    __nv_bfloat162 t; t.x = a; t.y = b; return *(uint32_t*)&t;
}
#define CP_ASYNC16(saddr, gptr) \
    asm volatile("cp.async.cg.shared.global [%0], [%1], 16;" \
        :: "r"((uint32_t)(saddr)), "l"(gptr) : "memory")
#define CP_COMMIT() asm volatile("cp.async.commit_group;" ::: "memory")
#define CP_WAIT(n)  asm volatile("cp.async.wait_group %0;" :: "n"(n) : "memory")

#if HAS_TCGEN05
__device__ __forceinline__ uint32_t elect_one_pred() {
    uint32_t pred;
    asm volatile("{\n\t.reg .pred p;\n\telect.sync _|p, 0xFFFFFFFF;\n\tselp.b32 %0, 1, 0, p;\n\t}" : "=r"(pred));
    return pred;
}
#define TCGEN05_ALLOC(smem_addr, nCols) \
    asm volatile("tcgen05.alloc.cta_group::1.sync.aligned.shared::cta.b32 [%0], %1;" \
        :: "r"((uint32_t)(smem_addr)), "r"((uint32_t)(nCols)) : "memory")
#define TCGEN05_DEALLOC(tmem_addr, nCols) \
    asm volatile("tcgen05.dealloc.cta_group::1.sync.aligned.b32 %0, %1;" \
        :: "r"(tmem_addr), "r"((uint32_t)(nCols)))
#define TCGEN05_COMMIT(mbar) \
    asm volatile("tcgen05.commit.cta_group::1.mbarrier::arrive::one.shared::cluster.b64 [%0];" \
        :: "r"((uint32_t)(mbar)) : "memory")
#define TCGEN05_WAIT_LD()  asm volatile("tcgen05.wait::ld.sync.aligned;" ::: "memory")
#define TCGEN05_FENCE_BEFORE() asm volatile("tcgen05.fence::before_thread_sync;" ::: "memory")
#define TCGEN05_FENCE_AFTER()  asm volatile("tcgen05.fence::after_thread_sync;" ::: "memory")
#define FENCE_ASYNC_SHARED() asm volatile("fence.proxy.async.shared::cta;" ::: "memory")
#define MBARRIER_INIT(mbar, cnt) \
    asm volatile("mbarrier.init.shared.b64 [%0], %1;" :: "r"((uint32_t)(mbar)), "r"((uint32_t)(cnt)) : "memory")
#define MBARRIER_INVAL(mbar) \
    asm volatile("mbarrier.inval.shared.b64 [%0];" :: "r"((uint32_t)(mbar)) : "memory")
#define MBARRIER_WAIT_PARITY(mbar, parity) do {                                    \
    uint32_t _mb = (uint32_t)(mbar);                                               \
    uint32_t _pa = (uint32_t)(parity);                                             \
    uint32_t _done;                                                                \
    asm volatile(                                                                  \
        "{\n\t.reg .pred p;\n\t"                                                   \
        "mbarrier.try_wait.parity.acquire.cta.shared::cta.b64 p, [%1], %2;\n\t"    \
        "selp.b32 %0, 1, 0, p;\n\t}"                                               \
        : "=r"(_done) : "r"(_mb), "r"(_pa) : "memory");                            \
    if (!_done) {                                                                  \
        asm volatile(                                                              \
            "{\n\t.reg .pred P1;\n\t"                                              \
            "WL_%=:\n\t"                                                           \
            "mbarrier.try_wait.parity.acquire.cta.shared::cta.b64 P1, [%0], %1, 0x989680;\n\t" \
            "@P1 bra.uni WD_%=;\n\t"                                               \
            "bra.uni WL_%=;\n\t"                                                   \
            "WD_%=:\n\t}"                                                          \
            :: "r"(_mb), "r"(_pa) : "memory");                                     \
    }                                                                              \
} while (0)
#define TCGEN05_LD_X32(r, addr) \
    asm volatile( \
        "tcgen05.ld.sync.aligned.32x32b.x32.b32 " \
        "{%0, %1, %2, %3, %4, %5, %6, %7, " \
        " %8, %9, %10, %11, %12, %13, %14, %15, " \
        " %16, %17, %18, %19, %20, %21, %22, %23, " \
        " %24, %25, %26, %27, %28, %29, %30, %31}, [%32];" \
        : "=r"((r)[0]),  "=r"((r)[1]),  "=r"((r)[2]),  "=r"((r)[3]), \
          "=r"((r)[4]),  "=r"((r)[5]),  "=r"((r)[6]),  "=r"((r)[7]), \
          "=r"((r)[8]),  "=r"((r)[9]),  "=r"((r)[10]), "=r"((r)[11]), \
          "=r"((r)[12]), "=r"((r)[13]), "=r"((r)[14]), "=r"((r)[15]), \
          "=r"((r)[16]), "=r"((r)[17]), "=r"((r)[18]), "=r"((r)[19]), \
          "=r"((r)[20]), "=r"((r)[21]), "=r"((r)[22]), "=r"((r)[23]), \
          "=r"((r)[24]), "=r"((r)[25]), "=r"((r)[26]), "=r"((r)[27]), \
          "=r"((r)[28]), "=r"((r)[29]), "=r"((r)[30]), "=r"((r)[31]) \
        : "r"(addr))

__device__ __forceinline__ uint64_t make_desc_sw128(uint32_t addr) {
    constexpr uint64_t BASE =
        (uint64_t(2) << 61) | (uint64_t(1) << 46) | (uint64_t(64) << 32) | (uint64_t(1) << 16);
    return BASE | ((uint64_t)(addr >> 4) & 0x3FFF);
}
__device__ __forceinline__ void mma_bf16_ss(uint32_t d, uint64_t ad, uint64_t bd,
                                            uint32_t idesc, bool acc) {
    uint32_t en = acc ? 1u : 0u;
    asm volatile(
        "{\n\t.reg .pred p;\n\t"
        "setp.ne.u32 p, %5, 0;\n\t"
        "tcgen05.mma.cta_group::1.kind::f16 [%0], %1, %2, %3, {%4, %4, %4, %4}, p;\n\t}"
        :: "r"(d), "l"(ad), "l"(bd), "r"(idesc), "r"(0u), "r"(en) : "memory");
}
#endif

constexpr uint32_t GEMM_IDESC =
    (1u << 4) | (1u << 7) | (1u << 10) | ((128 / 8) << 17) | ((128 / 16) << 24);
constexpr uint32_t IDESC_N64 =
    (1u << 4) | (1u << 7) | (1u << 10) | ((64 / 8) << 17) | ((128 / 16) << 24);

// ---------------- weight prep ----------------
__global__ void prep_w_kernel(const float* __restrict__ W,
                              __nv_bfloat16* __restrict__ Bh,
                              __nv_bfloat16* __restrict__ Bl, int K, int N)
{
    __shared__ float t[32][33];
    const int n0 = blockIdx.x * 32, k0 = blockIdx.y * 32;
#pragma unroll
    for (int i = 0; i < 4; i++)
        t[threadIdx.y + i * 8][threadIdx.x] =
            W[(size_t)(k0 + threadIdx.y + i * 8) * N + n0 + threadIdx.x];
    __syncthreads();
#pragma unroll
    for (int i = 0; i < 4; i++) {
        int n = threadIdx.y + i * 8;
        float v = t[threadIdx.x][n];
        __nv_bfloat16 h = __float2bfloat16(v);
        size_t idx = (size_t)(n0 + n) * K + k0 + threadIdx.x;
        Bh[idx] = h;
        Bl[idx] = __float2bfloat16(v - __bfloat162float(h));
    }
}

// fp32 -> bf16 hi/lo split
__global__ __launch_bounds__(256) void split_kernel(
    const float* __restrict__ in,
    __nv_bfloat16* __restrict__ oh, __nv_bfloat16* __restrict__ ol)
{
    size_t i = ((size_t)blockIdx.x * 256 + threadIdx.x) * 4;
    float4 v = *(const float4*)(in + i);
    __nv_bfloat16 h0 = __float2bfloat16(v.x), h1 = __float2bfloat16(v.y);
    __nv_bfloat16 h2 = __float2bfloat16(v.z), h3 = __float2bfloat16(v.w);
    *(uint2*)(oh + i) = make_uint2(pack_bf2(h0, h1), pack_bf2(h2, h3));
    *(uint2*)(ol + i) = make_uint2(
        pack_bf2(__float2bfloat16(v.x - __bfloat162float(h0)),
                 __float2bfloat16(v.y - __bfloat162float(h1))),
        pack_bf2(__float2bfloat16(v.z - __bfloat162float(h2)),
                 __float2bfloat16(v.w - __bfloat162float(h3))));
}

// V transpose: vh [BH][SS][HD] -> vt [BH][HD][SS].  block 256, grid (SS/64, BH)
__global__ __launch_bounds__(256) void transpose_v_kernel(
    const __nv_bfloat16* __restrict__ vh, __nv_bfloat16* __restrict__ vt)
{
    __shared__ __nv_bfloat16 t[64][72];
    const int bh = blockIdx.y;
    const int s0 = blockIdx.x * 64;
    const int r = threadIdx.x >> 2;          // 0..63
    const int c = (threadIdx.x & 3) * 16;    // 0,16,32,48
    const __nv_bfloat16* src = vh + ((size_t)(bh * SS + s0 + r)) * HD + c;
    *(uint4*)(&t[r][c])     = *(const uint4*)(src);
    *(uint4*)(&t[r][c + 8]) = *(const uint4*)(src + 8);
    __syncthreads();
    // write: row d = r, keys c..c+15
    __nv_bfloat16* dst = vt + ((size_t)(bh * HD + r)) * SS + s0 + c;
    __nv_bfloat16 tmp[16];
#pragma unroll
    for (int j = 0; j < 16; j++) tmp[j] = t[c + j][r];
    *(uint4*)(dst)     = *(uint4*)(tmp);
    *(uint4*)(dst + 8) = *(uint4*)(tmp + 8);
}

// ---------------------------------------------------------------------------
// GEMM (unchanged from R10; proven): 256x128 tile, 2-stage cp.async
// ---------------------------------------------------------------------------
constexpr int GEMM_STAGE = 98304;
constexpr int GEMM_SMEM_BYTES = 2 * GEMM_STAGE + 1024;

template <int EPI>
__global__ __launch_bounds__(256, 1) void gemm_bf(
    const __nv_bfloat16* __restrict__ Ah, const __nv_bfloat16* __restrict__ Al,
    const __nv_bfloat16* __restrict__ Bh, const __nv_bfloat16* __restrict__ Bl,
    float* __restrict__ Cf, __nv_bfloat16* __restrict__ Ch, __nv_bfloat16* __restrict__ Cl,
    __nv_bfloat16* __restrict__ D0, __nv_bfloat16* __restrict__ D1, __nv_bfloat16* __restrict__ D2,
    const float* __restrict__ bias0, const float* __restrict__ bias1, const float* __restrict__ bias2,
    int M, int N, int K)
{
    extern __shared__ char dsmem[];
    uintptr_t p = ((uintptr_t)dsmem + 1023) & ~(uintptr_t)1023;
    char* buf = (char*)p;
    const int tid = threadIdx.x;
    const int wid = tid >> 5;
    const int lane = tid & 31;
    const int m0 = blockIdx.y << 8;
    const int n0 = blockIdx.x << 7;

#if HAS_TCGEN05
    __shared__ alignas(16) unsigned long long ctrlq[4];
    const uint32_t sbuf = smem_u32(buf);
    const uint32_t ctrl = smem_u32(ctrlq);

    if (wid == 0) TCGEN05_ALLOC(ctrl, 256);
    if (tid == 0) {
        MBARRIER_INIT(ctrl + 8, 1);
        MBARRIER_INIT(ctrl + 16, 1);
        MBARRIER_INIT(ctrl + 24, 1);
    }
    __syncthreads();
    uint32_t tmem;
    asm volatile("ld.shared.b32 %0, [%1];" : "=r"(tmem) : "r"(ctrl));

    const int NC = K >> 6;

    auto load_chunk = [&](int ck, int st) {
        const uint32_t sb = sbuf + (uint32_t)st * GEMM_STAGE;
        const int k0 = ck << 6;
#pragma unroll
        for (int j = 0; j < 8; j++) {
            int u = tid + j * 256;
            int r = u >> 3, g = u & 7;
            uint32_t so = swz128((uint32_t)(r * 128 + g * 16));
            size_t ao = (size_t)(m0 + r) * K + k0 + g * 8;
            CP_ASYNC16(sb + so,         Ah + ao);
            CP_ASYNC16(sb + 32768 + so, Al + ao);
        }
#pragma unroll
        for (int j = 0; j < 4; j++) {
            int u = tid + j * 256;
            int r = u >> 3, g = u & 7;
            uint32_t so = swz128((uint32_t)(r * 128 + g * 16));
            size_t bo = (size_t)(n0 + r) * K + k0 + g * 8;
            CP_ASYNC16(sb + 65536 + so, Bh + bo);
            CP_ASYNC16(sb + 81920 + so, Bl + bo);
        }
    };

    load_chunk(0, 0);
    CP_COMMIT();
    load_chunk(1, 1);
    CP_COMMIT();

    int ph[2] = {0, 0};

    for (int i = 0; i < NC; i++) {
        const int st = i & 1;
        if (i < NC - 1) CP_WAIT(1);
        else            CP_WAIT(0);
        __syncthreads();
        FENCE_ASYNC_SHARED();

        if (wid == 0 && elect_one_pred()) {
            const uint32_t sb = sbuf + (uint32_t)st * GEMM_STAGE;
            uint64_t dBh = make_desc_sw128(sb + 65536);
            uint64_t dBl = make_desc_sw128(sb + 81920);
#pragma unroll
            for (int mt = 0; mt < 2; mt++) {
                uint64_t dAh = make_desc_sw128(sb + mt * 16384);
                uint64_t dAl = make_desc_sw128(sb + 32768 + mt * 16384);
                uint32_t dst = tmem + mt * 128;
#pragma unroll
                for (int ks = 0; ks < 4; ks++)
                    mma_bf16_ss(dst, dAh + ks * 2, dBh + ks * 2, GEMM_IDESC, !(i == 0 && ks == 0));
#pragma unroll
                for (int ks = 0; ks < 4; ks++)
                    mma_bf16_ss(dst, dAl + ks * 2, dBh + ks * 2, GEMM_IDESC, true);
#pragma unroll
                for (int ks = 0; ks < 4; ks++)
                    mma_bf16_ss(dst, dAh + ks * 2, dBl + ks * 2, GEMM_IDESC, true);
            }
            TCGEN05_COMMIT(ctrl + 8 + st * 8);
        }

        if (i + 2 < NC) {
            MBARRIER_WAIT_PARITY(ctrl + 8 + st * 8, ph[st]);
            ph[st] ^= 1;
            load_chunk(i + 2, st);
            CP_COMMIT();
        }
    }

    if (wid == 0 && elect_one_pred()) TCGEN05_COMMIT(ctrl + 24);
    MBARRIER_WAIT_PARITY(ctrl + 24, 0);
    TCGEN05_FENCE_AFTER();

    {
        const int sp = wid & 3;
        const int chf = wid >> 2;
#pragma unroll
        for (int mt = 0; mt < 2; mt++) {
            uint32_t r[64];
            TCGEN05_LD_X32(r, tmem + mt * 128 + chf * 64);
            TCGEN05_LD_X32(r + 32, tmem + mt * 128 + chf * 64 + 32);
            TCGEN05_WAIT_LD();
            TCGEN05_FENCE_BEFORE();

            const int row = m0 + mt * 128 + sp * 32 + lane;
            const int c0 = n0 + chf * 64;

            if (EPI == 0) {
                float* cp = Cf + (size_t)row * N + c0;
#pragma unroll
                for (int c = 0; c < 16; c++) {
                    float4 v;
                    v.x = __uint_as_float(r[4 * c + 0]);
                    v.y = __uint_as_float(r[4 * c + 1]);
                    v.z = __uint_as_float(r[4 * c + 2]);
                    v.w = __uint_as_float(r[4 * c + 3]);
                    *(float4*)(cp + 4 * c) = v;
                }
            } else if (EPI == 1) {
                size_t base = (size_t)row * N + c0;
#pragma unroll
                for (int j8 = 0; j8 < 8; j8++) {
                    uint32_t hw[4], lw[4];
#pragma unroll
                    for (int q = 0; q < 4; q++) {
                        int j = j8 * 8 + q * 2;
                        float v0 = fmaxf(__uint_as_float(r[j])     + bias0[c0 + j],     0.0f);
                        float v1 = fmaxf(__uint_as_float(r[j + 1]) + bias0[c0 + j + 1], 0.0f);
                        __nv_bfloat16 h0 = __float2bfloat16(v0), h1 = __float2bfloat16(v1);
                        hw[q] = pack_bf2(h0, h1);
                        lw[q] = pack_bf2(__float2bfloat16(v0 - __bfloat162float(h0)),
                                         __float2bfloat16(v1 - __bfloat162float(h1)));
                    }
                    *(uint4*)(Ch + base + j8 * 8) = make_uint4(hw[0], hw[1], hw[2], hw[3]);
                    *(uint4*)(Cl + base + j8 * 8) = make_uint4(lw[0], lw[1], lw[2], lw[3]);
                }
            } else {
                const int mat = c0 >> 10;
                const int lc = c0 & 1023;
                const float* bs = (mat == 0) ? bias0 : (mat == 1) ? bias1 : bias2;
                __nv_bfloat16* Dd = (mat == 0) ? D0 : (mat == 1) ? D1 : D2;
                const int h_ = lc >> 6;
                const int b_ = row >> 11;
                const int s_ = row & (SS - 1);
                size_t base = (((size_t)b_ * HH + h_) * SS + s_) * HD;
#pragma unroll
                for (int j8 = 0; j8 < 8; j8++) {
                    uint32_t hw[4];
#pragma unroll
                    for (int q = 0; q < 4; q++) {
                        int j = j8 * 8 + q * 2;
                        float v0 = __uint_as_float(r[j])     + bs[lc + j];
                        float v1 = __uint_as_float(r[j + 1]) + bs[lc + j + 1];
                        hw[q] = pack_bf2(__float2bfloat16(v0), __float2bfloat16(v1));
                    }
                    *(uint4*)(Dd + base + j8 * 8) = make_uint4(hw[0], hw[1], hw[2], hw[3]);
                }
            }
        }
    }

    __syncthreads();
    if (tid == 0) {
        MBARRIER_INVAL(ctrl + 8);
        MBARRIER_INVAL(ctrl + 16);
        MBARRIER_INVAL(ctrl + 24);
    }
    __syncthreads();
    if (wid == 0) TCGEN05_DEALLOC(tmem, 256);

#else  // FFMA fallback
    float* As = (float*)buf;
    float* Bs = As + 16 * 132;
    const int tx = tid & 15, ty = tid >> 4;
    for (int mt = 0; mt < 2; mt++) {
        const int mb = m0 + mt * 128;
        float acc[8][8];
#pragma unroll
        for (int i = 0; i < 8; i++)
#pragma unroll
            for (int j = 0; j < 8; j++) acc[i][j] = 0.0f;
        for (int k0 = 0; k0 < K; k0 += 16) {
            for (int it = 0; it < 8; it++) {
                int idx = tid + it * 256;
                int rr = idx >> 4, kk = idx & 15;
                As[kk * 132 + rr] =
                    __bfloat162float(Ah[(size_t)(mb + rr) * K + k0 + kk]) +
                    __bfloat162float(Al[(size_t)(mb + rr) * K + k0 + kk]);
                Bs[kk * 132 + rr] =
                    __bfloat162float(Bh[(size_t)(n0 + rr) * K + k0 + kk]) +
                    __bfloat162float(Bl[(size_t)(n0 + rr) * K + k0 + kk]);
            }
            __syncthreads();
#pragma unroll
            for (int k = 0; k < 16; k++) {
                float a[8], bb[8];
#pragma unroll
                for (int i = 0; i < 8; i++) a[i] = As[k * 132 + ty * 8 + i];
#pragma unroll
                for (int j = 0; j < 8; j++) bb[j] = Bs[k * 132 + tx * 8 + j];
#pragma unroll
                for (int i = 0; i < 8; i++)
#pragma unroll
                    for (int j = 0; j < 8; j++) acc[i][j] = fmaf(a[i], bb[j], acc[i][j]);
            }
            __syncthreads();
        }
#pragma unroll
        for (int i = 0; i < 8; i++) {
            int row = mb + ty * 8 + i;
#pragma unroll
            for (int j = 0; j < 8; j++) {
                int col = n0 + tx * 8 + j;
                float v = acc[i][j];
                if (EPI == 0) {
                    Cf[(size_t)row * N + col] = v;
                } else if (EPI == 1) {
                    v = fmaxf(v + bias0[col], 0.0f);
                    __nv_bfloat16 h = __float2bfloat16(v);
                    Ch[(size_t)row * N + col] = h;
                    Cl[(size_t)row * N + col] = __float2bfloat16(v - __bfloat162float(h));
                } else {
                    int mat = col >> 10, lc = col & 1023;
                    const float* bs = (mat == 0) ? bias0 : (mat == 1) ? bias1 : bias2;
                    __nv_bfloat16* Dd = (mat == 0) ? D0 : (mat == 1) ? D1 : D2;
                    float vv = v + bs[lc];
                    int h_ = lc >> 6, d = lc & 63;
                    int b_ = row >> 11, s_ = row & (SS - 1);
                    Dd[(((size_t)b_ * HH + h_) * SS + s_) * HD + d] = __float2bfloat16(vv);
                }
            }
        }
        __syncthreads();
    }
#endif
}

// ---------------------------------------------------------------------------
// Pipelined tcgen05 flash attention.
// smem: Q 16K | K x3 16K | VT x3 16K | P 32K | mask 8K | ctrl+lpart
// TMEM: S0 @ 0, S1 @ 128, O @ 256.  cp.async ring for K/VT (3 stages).
// ---------------------------------------------------------------------------
constexpr int FL_Q  = 0;
constexpr int FL_K  = 16384;     // 3 stages
constexpr int FL_VT = 65536;     // 3 stages
constexpr int FL_P  = 114688;
constexpr int FL_MS = 147456;    // mask 8K
constexpr int FL_CT = 155648;    // ctrl 64B + lpart 1K
constexpr int FL_SMEM = FL_CT + 64 + 1024 + 1024;
constexpr int NKB = SS / 128;    // 16

__global__ __launch_bounds__(256, 1) void flash_tc_kernel(
    const __nv_bfloat16* __restrict__ qg, const __nv_bfloat16* __restrict__ kg,
    const __nv_bfloat16* __restrict__ vt, const int* __restrict__ mask,
    __nv_bfloat16* __restrict__ outh, __nv_bfloat16* __restrict__ outl)
{
    extern __shared__ char dsmem[];
    uintptr_t pb = ((uintptr_t)dsmem + 1023) & ~(uintptr_t)1023;
    char* buf = (char*)pb;
    const int tid = threadIdx.x;
    const int wid = tid >> 5;
    const int lane = tid & 31;
    const int bh = blockIdx.y;
    const int b_ = bh >> 4;
    const int h_ = bh & (HH - 1);
    const int q0 = blockIdx.x * 128;

#if HAS_TCGEN05
    const int sp = wid & 3;
    const int chf = wid >> 2;
    const uint32_t sbuf = smem_u32(buf);
    const uint32_t ctrl = sbuf + FL_CT;
    int* msk_s = (int*)(buf + FL_MS);
    float* lpart = (float*)(buf + FL_CT + 64);

    if (wid == 0) TCGEN05_ALLOC(ctrl, 512);
    if (tid == 0) { MBARRIER_INIT(ctrl + 8, 1); MBARRIER_INIT(ctrl + 16, 1); }
    __syncthreads();
    uint32_t tmem;
    asm volatile("ld.shared.b32 %0, [%1];" : "=r"(tmem) : "r"(ctrl));

    auto load_kv = [&](int kb, int st) {
        const uint32_t sbK = sbuf + FL_K + (uint32_t)st * 16384;
        const uint32_t sbV = sbuf + FL_VT + (uint32_t)st * 16384;
#pragma unroll
        for (int j = 0; j < 4; j++) {
            int u = tid + j * 256;
            int r = u >> 3, g = u & 7;
            CP_ASYNC16(sbK + swz128((uint32_t)(r * 128 + g * 16)),
                       kg + ((size_t)(bh * SS + kb * 128 + r)) * HD + g * 8);
        }
#pragma unroll
        for (int j = 0; j < 4; j++) {
            int u = tid + j * 256;
            int d = u >> 4, g = u & 15;
            int key0 = g * 8;
            uint32_t o = (uint32_t)(((key0 >> 6) * 8 + (d >> 3)) * 1024 + (d & 7) * 128 + (key0 & 63) * 2);
            CP_ASYNC16(sbV + swz128(o),
                       vt + ((size_t)(bh * HD + d)) * SS + kb * 128 + key0);
        }
    };

    // prologue: Q + mask + stage0, then stage1
#pragma unroll
    for (int j = 0; j < 4; j++) {
        int u = tid + j * 256;
        int r = u >> 3, g = u & 7;
        CP_ASYNC16(sbuf + FL_Q + swz128((uint32_t)(r * 128 + g * 16)),
                   qg + ((size_t)(bh * SS + q0 + r)) * HD + g * 8);
    }
#pragma unroll
    for (int j = 0; j < 2; j++)
        CP_ASYNC16(sbuf + FL_MS + tid * 16 + j * 4096,
                   mask + b_ * SS + tid * 4 + j * 1024);
    load_kv(0, 0);
    CP_COMMIT();
    load_kv(1, 1);
    CP_COMMIT();

    const uint64_t dQ = make_desc_sw128(sbuf + FL_Q);
    const uint64_t dP = make_desc_sw128(sbuf + FL_P);
    const int pOff[8] = {0, 2, 4, 6, 1024, 1026, 1028, 1030};
    const int vOff[8] = {0, 2, 4, 6, 512, 514, 516, 518};

    CP_WAIT(1);
    __syncthreads();
    FENCE_ASYNC_SHARED();
    if (wid == 0 && elect_one_pred()) {
        uint64_t dK = make_desc_sw128(sbuf + FL_K);
#pragma unroll
        for (int s = 0; s < 4; s++)
            mma_bf16_ss(tmem, dQ + s * 2, dK + s * 2, GEMM_IDESC, s != 0);
        TCGEN05_COMMIT(ctrl + 8);
    }

    float lsum = 0.0f;
    int phS = 0, phO = 0;
    const int r = sp * 32 + lane;

    for (int k = 0; k < NKB; k++) {
        const int st = k % 3;
        const uint32_t sbase = (uint32_t)(k & 1) * 128;

        // wait S_k
        MBARRIER_WAIT_PARITY(ctrl + 8, phS);
        phS ^= 1;
        TCGEN05_FENCE_AFTER();

        // LDTM + exp into registers
        uint32_t ppk[32];
#pragma unroll
        for (int h2 = 0; h2 < 2; h2++) {
            uint32_t sr[32];
            TCGEN05_LD_X32(sr, tmem + sbase + chf * 64 + h2 * 32);
            TCGEN05_WAIT_LD();
            const int cbase = k * 128 + chf * 64 + h2 * 32;
#pragma unroll
            for (int j = 0; j < 16; j++) {
                float p0 = msk_s[cbase + 2 * j]     ? __expf(__uint_as_float(sr[2 * j])     * 0.125f) : 0.0f;
                float p1 = msk_s[cbase + 2 * j + 1] ? __expf(__uint_as_float(sr[2 * j + 1]) * 0.125f) : 0.0f;
                __nv_bfloat16 bp0 = __float2bfloat16(p0), bp1 = __float2bfloat16(p1);
                ppk[h2 * 16 + j] = pack_bf2(bp0, bp1);
                lsum += __bfloat162float(bp0) + __bfloat162float(bp1);
            }
        }

        // wait PV_{k-1}: frees P buffer and the stage buffer for block k+2
        if (k > 0) { MBARRIER_WAIT_PARITY(ctrl + 16, phO); phO ^= 1; }

        // kick loads for block k+2
        if (k + 2 < NKB) { load_kv(k + 2, (k + 2) % 3); CP_COMMIT(); }

        // write P
#pragma unroll
        for (int h2 = 0; h2 < 2; h2++) {
            uint32_t pbo = (uint32_t)((chf * 16 + (r >> 3)) * 1024 + (r & 7) * 128 + h2 * 64);
#pragma unroll
            for (int j = 0; j < 4; j++)
                *(uint4*)(buf + FL_P + swz128(pbo + j * 16)) =
                    make_uint4(ppk[h2 * 16 + 4 * j], ppk[h2 * 16 + 4 * j + 1],
                               ppk[h2 * 16 + 4 * j + 2], ppk[h2 * 16 + 4 * j + 3]);
        }
        TCGEN05_FENCE_BEFORE();
        FENCE_ASYNC_SHARED();
        __syncthreads();

        // PV_k
        if (wid == 0 && elect_one_pred()) {
            uint64_t dVT = make_desc_sw128(sbuf + FL_VT + (uint32_t)st * 16384);
#pragma unroll
            for (int s = 0; s < 8; s++)
                mma_bf16_ss(tmem + 256, dP + pOff[s], dVT + vOff[s], IDESC_N64,
                            !(k == 0 && s == 0));
            TCGEN05_COMMIT(ctrl + 16);
        }

        // issue S_{k+1}
        if (k + 1 < NKB) {
            if (k + 2 < NKB) CP_WAIT(1);
            else             CP_WAIT(0);
            __syncthreads();
            FENCE_ASYNC_SHARED();
            if (wid == 0 && elect_one_pred()) {
                uint64_t dK = make_desc_sw128(sbuf + FL_K + (uint32_t)((k + 1) % 3) * 16384);
                uint32_t dst = tmem + ((k + 1) & 1) * 128;
#pragma unroll
                for (int s = 0; s < 4; s++)
                    mma_bf16_ss(dst, dQ + s * 2, dK + s * 2, GEMM_IDESC, s != 0);
                TCGEN05_COMMIT(ctrl + 8);
            }
        }
    }

    MBARRIER_WAIT_PARITY(ctrl + 16, phO);
    TCGEN05_FENCE_AFTER();
    lpart[chf * 128 + r] = lsum;
    __syncthreads();

    if (wid < 4) {
        uint32_t orr[64];
        TCGEN05_LD_X32(orr, tmem + 256);
        TCGEN05_LD_X32(orr + 32, tmem + 288);
        TCGEN05_WAIT_LD();
        TCGEN05_FENCE_BEFORE();
        float inv = 1.0f / (lpart[r] + lpart[128 + r]);
        size_t base = ((size_t)(b_ * SS + q0 + r)) * DD + h_ * HD;
#pragma unroll
        for (int j8 = 0; j8 < 8; j8++) {
            uint32_t hw[4], lw[4];
#pragma unroll
            for (int q = 0; q < 4; q++) {
                int j = j8 * 8 + q * 2;
                float v0 = __uint_as_float(orr[j])     * inv;
                float v1 = __uint_as_float(orr[j + 1]) * inv;
                __nv_bfloat16 h0 = __float2bfloat16(v0), h1 = __float2bfloat16(v1);
                hw[q] = pack_bf2(h0, h1);
                lw[q] = pack_bf2(__float2bfloat16(v0 - __bfloat162float(h0)),
                                 __float2bfloat16(v1 - __bfloat162float(h1)));
            }
            *(uint4*)(outh + base + j8 * 8) = make_uint4(hw[0], hw[1], hw[2], hw[3]);
            *(uint4*)(outl + base + j8 * 8) = make_uint4(lw[0], lw[1], lw[2], lw[3]);
        }
    }
    __syncthreads();
    if (tid == 0) { MBARRIER_INVAL(ctrl + 8); MBARRIER_INVAL(ctrl + 16); }
    __syncthreads();
    if (wid == 0) TCGEN05_DEALLOC(tmem, 512);
#else
    // slow fallback (vt layout: [BH][HD][SS])
    if (tid < 128) {
        int rr = q0 + tid;
        float qr[64], o[64], l = 0.0f;
        for (int d = 0; d < 64; d++) {
            qr[d] = __bfloat162float(qg[((size_t)(bh * SS + rr)) * HD + d]);
            o[d] = 0.0f;
        }
        for (int key = 0; key < SS; key++) {
            if (!mask[b_ * SS + key]) continue;
            float s = 0.0f;
            const __nv_bfloat16* kp = kg + ((size_t)(bh * SS + key)) * HD;
            for (int d = 0; d < 64; d++) s += qr[d] * __bfloat162float(kp[d]);
            float pw = __expf(s * 0.125f);
            l += pw;
            for (int d = 0; d < 64; d++)
                o[d] += pw * __bfloat162float(vt[((size_t)(bh * HD + d)) * SS + key]);
        }
        float inv = 1.0f / l;
        for (int d = 0; d < 64; d++) {
            float v = o[d] * inv;
            __nv_bfloat16 h = __float2bfloat16(v);
            size_t idx = ((size_t)(b_ * SS + rr)) * DD + h_ * HD + d;
            outh[idx] = h;
            outl[idx] = __float2bfloat16(v - __bfloat162float(h));
        }
    }
#endif
}

// ---------------- residual + bias + LN ----------------
template <bool SPLIT>
__global__ __launch_bounds__(256) void add_ln_kernel(
    const float* __restrict__ a, const float* __restrict__ b,
    const float* __restrict__ bias,
    const float* __restrict__ g, const float* __restrict__ be,
    float* __restrict__ out,
    __nv_bfloat16* __restrict__ oh, __nv_bfloat16* __restrict__ ol)
{
    __shared__ float sh[10];
    const int row = blockIdx.x;
    const int tid = threadIdx.x;
    const int wid = tid >> 5, lane = tid & 31;
    const size_t base = (size_t)row * DD + tid * 4;

    float4 av = *(const float4*)(a + base);
    float4 bv = *(const float4*)(b + base);
    float4 cv = *(const float4*)(bias + tid * 4);
    float4 t = make_float4(av.x + bv.x + cv.x, av.y + bv.y + cv.y,
                           av.z + bv.z + cv.z, av.w + bv.w + cv.w);
    float s = t.x + t.y + t.z + t.w;
#pragma unroll
    for (int off = 16; off >= 1; off >>= 1) s += __shfl_xor_sync(0xffffffffu, s, off);
    if (lane == 0) sh[wid] = s;
    __syncthreads();
    if (tid == 0) {
        float t2 = 0.f;
#pragma unroll
        for (int w = 0; w < 8; w++) t2 += sh[w];
        sh[8] = t2 * (1.0f / 1024.0f);
    }
    __syncthreads();
    float mu = sh[8];
    float dx = t.x - mu, dy = t.y - mu, dz = t.z - mu, dw = t.w - mu;
    float sq = dx * dx + dy * dy + dz * dz + dw * dw;
#pragma unroll
    for (int off = 16; off >= 1; off >>= 1) sq += __shfl_xor_sync(0xffffffffu, sq, off);
    if (lane == 0) sh[wid] = sq;
    __syncthreads();
    if (tid == 0) {
        float t2 = 0.f;
#pragma unroll
        for (int w = 0; w < 8; w++) t2 += sh[w];
        sh[9] = rsqrtf(t2 * (1.0f / 1024.0f) + 1e-5f);
    }
    __syncthreads();
    float inv = sh[9];
    float4 gv = *(const float4*)(g + tid * 4);
    float4 bev = *(const float4*)(be + tid * 4);
    float4 r = make_float4(dx * inv * gv.x + bev.x, dy * inv * gv.y + bev.y,
                           dz * inv * gv.z + bev.z, dw * inv * gv.w + bev.w);
    *(float4*)(out + base) = r;
    if (SPLIT) {
        __nv_bfloat16 h0 = __float2bfloat16(r.x), h1 = __float2bfloat16(r.y);
        __nv_bfloat16 h2 = __float2bfloat16(r.z), h3 = __float2bfloat16(r.w);
        *(uint2*)(oh + base) = make_uint2(pack_bf2(h0, h1), pack_bf2(h2, h3));
        *(uint2*)(ol + base) = make_uint2(
            pack_bf2(__float2bfloat16(r.x - __bfloat162float(h0)),
                     __float2bfloat16(r.y - __bfloat162float(h1))),
            pack_bf2(__float2bfloat16(r.z - __bfloat162float(h2)),
                     __float2bfloat16(r.w - __bfloat162float(h3))));
    }
}

// ---------------------------------------------------------------------------
extern "C" void kernel_launch(void* const* d_in, const int* in_sizes, int n_in,
                              void* d_out, int out_size)
{
    const float* x   = (const float*)d_in[0];
    const int*   msk = (const int*)d_in[1];
    const float* Wq  = (const float*)d_in[2];
    const float* bq  = (const float*)d_in[3];
    const float* Wk  = (const float*)d_in[4];
    const float* bk  = (const float*)d_in[5];
    const float* Wv  = (const float*)d_in[6];
    const float* bv  = (const float*)d_in[7];
    const float* Wo  = (const float*)d_in[8];
    const float* bo  = (const float*)d_in[9];
    const float* W1  = (const float*)d_in[10];
    const float* b1  = (const float*)d_in[11];
    const float* W2  = (const float*)d_in[12];
    const float* b2  = (const float*)d_in[13];
    const float* g1  = (const float*)d_in[14];
    const float* be1 = (const float*)d_in[15];
    const float* g2  = (const float*)d_in[16];
    const float* be2 = (const float*)d_in[17];
    float* out = (float*)d_out;

    __nv_bfloat16 *xh, *xl, *qh, *kh, *vh, *vt, *oh, *ol, *hb, *hl, *fh, *fl, *wh, *wl;
    float *f32a, *f32b, *f32c;
    cudaGetSymbolAddress((void**)&xh, g_xh);
    cudaGetSymbolAddress((void**)&xl, g_xl);
    cudaGetSymbolAddress((void**)&qh, g_qh);
    cudaGetSymbolAddress((void**)&kh, g_kh);
    cudaGetSymbolAddress((void**)&vh, g_vh);
    cudaGetSymbolAddress((void**)&vt, g_vt);
    cudaGetSymbolAddress((void**)&oh, g_oh);
    cudaGetSymbolAddress((void**)&ol, g_ol);
    cudaGetSymbolAddress((void**)&hb, g_hb);
    cudaGetSymbolAddress((void**)&hl, g_hl);
    cudaGetSymbolAddress((void**)&fh, g_fh);
    cudaGetSymbolAddress((void**)&fl, g_fl);
    cudaGetSymbolAddress((void**)&wh, g_wh);
    cudaGetSymbolAddress((void**)&wl, g_wl);
    cudaGetSymbolAddress((void**)&f32a, g_f32a);
    cudaGetSymbolAddress((void**)&f32b, g_f32b);
    cudaGetSymbolAddress((void**)&f32c, g_f32c);

    cudaFuncSetAttribute(gemm_bf<0>, cudaFuncAttributeMaxDynamicSharedMemorySize, GEMM_SMEM_BYTES);
    cudaFuncSetAttribute(gemm_bf<1>, cudaFuncAttributeMaxDynamicSharedMemorySize, GEMM_SMEM_BYTES);
    cudaFuncSetAttribute(gemm_bf<2>, cudaFuncAttributeMaxDynamicSharedMemorySize, GEMM_SMEM_BYTES);
    cudaFuncSetAttribute(flash_tc_kernel, cudaFuncAttributeMaxDynamicSharedMemorySize, FL_SMEM);

    dim3 blk(256);
    dim3 pw(32, 8);

    // x -> bf16 hi/lo
    split_kernel<<<(size_t)MM * DD / 1024, blk>>>(x, xh, xl);

    // weights -> transposed bf16 hi/lo
    prep_w_kernel<<<dim3(DD / 32, DD / 32), pw>>>(Wq, wh + WQ_OFF, wl + WQ_OFF, DD, DD);
    prep_w_kernel<<<dim3(DD / 32, DD / 32), pw>>>(Wk, wh + WK_OFF, wl + WK_OFF, DD, DD);
    prep_w_kernel<<<dim3(DD / 32, DD / 32), pw>>>(Wv, wh + WV_OFF, wl + WV_OFF, DD, DD);
    prep_w_kernel<<<dim3(DD / 32, DD / 32), pw>>>(Wo, wh + WO_OFF, wl + WO_OFF, DD, DD);
    prep_w_kernel<<<dim3(FF / 32, DD / 32), pw>>>(W1, wh + W1_OFF, wl + W1_OFF, DD, FF);
    prep_w_kernel<<<dim3(DD / 32, FF / 32), pw>>>(W2, wh + W2_OFF, wl + W2_OFF, FF, DD);

    // QKV combined (N=3072) -> head-layout bf16 with bias
    gemm_bf<2><<<dim3(24, 32), blk, GEMM_SMEM_BYTES>>>(
        xh, xl, wh + WQ_OFF, wl + WQ_OFF,
        nullptr, nullptr, nullptr, qh, kh, vh, bq, bk, bv, MM, 3 * DD, DD);

    // V -> V^T
    transpose_v_kernel<<<dim3(SS / 64, BB * HH), blk>>>(vh, vt);

    // pipelined flash attention -> token-layout bf16 hi/lo
    flash_tc_kernel<<<dim3(SS / 128, BB * HH), blk, FL_SMEM>>>(qh, kh, vt, msk, oh, ol);

    // O projection (fp32 out, bias folded into LN)
    gemm_bf<0><<<dim3(8, 32), blk, GEMM_SMEM_BYTES>>>(
        oh, ol, wh + WO_OFF, wl + WO_OFF,
        f32a, nullptr, nullptr, nullptr, nullptr, nullptr, nullptr, nullptr, nullptr,
        MM, DD, DD);

    // h = LN(x + o + bo): fp32 + bf16 split
    add_ln_kernel<true><<<MM, blk>>>(x, f32a, bo, g1, be1, f32b, hb, hl);

    // FFN1: relu(h W1 + b1) -> bf16 hi/lo
    gemm_bf<1><<<dim3(32, 32), blk, GEMM_SMEM_BYTES>>>(
        hb, hl, wh + W1_OFF, wl + W1_OFF,
        nullptr, fh, fl, nullptr, nullptr, nullptr, b1, nullptr, nullptr, MM, FF, DD);

    // FFN2 (fp32 out)
    gemm_bf<0><<<dim3(8, 32), blk, GEMM_SMEM_BYTES>>>(
        fh, fl, wh + W2_OFF, wl + W2_OFF,
        f32c, nullptr, nullptr, nullptr, nullptr, nullptr, nullptr, nullptr, nullptr,
        MM, DD, FF);

    // out = LN(h + ffn + b2)
    add_ln_kernel<false><<<MM, blk>>>(f32b, f32c, b2, g2, be2, out, nullptr, nullptr);
}